// round 2
// baseline (speedup 1.0000x reference)
#include <cuda_runtime.h>
#include <cstddef>

#define D_    2048
#define H_    16
#define S_    2048
#define B_    2
#define KD    128
#define QKV_N 2304   // D + 2*KD

// Scratch (allocation-free rule: __device__ globals)
__device__ float g_qkv[(size_t)B_ * S_ * QKV_N];   // 37.75 MB
__device__ float g_max[(size_t)B_ * H_ * S_];
__device__ float g_sum[(size_t)B_ * H_ * S_];

// ---------------------------------------------------------------------------
// K1: C[M,N] = A[M,K] @ B[K,N] + bias[N]    (lda=K, ldb=N, ldc=N)
// BM=BN=128, BK=16, 256 threads, 8x8 per thread.
// ---------------------------------------------------------------------------
__global__ void __launch_bounds__(256) gemm_bias_nn(
    const float* __restrict__ A, const float* __restrict__ Bm,
    const float* __restrict__ bias, float* __restrict__ C,
    int K, int N)
{
    __shared__ float As[16][132];
    __shared__ float Bs[16][128];

    const int tid = threadIdx.x;
    const int m0 = blockIdx.y * 128;
    const int n0 = blockIdx.x * 128;
    const int tm = (tid / 16) * 8;
    const int tn = (tid % 16) * 8;

    float acc[8][8];
    #pragma unroll
    for (int i = 0; i < 8; i++)
        #pragma unroll
        for (int j = 0; j < 8; j++) acc[i][j] = 0.0f;

    for (int k0 = 0; k0 < K; k0 += 16) {
        #pragma unroll
        for (int l = 0; l < 2; l++) {
            int idx = tid + l * 256;          // 512 float4 for A
            int row = idx >> 2;
            int k4  = (idx & 3) * 4;
            float4 v = *(const float4*)(&A[(size_t)(m0 + row) * K + k0 + k4]);
            As[k4 + 0][row] = v.x;
            As[k4 + 1][row] = v.y;
            As[k4 + 2][row] = v.z;
            As[k4 + 3][row] = v.w;
        }
        #pragma unroll
        for (int l = 0; l < 2; l++) {
            int idx = tid + l * 256;          // 512 float4 for B
            int row = idx >> 5;
            int n4  = (idx & 31) * 4;
            *(float4*)(&Bs[row][n4]) =
                *(const float4*)(&Bm[(size_t)(k0 + row) * N + n0 + n4]);
        }
        __syncthreads();

        #pragma unroll
        for (int kk = 0; kk < 16; kk++) {
            float a[8], b[8];
            #pragma unroll
            for (int i = 0; i < 8; i++) a[i] = As[kk][tm + i];
            #pragma unroll
            for (int j = 0; j < 8; j++) b[j] = Bs[kk][tn + j];
            #pragma unroll
            for (int i = 0; i < 8; i++)
                #pragma unroll
                for (int j = 0; j < 8; j++)
                    acc[i][j] += a[i] * b[j];
        }
        __syncthreads();
    }

    #pragma unroll
    for (int i = 0; i < 8; i++) {
        size_t crow = (size_t)(m0 + tm + i) * N + n0;
        #pragma unroll
        for (int j = 0; j < 8; j++)
            C[crow + tn + j] = acc[i][j] + bias[n0 + tn + j];
    }
}

// ---------------------------------------------------------------------------
// K2: score[bh, s, t] = (q[b,s,h,:] . k[b,t,:]) / 16384
// A = qkv + b*S*QKV_N + h*KD   (ld QKV_N), B = qkv + b*S*QKV_N + D (ld QKV_N)
// BM=BN=128, BK=32 (K total = 128), 256 threads, 8x8 per thread.
// ---------------------------------------------------------------------------
__global__ void __launch_bounds__(256) score_kernel(float* __restrict__ score)
{
    __shared__ float As[32][132];
    __shared__ float Bs[32][132];

    const int bh = blockIdx.z;
    const int b  = bh >> 4;
    const int h  = bh & 15;
    const float* A  = g_qkv + (size_t)b * S_ * QKV_N + h * KD;
    const float* Bk = g_qkv + (size_t)b * S_ * QKV_N + D_;
    float* C = score + (size_t)bh * S_ * S_;

    const int m0 = blockIdx.y * 128;
    const int n0 = blockIdx.x * 128;
    const int tid = threadIdx.x;
    const int tm = (tid / 16) * 8;
    const int tn = (tid % 16) * 8;

    float acc[8][8];
    #pragma unroll
    for (int i = 0; i < 8; i++)
        #pragma unroll
        for (int j = 0; j < 8; j++) acc[i][j] = 0.0f;

    for (int k0 = 0; k0 < KD; k0 += 32) {
        #pragma unroll
        for (int l = 0; l < 4; l++) {
            int idx = tid + l * 256;       // 1024 float4 each for A and B
            int row = idx >> 3;
            int k4  = (idx & 7) * 4;
            float4 v = *(const float4*)(&A[(size_t)(m0 + row) * QKV_N + k0 + k4]);
            As[k4 + 0][row] = v.x;
            As[k4 + 1][row] = v.y;
            As[k4 + 2][row] = v.z;
            As[k4 + 3][row] = v.w;
            float4 w = *(const float4*)(&Bk[(size_t)(n0 + row) * QKV_N + k0 + k4]);
            Bs[k4 + 0][row] = w.x;
            Bs[k4 + 1][row] = w.y;
            Bs[k4 + 2][row] = w.z;
            Bs[k4 + 3][row] = w.w;
        }
        __syncthreads();

        #pragma unroll
        for (int kk = 0; kk < 32; kk++) {
            float a[8], bb[8];
            #pragma unroll
            for (int i = 0; i < 8; i++) a[i] = As[kk][tm + i];
            #pragma unroll
            for (int j = 0; j < 8; j++) bb[j] = Bs[kk][tn + j];
            #pragma unroll
            for (int i = 0; i < 8; i++)
                #pragma unroll
                for (int j = 0; j < 8; j++)
                    acc[i][j] += a[i] * bb[j];
        }
        __syncthreads();
    }

    const float inv = 1.0f / 16384.0f;
    #pragma unroll
    for (int i = 0; i < 8; i++) {
        size_t crow = (size_t)(m0 + tm + i) * S_ + n0;
        #pragma unroll
        for (int j = 0; j < 8; j++)
            C[crow + tn + j] = acc[i][j] * inv;
    }
}

// ---------------------------------------------------------------------------
// K3: per-row max and sum of exp over the score rows (65536 rows x 2048)
// ---------------------------------------------------------------------------
__global__ void __launch_bounds__(256) softmax_stats(const float* __restrict__ score)
{
    const int row = blockIdx.x;
    const float* p = score + (size_t)row * S_;
    const int tid  = threadIdx.x;
    const int lane = tid & 31;
    const int wid  = tid >> 5;

    __shared__ float red[8];

    float vals[8];
    float vmax = -1e30f;
    #pragma unroll
    for (int i = 0; i < 8; i++) {
        vals[i] = p[tid + i * 256];
        vmax = fmaxf(vmax, vals[i]);
    }
    #pragma unroll
    for (int o = 16; o > 0; o >>= 1)
        vmax = fmaxf(vmax, __shfl_xor_sync(0xFFFFFFFFu, vmax, o));
    if (lane == 0) red[wid] = vmax;
    __syncthreads();
    float m = red[0];
    #pragma unroll
    for (int w = 1; w < 8; w++) m = fmaxf(m, red[w]);
    __syncthreads();

    float s = 0.0f;
    #pragma unroll
    for (int i = 0; i < 8; i++) s += __expf(vals[i] - m);
    #pragma unroll
    for (int o = 16; o > 0; o >>= 1)
        s += __shfl_xor_sync(0xFFFFFFFFu, s, o);
    if (lane == 0) red[wid] = s;
    __syncthreads();
    if (tid == 0) {
        float t = 0.0f;
        #pragma unroll
        for (int w = 0; w < 8; w++) t += red[w];
        g_max[row] = m;
        g_sum[row] = t;
    }
}

// ---------------------------------------------------------------------------
// K4: atten[bh,s,:] = (exp(score[bh,s,:]-m)/l) @ v   and res transpose write.
// BM=128, BN=128(=KD), BK=32, K loop over S_=2048. exp fused into A-tile load.
// ---------------------------------------------------------------------------
__global__ void __launch_bounds__(256) attn_pv(
    const float* __restrict__ score, float* __restrict__ atten,
    float* __restrict__ res)
{
    __shared__ float As[32][132];
    __shared__ float Bs[32][128];
    __shared__ float smax[128];
    __shared__ float sinv[128];

    const int bh = blockIdx.y;
    const int b  = bh >> 4;
    const int h  = bh & 15;
    const float* A = score + (size_t)bh * S_ * S_;
    const float* V = g_qkv + (size_t)b * S_ * QKV_N + D_ + KD;  // ld QKV_N
    const int m0  = blockIdx.x * 128;
    const int tid = threadIdx.x;

    if (tid < 128) {
        int r = bh * S_ + m0 + tid;
        smax[tid] = g_max[r];
        sinv[tid] = 1.0f / g_sum[r];
    }
    __syncthreads();

    const int tm = (tid / 16) * 8;
    const int tn = (tid % 16) * 8;

    float acc[8][8];
    #pragma unroll
    for (int i = 0; i < 8; i++)
        #pragma unroll
        for (int j = 0; j < 8; j++) acc[i][j] = 0.0f;

    for (int k0 = 0; k0 < S_; k0 += 32) {
        #pragma unroll
        for (int l = 0; l < 4; l++) {
            int idx = tid + l * 256;
            // A tile (128 rows x 32 k), exp applied on the fly
            int row = idx >> 3;
            int k4  = (idx & 7) * 4;
            float4 v = *(const float4*)(&A[(size_t)(m0 + row) * S_ + k0 + k4]);
            float mx = smax[row];
            As[k4 + 0][row] = __expf(v.x - mx);
            As[k4 + 1][row] = __expf(v.y - mx);
            As[k4 + 2][row] = __expf(v.z - mx);
            As[k4 + 3][row] = __expf(v.w - mx);
            // B tile (32 k-rows x 128 n)
            int vrow = idx >> 5;
            int n4   = (idx & 31) * 4;
            *(float4*)(&Bs[vrow][n4]) =
                *(const float4*)(&V[(size_t)(k0 + vrow) * QKV_N + n4]);
        }
        __syncthreads();

        #pragma unroll
        for (int kk = 0; kk < 32; kk++) {
            float a[8], bb[8];
            #pragma unroll
            for (int i = 0; i < 8; i++) a[i] = As[kk][tm + i];
            #pragma unroll
            for (int j = 0; j < 8; j++) bb[j] = Bs[kk][tn + j];
            #pragma unroll
            for (int i = 0; i < 8; i++)
                #pragma unroll
                for (int j = 0; j < 8; j++)
                    acc[i][j] += a[i] * bb[j];
        }
        __syncthreads();
    }

    #pragma unroll
    for (int i = 0; i < 8; i++) {
        int s = m0 + tm + i;
        float il = sinv[tm + i];
        size_t arow = (size_t)bh * S_ * KD + (size_t)s * KD + tn;
        size_t rrow = ((size_t)(b * S_ + s)) * D_ + h * KD + tn;
        #pragma unroll
        for (int j = 0; j < 8; j++) {
            float o = acc[i][j] * il;
            atten[arow + j] = o;
            res[rrow + j]   = o;
        }
    }
}

// ---------------------------------------------------------------------------
extern "C" void kernel_launch(void* const* d_in, const int* in_sizes, int n_in,
                              void* d_out, int out_size)
{
    const float* in_x  = (const float*)d_in[0];
    const float* W_sc  = (const float*)d_in[1];
    const float* b_sc  = (const float*)d_in[2];
    const float* W_qkv = (const float*)d_in[3];
    const float* b_qkv = (const float*)d_in[4];

    float* out       = (float*)d_out;
    float* score     = out;                                      // B*H*S*S
    float* atten     = score + (size_t)B_ * H_ * S_ * S_;        // B*H*S*KD
    float* res       = atten + (size_t)B_ * H_ * S_ * KD;        // B*S*D
    float* short_cut = res   + (size_t)B_ * S_ * D_;             // B*S*D

    float* qkv_s = nullptr;
    cudaGetSymbolAddress((void**)&qkv_s, g_qkv);

    // short_cut = X @ W_sc + b_sc
    gemm_bias_nn<<<dim3(D_ / 128, (B_ * S_) / 128), 256>>>(
        in_x, W_sc, b_sc, short_cut, D_, D_);
    // qkv = X @ W_qkv + b_qkv
    gemm_bias_nn<<<dim3(QKV_N / 128, (B_ * S_) / 128), 256>>>(
        in_x, W_qkv, b_qkv, qkv_s, D_, QKV_N);
    // score = q k^T / kd^2
    score_kernel<<<dim3(S_ / 128, S_ / 128, B_ * H_), 256>>>(score);
    // softmax stats
    softmax_stats<<<B_ * H_ * S_, 256>>>(score);
    // atten + res
    attn_pv<<<dim3(S_ / 128, B_ * H_), 256>>>(score, atten, res);
}

// round 5
// speedup vs baseline: 2.2111x; 2.2111x over previous
#include <cuda_runtime.h>
#include <cuda_bf16.h>
#include <cstdint>
#include <cstddef>

#define S_    2048
#define D_    2048
#define QKV_N 2304
#define KD    128
#define NTOT  4352   // D + QKV_N
#define BH_   32
#define B_    2
#define H_    16

// ---------------- scratch (__device__ globals; no allocations) --------------
__device__ float g_qkv[(size_t)B_ * S_ * QKV_N];        // 37.7 MB
__device__ float g_wt[(size_t)NTOT * D_];               // 35.7 MB (concat W, [n][k])
__device__ float g_bias[NTOT];
__device__ float g_vt[(size_t)B_ * KD * S_];            // 2 MB  v^T per batch [d][t]
__device__ float g_partial[(size_t)64 * BH_ * S_];      // 16.8 MB, p-major partial sums
__device__ float g_sum[(size_t)BH_ * S_];

// ---------------- mma helper ------------------------------------------------
__device__ __forceinline__ void mma_bf16(float c[4], const uint32_t a[4],
                                         const uint32_t b[2]) {
    asm volatile(
        "mma.sync.aligned.m16n8k16.row.col.f32.bf16.bf16.f32 "
        "{%0,%1,%2,%3}, {%4,%5,%6,%7}, {%8,%9}, {%0,%1,%2,%3};"
        : "+f"(c[0]), "+f"(c[1]), "+f"(c[2]), "+f"(c[3])
        : "r"(a[0]), "r"(a[1]), "r"(a[2]), "r"(a[3]), "r"(b[0]), "r"(b[1]));
}

// split a float4 (4 consecutive k) into hi/lo bf16x2 pairs and store to smem
__device__ __forceinline__ void sst(uint32_t* hi, uint32_t* lo, int wof, float4 v) {
    __nv_bfloat162 h01 = __floats2bfloat162_rn(v.x, v.y);
    __nv_bfloat162 h23 = __floats2bfloat162_rn(v.z, v.w);
    float hx = __bfloat162float(h01.x), hy = __bfloat162float(h01.y);
    float hz = __bfloat162float(h23.x), hw = __bfloat162float(h23.y);
    __nv_bfloat162 l01 = __floats2bfloat162_rn(v.x - hx, v.y - hy);
    __nv_bfloat162 l23 = __floats2bfloat162_rn(v.z - hz, v.w - hw);
    hi[wof]     = *(uint32_t*)&h01;
    hi[wof + 1] = *(uint32_t*)&h23;
    lo[wof]     = *(uint32_t*)&l01;
    lo[wof + 1] = *(uint32_t*)&l23;
}

// ---------------------------------------------------------------------------
// prep: W concat transpose -> g_wt[n][k]  + bias concat
// ---------------------------------------------------------------------------
__global__ void __launch_bounds__(256) trans_w(
    const float* __restrict__ Wsc, const float* __restrict__ Wqkv,
    const float* __restrict__ bsc, const float* __restrict__ bqkv)
{
    __shared__ float t[32][33];
    const int n0 = blockIdx.x * 32, k0 = blockIdx.y * 32;
    const int tx = threadIdx.x & 31, ty = threadIdx.x >> 5;
    const int n = n0 + tx;
    #pragma unroll
    for (int r = 0; r < 4; r++) {
        int k = k0 + ty + r * 8;
        float v = (n < D_) ? Wsc[(size_t)k * D_ + n]
                           : Wqkv[(size_t)k * QKV_N + (n - D_)];
        t[ty + r * 8][tx] = v;
    }
    if (blockIdx.y == 0 && threadIdx.x < 32) {
        int nb = n0 + threadIdx.x;
        g_bias[nb] = (nb < D_) ? bsc[nb] : bqkv[nb - D_];
    }
    __syncthreads();
    #pragma unroll
    for (int r = 0; r < 4; r++)
        g_wt[(size_t)(n0 + ty + r * 8) * D_ + k0 + tx] = t[tx][ty + r * 8];
}

// prep: v transpose -> g_vt[b][d][t]
__global__ void __launch_bounds__(256) trans_v()
{
    __shared__ float t[32][33];
    const int b = blockIdx.z;
    const int t0 = blockIdx.x * 32, d0 = blockIdx.y * 32;
    const int tx = threadIdx.x & 31, ty = threadIdx.x >> 5;
    const float* q = g_qkv + (size_t)b * S_ * QKV_N + D_ + KD;
    #pragma unroll
    for (int r = 0; r < 4; r++)
        t[ty + r * 8][tx] = q[(size_t)(t0 + ty + r * 8) * QKV_N + d0 + tx];
    __syncthreads();
    #pragma unroll
    for (int r = 0; r < 4; r++)
        g_vt[(size_t)b * KD * S_ + (size_t)(d0 + ty + r * 8) * S_ + t0 + tx]
            = t[tx][ty + r * 8];
}

// reduce: g_sum[row] = sum of 64 p-major partials (coalesced)
__global__ void __launch_bounds__(256) reduce_sums()
{
    const int r = blockIdx.x * 256 + threadIdx.x;
    float s = 0.0f;
    #pragma unroll
    for (int p = 0; p < 64; p++)
        s += g_partial[(size_t)p * (BH_ * S_) + r];
    g_sum[r] = s;
}

// ---------------------------------------------------------------------------
// bf16x3 mma.sync GEMM. BM=BN=128, BK=32, 256 thr (8 warps, 2x4 warp grid,
// warp tile 64x32). Double-buffered smem, register prefetch, 1 sync/iter.
// SMEM planes (u32 words): A_hi | A_lo | B_hi | B_lo, row stride 18 words.
// MODE 0: C = X @ g_wt^T + bias     -> shortcut (n<2048) / g_qkv (n>=2048)
// MODE 1: score = q k^T / 16384     -> score + p-major partial sums of exp
// MODE 2: atten = exp(score) @ v^T / sum -> atten + res (head transpose)
// ---------------------------------------------------------------------------
#define PLW   2304        // 128 rows * 18 words
#define BUFW  (4 * PLW)   // words per buffer
#define SMEMB (2 * BUFW * 4)

template <int MODE>
__global__ void __launch_bounds__(256, 1) gemm_mma(
    const float* __restrict__ in_x, float* __restrict__ score,
    float* __restrict__ atten, float* __restrict__ res,
    float* __restrict__ shortcut)
{
    extern __shared__ uint32_t smw[];

    const int tid = threadIdx.x;
    const int warp = tid >> 5, lane = tid & 31;
    const int gid = lane >> 2, tig = lane & 3;
    const int wm = warp >> 2, wn = warp & 3;

    int m0, n0, bh = 0, bb = 0;
    const float *Ap, *Bp;
    int lda, ldb;
    constexpr int K = (MODE == 1) ? KD : ((MODE == 2) ? S_ : D_);
    constexpr int NITER = K / 32;

    if (MODE == 0) {
        m0 = blockIdx.y * 128; n0 = blockIdx.x * 128;
        Ap = in_x; lda = D_;  Bp = g_wt; ldb = D_;
    } else if (MODE == 1) {
        bh = blockIdx.z; bb = bh >> 4;
        m0 = blockIdx.y * 128; n0 = blockIdx.x * 128;
        Ap = g_qkv + (size_t)bb * S_ * QKV_N + (bh & 15) * KD; lda = QKV_N;
        Bp = g_qkv + (size_t)bb * S_ * QKV_N + D_;             ldb = QKV_N;
    } else {
        bh = blockIdx.y; bb = bh >> 4;
        m0 = blockIdx.x * 128; n0 = 0;
        Ap = score + (size_t)bh * S_ * S_; lda = S_;
        Bp = g_vt + (size_t)bb * KD * S_;  ldb = S_;
    }

    float c[4][4][4];
    #pragma unroll
    for (int mt = 0; mt < 4; mt++)
        #pragma unroll
        for (int nt = 0; nt < 4; nt++)
            #pragma unroll
            for (int q = 0; q < 4; q++) c[mt][nt][q] = 0.0f;

    float4 pa[4], pb[4];

    // -------- prologue: load iter 0, store to buf 0 --------
    #pragma unroll
    for (int l = 0; l < 4; l++) {
        int idx = tid + l * 256, row = idx >> 3, f4 = idx & 7;
        pa[l] = *(const float4*)(Ap + (size_t)(m0 + row) * lda + f4 * 4);
        pb[l] = *(const float4*)(Bp + (size_t)(n0 + row) * ldb + f4 * 4);
    }
    {
        uint32_t* ah = smw;            uint32_t* al = smw + PLW;
        uint32_t* bhp = smw + 2 * PLW; uint32_t* blp = smw + 3 * PLW;
        #pragma unroll
        for (int l = 0; l < 4; l++) {
            int idx = tid + l * 256, row = idx >> 3, f4 = idx & 7;
            int wof = row * 18 + f4 * 2;
            float4 va = pa[l];
            if (MODE == 2) {
                va.x = __expf(va.x); va.y = __expf(va.y);
                va.z = __expf(va.z); va.w = __expf(va.w);
            }
            sst(ah, al, wof, va);
            sst(bhp, blp, wof, pb[l]);
        }
    }
    __syncthreads();

    for (int it = 0; it < NITER; it++) {
        // prefetch next k-slab into registers
        if (it + 1 < NITER) {
            const int k0 = (it + 1) * 32;
            #pragma unroll
            for (int l = 0; l < 4; l++) {
                int idx = tid + l * 256, row = idx >> 3, f4 = idx & 7;
                pa[l] = *(const float4*)(Ap + (size_t)(m0 + row) * lda + k0 + f4 * 4);
                pb[l] = *(const float4*)(Bp + (size_t)(n0 + row) * ldb + k0 + f4 * 4);
            }
        }

        // -------- compute from buffer it&1 --------
        {
            const uint32_t* sa_h = smw + (it & 1) * BUFW;
            const uint32_t* sa_l = sa_h + PLW;
            const uint32_t* sb_h = sa_h + 2 * PLW;
            const uint32_t* sb_l = sa_h + 3 * PLW;
            #pragma unroll
            for (int ks = 0; ks < 2; ks++) {
                uint32_t afh[4][4], afl[4][4], bfh[4][2], bfl[4][2];
                #pragma unroll
                for (int mt = 0; mt < 4; mt++) {
                    int off = (wm * 64 + mt * 16 + gid) * 18 + ks * 8 + tig;
                    afh[mt][0] = sa_h[off];       afh[mt][2] = sa_h[off + 4];
                    afh[mt][1] = sa_h[off + 144]; afh[mt][3] = sa_h[off + 148];
                    afl[mt][0] = sa_l[off];       afl[mt][2] = sa_l[off + 4];
                    afl[mt][1] = sa_l[off + 144]; afl[mt][3] = sa_l[off + 148];
                }
                #pragma unroll
                for (int nt = 0; nt < 4; nt++) {
                    int off = (wn * 32 + nt * 8 + gid) * 18 + ks * 8 + tig;
                    bfh[nt][0] = sb_h[off]; bfh[nt][1] = sb_h[off + 4];
                    bfl[nt][0] = sb_l[off]; bfl[nt][1] = sb_l[off + 4];
                }
                #pragma unroll
                for (int mt = 0; mt < 4; mt++)
                    #pragma unroll
                    for (int nt = 0; nt < 4; nt++) {
                        mma_bf16(c[mt][nt], afh[mt], bfh[nt]);
                        mma_bf16(c[mt][nt], afh[mt], bfl[nt]);
                        mma_bf16(c[mt][nt], afl[mt], bfh[nt]);
                    }
            }
        }

        // -------- store prefetched slab to the other buffer --------
        if (it + 1 < NITER) {
            uint32_t* base = smw + ((it + 1) & 1) * BUFW;
            uint32_t* ah = base;            uint32_t* al = base + PLW;
            uint32_t* bhp = base + 2 * PLW; uint32_t* blp = base + 3 * PLW;
            #pragma unroll
            for (int l = 0; l < 4; l++) {
                int idx = tid + l * 256, row = idx >> 3, f4 = idx & 7;
                int wof = row * 18 + f4 * 2;
                float4 va = pa[l];
                if (MODE == 2) {
                    va.x = __expf(va.x); va.y = __expf(va.y);
                    va.z = __expf(va.z); va.w = __expf(va.w);
                }
                sst(ah, al, wof, va);
                sst(bhp, blp, wof, pb[l]);
            }
            __syncthreads();
        }
    }

    // ------------------------------ epilogue --------------------------------
    if (MODE == 0) {
        #pragma unroll
        for (int mt = 0; mt < 4; mt++) {
            const int r0 = m0 + wm * 64 + mt * 16 + gid;
            #pragma unroll
            for (int nt = 0; nt < 4; nt++) {
                const int n = n0 + wn * 32 + nt * 8 + 2 * tig;
                const float b0 = g_bias[n], b1 = g_bias[n + 1];
                float* d0;
                float* d1;
                if (n < D_) {
                    d0 = shortcut + (size_t)r0 * D_ + n;
                    d1 = shortcut + (size_t)(r0 + 8) * D_ + n;
                } else {
                    d0 = g_qkv + (size_t)r0 * QKV_N + (n - D_);
                    d1 = g_qkv + (size_t)(r0 + 8) * QKV_N + (n - D_);
                }
                *(float2*)d0 = make_float2(c[mt][nt][0] + b0, c[mt][nt][1] + b1);
                *(float2*)d1 = make_float2(c[mt][nt][2] + b0, c[mt][nt][3] + b1);
            }
        }
    } else if (MODE == 1) {
        const float inv = 1.0f / 16384.0f;
        float* Cp = score + (size_t)bh * S_ * S_;
        float rs[4][2];
        #pragma unroll
        for (int mt = 0; mt < 4; mt++) { rs[mt][0] = 0.0f; rs[mt][1] = 0.0f; }
        #pragma unroll
        for (int mt = 0; mt < 4; mt++) {
            const int r0 = m0 + wm * 64 + mt * 16 + gid;
            #pragma unroll
            for (int nt = 0; nt < 4; nt++) {
                const int n = n0 + wn * 32 + nt * 8 + 2 * tig;
                float v0 = c[mt][nt][0] * inv, v1 = c[mt][nt][1] * inv;
                float v2 = c[mt][nt][2] * inv, v3 = c[mt][nt][3] * inv;
                *(float2*)(Cp + (size_t)r0 * S_ + n)       = make_float2(v0, v1);
                *(float2*)(Cp + (size_t)(r0 + 8) * S_ + n) = make_float2(v2, v3);
                rs[mt][0] += __expf(v0) + __expf(v1);
                rs[mt][1] += __expf(v2) + __expf(v3);
            }
        }
        const int pidx = blockIdx.x * 4 + wn;
        #pragma unroll
        for (int mt = 0; mt < 4; mt++) {
            #pragma unroll
            for (int hf = 0; hf < 2; hf++) {
                float v = rs[mt][hf];
                v += __shfl_xor_sync(0xFFFFFFFFu, v, 1);
                v += __shfl_xor_sync(0xFFFFFFFFu, v, 2);
                if (tig == 0) {
                    const int row = m0 + wm * 64 + mt * 16 + gid + hf * 8;
                    g_partial[(size_t)pidx * (BH_ * S_) + (size_t)bh * S_ + row] = v;
                }
            }
        }
    } else {
        #pragma unroll
        for (int mt = 0; mt < 4; mt++) {
            const int r0 = m0 + wm * 64 + mt * 16 + gid;
            const float il0 = 1.0f / g_sum[(size_t)bh * S_ + r0];
            const float il1 = 1.0f / g_sum[(size_t)bh * S_ + r0 + 8];
            #pragma unroll
            for (int nt = 0; nt < 4; nt++) {
                const int col = wn * 32 + nt * 8 + 2 * tig;
                float2 o0 = make_float2(c[mt][nt][0] * il0, c[mt][nt][1] * il0);
                float2 o1 = make_float2(c[mt][nt][2] * il1, c[mt][nt][3] * il1);
                *(float2*)(atten + (size_t)bh * S_ * KD + (size_t)r0 * KD + col) = o0;
                *(float2*)(atten + (size_t)bh * S_ * KD + (size_t)(r0 + 8) * KD + col) = o1;
                *(float2*)(res + (size_t)(bb * S_ + r0) * D_ + (bh & 15) * KD + col) = o0;
                *(float2*)(res + (size_t)(bb * S_ + r0 + 8) * D_ + (bh & 15) * KD + col) = o1;
            }
        }
    }
}

// ---------------------------------------------------------------------------
extern "C" void kernel_launch(void* const* d_in, const int* in_sizes, int n_in,
                              void* d_out, int out_size)
{
    const float* in_x  = (const float*)d_in[0];
    const float* W_sc  = (const float*)d_in[1];
    const float* b_sc  = (const float*)d_in[2];
    const float* W_qkv = (const float*)d_in[3];
    const float* b_qkv = (const float*)d_in[4];

    float* out       = (float*)d_out;
    float* score     = out;                                  // BH*S*S
    float* atten     = score + (size_t)BH_ * S_ * S_;        // BH*S*KD
    float* res       = atten + (size_t)BH_ * S_ * KD;        // B*S*D
    float* short_cut = res   + (size_t)B_ * S_ * D_;         // B*S*D

    cudaFuncSetAttribute(gemm_mma<0>, cudaFuncAttributeMaxDynamicSharedMemorySize, SMEMB);
    cudaFuncSetAttribute(gemm_mma<1>, cudaFuncAttributeMaxDynamicSharedMemorySize, SMEMB);
    cudaFuncSetAttribute(gemm_mma<2>, cudaFuncAttributeMaxDynamicSharedMemorySize, SMEMB);

    // 1. W/bias concat + transpose
    trans_w<<<dim3(NTOT / 32, D_ / 32), 256>>>(W_sc, W_qkv, b_sc, b_qkv);
    // 2. fused shortcut+qkv GEMM
    gemm_mma<0><<<dim3(NTOT / 128, (B_ * S_) / 128), 256, SMEMB>>>(
        in_x, score, atten, res, short_cut);
    // 3. v transpose
    trans_v<<<dim3(S_ / 32, KD / 32, B_), 256>>>();
    // 4. score GEMM (+ partial exp sums from accumulators)
    gemm_mma<1><<<dim3(S_ / 128, S_ / 128, BH_), 256, SMEMB>>>(
        in_x, score, atten, res, short_cut);
    // 5. softmax denominators
    reduce_sums<<<(BH_ * S_) / 256, 256>>>();
    // 6. PV GEMM (+ atten/res writes)
    gemm_mma<2><<<dim3(S_ / 128, BH_), 256, SMEMB>>>(
        in_x, score, atten, res, short_cut);
}

// round 6
// speedup vs baseline: 2.5118x; 1.1360x over previous
#include <cuda_runtime.h>
#include <cuda_bf16.h>
#include <cstdint>
#include <cstddef>

#define S_    2048
#define D_    2048
#define QKV_N 2304
#define KD    128
#define NTOT  4352   // D + QKV_N
#define BH_   32
#define B_    2
#define H_    16

// ---------------- scratch (__device__ globals; no allocations) --------------
__device__ float g_qkv[(size_t)B_ * S_ * QKV_N];        // 37.7 MB
__device__ float g_wt[(size_t)NTOT * D_];               // 35.7 MB (concat W, [n][k])
__device__ float g_bias[NTOT];
__device__ float g_vt[(size_t)B_ * KD * S_];            // 2 MB  v^T per batch [d][t]
__device__ float g_partial[(size_t)64 * BH_ * S_];      // 16.8 MB p-major partials
__device__ float g_sum[(size_t)BH_ * S_];

// ---------------- helpers ----------------------------------------------------
__device__ __forceinline__ uint32_t smem_u32(const void* p) {
    uint32_t a;
    asm("{ .reg .u64 t; cvta.to.shared.u64 t, %1; cvt.u32.u64 %0, t; }" : "=r"(a) : "l"(p));
    return a;
}
__device__ __forceinline__ void mma_bf16(float c[4], const uint32_t a[4],
                                         const uint32_t b[2]) {
    asm volatile(
        "mma.sync.aligned.m16n8k16.row.col.f32.bf16.bf16.f32 "
        "{%0,%1,%2,%3}, {%4,%5,%6,%7}, {%8,%9}, {%0,%1,%2,%3};"
        : "+f"(c[0]), "+f"(c[1]), "+f"(c[2]), "+f"(c[3])
        : "r"(a[0]), "r"(a[1]), "r"(a[2]), "r"(a[3]), "r"(b[0]), "r"(b[1]));
}
__device__ __forceinline__ void ldsm4(uint32_t r[4], uint32_t addr) {
    asm volatile("ldmatrix.sync.aligned.m8n8.x4.shared.b16 {%0,%1,%2,%3}, [%4];"
        : "=r"(r[0]), "=r"(r[1]), "=r"(r[2]), "=r"(r[3]) : "r"(addr));
}
// split float4 (4 consecutive k) into hi/lo bf16x2 and store to smem planes
__device__ __forceinline__ void sst(uint32_t* hi, uint32_t* lo, int wof, float4 v) {
    __nv_bfloat162 h01 = __floats2bfloat162_rn(v.x, v.y);
    __nv_bfloat162 h23 = __floats2bfloat162_rn(v.z, v.w);
    float hx = __bfloat162float(h01.x), hy = __bfloat162float(h01.y);
    float hz = __bfloat162float(h23.x), hw = __bfloat162float(h23.y);
    __nv_bfloat162 l01 = __floats2bfloat162_rn(v.x - hx, v.y - hy);
    __nv_bfloat162 l23 = __floats2bfloat162_rn(v.z - hz, v.w - hw);
    hi[wof]     = *(uint32_t*)&h01;
    hi[wof + 1] = *(uint32_t*)&h23;
    lo[wof]     = *(uint32_t*)&l01;
    lo[wof + 1] = *(uint32_t*)&l23;
}

// ---------------------------------------------------------------------------
// prep kernels
// ---------------------------------------------------------------------------
__global__ void __launch_bounds__(256) trans_w(
    const float* __restrict__ Wsc, const float* __restrict__ Wqkv,
    const float* __restrict__ bsc, const float* __restrict__ bqkv)
{
    __shared__ float t[32][33];
    const int n0 = blockIdx.x * 32, k0 = blockIdx.y * 32;
    const int tx = threadIdx.x & 31, ty = threadIdx.x >> 5;
    const int n = n0 + tx;
    #pragma unroll
    for (int r = 0; r < 4; r++) {
        int k = k0 + ty + r * 8;
        float v = (n < D_) ? Wsc[(size_t)k * D_ + n]
                           : Wqkv[(size_t)k * QKV_N + (n - D_)];
        t[ty + r * 8][tx] = v;
    }
    if (blockIdx.y == 0 && threadIdx.x < 32) {
        int nb = n0 + threadIdx.x;
        g_bias[nb] = (nb < D_) ? bsc[nb] : bqkv[nb - D_];
    }
    __syncthreads();
    #pragma unroll
    for (int r = 0; r < 4; r++)
        g_wt[(size_t)(n0 + ty + r * 8) * D_ + k0 + tx] = t[tx][ty + r * 8];
}

__global__ void __launch_bounds__(256) trans_v()
{
    __shared__ float t[32][33];
    const int b = blockIdx.z;
    const int t0 = blockIdx.x * 32, d0 = blockIdx.y * 32;
    const int tx = threadIdx.x & 31, ty = threadIdx.x >> 5;
    const float* q = g_qkv + (size_t)b * S_ * QKV_N + D_ + KD;
    #pragma unroll
    for (int r = 0; r < 4; r++)
        t[ty + r * 8][tx] = q[(size_t)(t0 + ty + r * 8) * QKV_N + d0 + tx];
    __syncthreads();
    #pragma unroll
    for (int r = 0; r < 4; r++)
        g_vt[(size_t)b * KD * S_ + (size_t)(d0 + ty + r * 8) * S_ + t0 + tx]
            = t[tx][ty + r * 8];
}

__global__ void __launch_bounds__(256) reduce_sums()
{
    const int r = blockIdx.x * 256 + threadIdx.x;
    float s = 0.0f;
    #pragma unroll
    for (int p = 0; p < 64; p++)
        s += g_partial[(size_t)p * (BH_ * S_) + r];
    g_sum[r] = s;
}

// ---------------------------------------------------------------------------
// bf16x3 mma.sync GEMM, 512 threads, warp grid 4x4, warp tile 32x32.
// BM=BN=128, BK=32, double-buffered smem, ldmatrix fragment loads.
// SMEM planes (u32 words, row stride 20): A_hi | A_lo | B_hi | B_lo.
// MODE 0: C = X @ g_wt^T + bias          -> shortcut / g_qkv
// MODE 1: score = q k^T / 16384          -> score + partial sums of exp
// MODE 2: atten = exp(score) @ v^T / sum -> atten + res
// ---------------------------------------------------------------------------
#define RSW   20                  // smem row stride in words
#define PLW   (128 * RSW)         // words per plane = 2560
#define BUFW  (4 * PLW)           // words per buffer = 10240
#define SMEMB (2 * BUFW * 4)      // 81920 B

template <int MODE>
__global__ void __launch_bounds__(512, 1) gemm_mma(
    const float* __restrict__ in_x, float* __restrict__ score,
    float* __restrict__ atten, float* __restrict__ res,
    float* __restrict__ shortcut)
{
    extern __shared__ uint32_t smw[];

    const int tid = threadIdx.x;
    const int warp = tid >> 5, lane = tid & 31;
    const int gid = lane >> 2, tig = lane & 3;
    const int wm = warp >> 2, wn = warp & 3;

    int m0, n0, bh = 0, bb = 0;
    const float *Ap, *Bp;
    int lda, ldb;
    constexpr int K = (MODE == 1) ? KD : ((MODE == 2) ? S_ : D_);
    constexpr int NITER = K / 32;

    if (MODE == 0) {
        m0 = blockIdx.y * 128; n0 = blockIdx.x * 128;
        Ap = in_x; lda = D_;  Bp = g_wt; ldb = D_;
    } else if (MODE == 1) {
        bh = blockIdx.z; bb = bh >> 4;
        m0 = blockIdx.y * 128; n0 = blockIdx.x * 128;
        Ap = g_qkv + (size_t)bb * S_ * QKV_N + (bh & 15) * KD; lda = QKV_N;
        Bp = g_qkv + (size_t)bb * S_ * QKV_N + D_;             ldb = QKV_N;
    } else {
        bh = blockIdx.y; bb = bh >> 4;
        m0 = blockIdx.x * 128; n0 = 0;
        Ap = score + (size_t)bh * S_ * S_; lda = S_;
        Bp = g_vt + (size_t)bb * KD * S_;  ldb = S_;
    }

    // ldmatrix per-lane base byte addresses (within buffer 0, ks=0, hi planes)
    const uint32_t smb = smem_u32(smw);
    const int lr = lane & 7;
    const int a_r8 = (lane >> 3) & 1, a_kh = lane >> 4;
    const int b_r8 = lane >> 4,       b_kh = (lane >> 3) & 1;
    uint32_t aAddr[2], bAddr[2];
    #pragma unroll
    for (int mt = 0; mt < 2; mt++)
        aAddr[mt] = smb + 4u * ((uint32_t)(wm * 32 + mt * 16 + lr + a_r8 * 8) * RSW
                                + a_kh * 4);
    #pragma unroll
    for (int np = 0; np < 2; np++)
        bAddr[np] = smb + 4u * ((uint32_t)(2 * PLW)
                                + (uint32_t)(wn * 32 + np * 16 + lr + b_r8 * 8) * RSW
                                + b_kh * 4);

    float c[2][4][4];
    #pragma unroll
    for (int mt = 0; mt < 2; mt++)
        #pragma unroll
        for (int nt = 0; nt < 4; nt++)
            #pragma unroll
            for (int q = 0; q < 4; q++) c[mt][nt][q] = 0.0f;

    float4 pa[2], pb[2];

    // -------- prologue: load iter 0, split-store to buf 0 --------
    #pragma unroll
    for (int l = 0; l < 2; l++) {
        int idx = tid + l * 512, row = idx >> 3, f4 = idx & 7;
        pa[l] = *(const float4*)(Ap + (size_t)(m0 + row) * lda + f4 * 4);
        pb[l] = *(const float4*)(Bp + (size_t)(n0 + row) * ldb + f4 * 4);
    }
    {
        uint32_t* ah = smw;            uint32_t* al = smw + PLW;
        uint32_t* bhp = smw + 2 * PLW; uint32_t* blp = smw + 3 * PLW;
        #pragma unroll
        for (int l = 0; l < 2; l++) {
            int idx = tid + l * 512, row = idx >> 3, f4 = idx & 7;
            int wof = row * RSW + f4 * 2;
            float4 va = pa[l];
            if (MODE == 2) {
                va.x = __expf(va.x); va.y = __expf(va.y);
                va.z = __expf(va.z); va.w = __expf(va.w);
            }
            sst(ah, al, wof, va);
            sst(bhp, blp, wof, pb[l]);
        }
    }
    __syncthreads();

    for (int it = 0; it < NITER; it++) {
        if (it + 1 < NITER) {
            const int k0 = (it + 1) * 32;
            #pragma unroll
            for (int l = 0; l < 2; l++) {
                int idx = tid + l * 512, row = idx >> 3, f4 = idx & 7;
                pa[l] = *(const float4*)(Ap + (size_t)(m0 + row) * lda + k0 + f4 * 4);
                pb[l] = *(const float4*)(Bp + (size_t)(n0 + row) * ldb + k0 + f4 * 4);
            }
        }

        // -------- compute from buffer it&1 --------
        {
            const uint32_t bufB = (uint32_t)((it & 1) * BUFW * 4);
            #pragma unroll
            for (int ks = 0; ks < 2; ks++) {
                const uint32_t ko = bufB + (uint32_t)(ks * 32);
                uint32_t ah[2][4], alo[2][4], bh2[2][4], bl2[2][4];
                #pragma unroll
                for (int mt = 0; mt < 2; mt++) {
                    ldsm4(ah[mt],  aAddr[mt] + ko);
                    ldsm4(alo[mt], aAddr[mt] + ko + (uint32_t)(PLW * 4));
                }
                #pragma unroll
                for (int np = 0; np < 2; np++) {
                    ldsm4(bh2[np], bAddr[np] + ko);
                    ldsm4(bl2[np], bAddr[np] + ko + (uint32_t)(PLW * 4));
                }
                #pragma unroll
                for (int mt = 0; mt < 2; mt++)
                    #pragma unroll
                    for (int nt = 0; nt < 4; nt++) {
                        const uint32_t* bh = &bh2[nt >> 1][(nt & 1) * 2];
                        const uint32_t* bl = &bl2[nt >> 1][(nt & 1) * 2];
                        mma_bf16(c[mt][nt], ah[mt],  bh);
                        mma_bf16(c[mt][nt], ah[mt],  bl);
                        mma_bf16(c[mt][nt], alo[mt], bh);
                    }
            }
        }

        // -------- store prefetched slab into the other buffer --------
        if (it + 1 < NITER) {
            __syncthreads();   // everyone done reading buf (it+1)&1 from 2 iters ago
            uint32_t* base = smw + ((it + 1) & 1) * BUFW;
            uint32_t* ah = base;            uint32_t* al = base + PLW;
            uint32_t* bhp = base + 2 * PLW; uint32_t* blp = base + 3 * PLW;
            #pragma unroll
            for (int l = 0; l < 2; l++) {
                int idx = tid + l * 512, row = idx >> 3, f4 = idx & 7;
                int wof = row * RSW + f4 * 2;
                float4 va = pa[l];
                if (MODE == 2) {
                    va.x = __expf(va.x); va.y = __expf(va.y);
                    va.z = __expf(va.z); va.w = __expf(va.w);
                }
                sst(ah, al, wof, va);
                sst(bhp, blp, wof, pb[l]);
            }
            __syncthreads();
        }
    }

    // ------------------------------ epilogue --------------------------------
    if (MODE == 0) {
        #pragma unroll
        for (int mt = 0; mt < 2; mt++) {
            const int r0 = m0 + wm * 32 + mt * 16 + gid;
            #pragma unroll
            for (int nt = 0; nt < 4; nt++) {
                const int n = n0 + wn * 32 + nt * 8 + 2 * tig;
                const float b0 = g_bias[n], b1 = g_bias[n + 1];
                float *d0, *d1;
                if (n < D_) {
                    d0 = shortcut + (size_t)r0 * D_ + n;
                    d1 = shortcut + (size_t)(r0 + 8) * D_ + n;
                } else {
                    d0 = g_qkv + (size_t)r0 * QKV_N + (n - D_);
                    d1 = g_qkv + (size_t)(r0 + 8) * QKV_N + (n - D_);
                }
                *(float2*)d0 = make_float2(c[mt][nt][0] + b0, c[mt][nt][1] + b1);
                *(float2*)d1 = make_float2(c[mt][nt][2] + b0, c[mt][nt][3] + b1);
            }
        }
    } else if (MODE == 1) {
        const float inv = 1.0f / 16384.0f;
        float* Cp = score + (size_t)bh * S_ * S_;
        #pragma unroll
        for (int mt = 0; mt < 2; mt++) {
            const int r0 = m0 + wm * 32 + mt * 16 + gid;
            float rs0 = 0.0f, rs1 = 0.0f;
            #pragma unroll
            for (int nt = 0; nt < 4; nt++) {
                const int n = n0 + wn * 32 + nt * 8 + 2 * tig;
                float v0 = c[mt][nt][0] * inv, v1 = c[mt][nt][1] * inv;
                float v2 = c[mt][nt][2] * inv, v3 = c[mt][nt][3] * inv;
                *(float2*)(Cp + (size_t)r0 * S_ + n)       = make_float2(v0, v1);
                *(float2*)(Cp + (size_t)(r0 + 8) * S_ + n) = make_float2(v2, v3);
                rs0 += __expf(v0) + __expf(v1);
                rs1 += __expf(v2) + __expf(v3);
            }
            rs0 += __shfl_xor_sync(0xFFFFFFFFu, rs0, 1);
            rs0 += __shfl_xor_sync(0xFFFFFFFFu, rs0, 2);
            rs1 += __shfl_xor_sync(0xFFFFFFFFu, rs1, 1);
            rs1 += __shfl_xor_sync(0xFFFFFFFFu, rs1, 2);
            if (tig == 0) {
                const size_t pidx = (size_t)(blockIdx.x * 4 + wn) * (BH_ * S_)
                                  + (size_t)bh * S_;
                g_partial[pidx + r0]     = rs0;
                g_partial[pidx + r0 + 8] = rs1;
            }
        }
    } else {
        #pragma unroll
        for (int mt = 0; mt < 2; mt++) {
            const int r0 = m0 + wm * 32 + mt * 16 + gid;
            const float il0 = 1.0f / g_sum[(size_t)bh * S_ + r0];
            const float il1 = 1.0f / g_sum[(size_t)bh * S_ + r0 + 8];
            #pragma unroll
            for (int nt = 0; nt < 4; nt++) {
                const int col = wn * 32 + nt * 8 + 2 * tig;
                float2 o0 = make_float2(c[mt][nt][0] * il0, c[mt][nt][1] * il0);
                float2 o1 = make_float2(c[mt][nt][2] * il1, c[mt][nt][3] * il1);
                *(float2*)(atten + (size_t)bh * S_ * KD + (size_t)r0 * KD + col) = o0;
                *(float2*)(atten + (size_t)bh * S_ * KD + (size_t)(r0 + 8) * KD + col) = o1;
                *(float2*)(res + (size_t)(bb * S_ + r0) * D_ + (bh & 15) * KD + col) = o0;
                *(float2*)(res + (size_t)(bb * S_ + r0 + 8) * D_ + (bh & 15) * KD + col) = o1;
            }
        }
    }
}

// ---------------------------------------------------------------------------
extern "C" void kernel_launch(void* const* d_in, const int* in_sizes, int n_in,
                              void* d_out, int out_size)
{
    const float* in_x  = (const float*)d_in[0];
    const float* W_sc  = (const float*)d_in[1];
    const float* b_sc  = (const float*)d_in[2];
    const float* W_qkv = (const float*)d_in[3];
    const float* b_qkv = (const float*)d_in[4];

    float* out       = (float*)d_out;
    float* score     = out;
    float* atten     = score + (size_t)BH_ * S_ * S_;
    float* res       = atten + (size_t)BH_ * S_ * KD;
    float* short_cut = res   + (size_t)B_ * S_ * D_;

    cudaFuncSetAttribute(gemm_mma<0>, cudaFuncAttributeMaxDynamicSharedMemorySize, SMEMB);
    cudaFuncSetAttribute(gemm_mma<1>, cudaFuncAttributeMaxDynamicSharedMemorySize, SMEMB);
    cudaFuncSetAttribute(gemm_mma<2>, cudaFuncAttributeMaxDynamicSharedMemorySize, SMEMB);

    trans_w<<<dim3(NTOT / 32, D_ / 32), 256>>>(W_sc, W_qkv, b_sc, b_qkv);
    gemm_mma<0><<<dim3(NTOT / 128, (B_ * S_) / 128), 512, SMEMB>>>(
        in_x, score, atten, res, short_cut);
    trans_v<<<dim3(S_ / 32, KD / 32, B_), 256>>>();
    gemm_mma<1><<<dim3(S_ / 128, S_ / 128, BH_), 512, SMEMB>>>(
        in_x, score, atten, res, short_cut);
    reduce_sums<<<(BH_ * S_) / 256, 256>>>();
    gemm_mma<2><<<dim3(S_ / 128, BH_), 512, SMEMB>>>(
        in_x, score, atten, res, short_cut);
}

// round 7
// speedup vs baseline: 2.6599x; 1.0589x over previous
#include <cuda_runtime.h>
#include <cuda_bf16.h>
#include <cstdint>
#include <cstddef>

#define S_    2048
#define D_    2048
#define QKV_N 2304
#define KD    128
#define NTOT  4352   // D + QKV_N
#define BH_   32
#define B_    2
#define H_    16

// ---------------- scratch (__device__ globals; no allocations) --------------
// packed format per 32-k chunk (u32 units): [0..15] = 32 bf16 hi, [16..31] = 32 bf16 lo
__device__ __align__(128) uint32_t g_xp[(size_t)B_ * S_ * D_];       // 33.5 MB
__device__ __align__(128) uint32_t g_wtp[(size_t)NTOT * D_];         // 35.7 MB
__device__ __align__(128) uint32_t g_qkvp[(size_t)B_ * S_ * QKV_N]; // 37.7 MB
__device__ __align__(128) uint32_t g_vtp[(size_t)B_ * KD * S_];     // 2 MB
__device__ float g_v[(size_t)B_ * S_ * KD];                          // 2 MB (v fp32 for transpose)
__device__ float g_bias[NTOT];
__device__ float g_partial[(size_t)64 * BH_ * S_];                   // 16.8 MB
__device__ float g_sum[(size_t)BH_ * S_];

// ---------------- helpers ----------------------------------------------------
__device__ __forceinline__ uint32_t smem_u32(const void* p) {
    uint32_t a;
    asm("{ .reg .u64 t; cvta.to.shared.u64 t, %1; cvt.u32.u64 %0, t; }" : "=r"(a) : "l"(p));
    return a;
}
__device__ __forceinline__ void mma_bf16(float c[4], const uint32_t a[4],
                                         const uint32_t b[2]) {
    asm volatile(
        "mma.sync.aligned.m16n8k16.row.col.f32.bf16.bf16.f32 "
        "{%0,%1,%2,%3}, {%4,%5,%6,%7}, {%8,%9}, {%0,%1,%2,%3};"
        : "+f"(c[0]), "+f"(c[1]), "+f"(c[2]), "+f"(c[3])
        : "r"(a[0]), "r"(a[1]), "r"(a[2]), "r"(a[3]), "r"(b[0]), "r"(b[1]));
}
__device__ __forceinline__ void ldsm4(uint32_t r[4], uint32_t addr) {
    asm volatile("ldmatrix.sync.aligned.m8n8.x4.shared.b16 {%0,%1,%2,%3}, [%4];"
        : "=r"(r[0]), "=r"(r[1]), "=r"(r[2]), "=r"(r[3]) : "r"(addr));
}
__device__ __forceinline__ void cpa16(uint32_t s, const void* g) {
    asm volatile("cp.async.cg.shared.global [%0], [%1], 16;" :: "r"(s), "l"(g) : "memory");
}
__device__ __forceinline__ void cpa_commit() {
    asm volatile("cp.async.commit_group;" ::: "memory");
}
__device__ __forceinline__ void cpa_wait1() {
    asm volatile("cp.async.wait_group 1;" ::: "memory");
}
__device__ __forceinline__ void cpa_wait0() {
    asm volatile("cp.async.wait_group 0;" ::: "memory");
}
// split 4 fp32 into hi/lo bf16x2 u32 pairs
__device__ __forceinline__ void split4u(float4 v, uint32_t& h01, uint32_t& h23,
                                        uint32_t& l01, uint32_t& l23) {
    __nv_bfloat162 h0 = __floats2bfloat162_rn(v.x, v.y);
    __nv_bfloat162 h1 = __floats2bfloat162_rn(v.z, v.w);
    __nv_bfloat162 l0 = __floats2bfloat162_rn(v.x - __bfloat162float(h0.x),
                                              v.y - __bfloat162float(h0.y));
    __nv_bfloat162 l1 = __floats2bfloat162_rn(v.z - __bfloat162float(h1.x),
                                              v.w - __bfloat162float(h1.y));
    h01 = *(uint32_t*)&h0; h23 = *(uint32_t*)&h1;
    l01 = *(uint32_t*)&l0; l23 = *(uint32_t*)&l1;
}

// ---------------------------------------------------------------------------
// prep: pack X into hi/lo chunk layout
// ---------------------------------------------------------------------------
__global__ void __launch_bounds__(256) pack_x(const float* __restrict__ in_x)
{
    const size_t fid = (size_t)blockIdx.x * 256 + threadIdx.x; // one float4 each
    const size_t row = fid >> 9;         // 512 float4 per row (D=2048)
    const int r = (int)(fid & 511);
    const int kc = r >> 3, f4 = r & 7, w = f4 * 4;
    float4 v = *(const float4*)(in_x + row * D_ + kc * 32 + w);
    uint32_t h01, h23, l01, l23;
    split4u(v, h01, h23, l01, l23);
    const size_t b32 = row * D_ + kc * 32;
    g_xp[b32 + (w >> 1)]      = h01;
    g_xp[b32 + (w >> 1) + 1]  = h23;
    g_xp[b32 + 16 + (w >> 1)] = l01;
    g_xp[b32 + 17 + (w >> 1)] = l23;
}

// prep: W concat + transpose + split-pack -> g_wtp[n][k], bias concat
__global__ void __launch_bounds__(256) trans_w(
    const float* __restrict__ Wsc, const float* __restrict__ Wqkv,
    const float* __restrict__ bsc, const float* __restrict__ bqkv)
{
    __shared__ float t[32][33];
    const int n0 = blockIdx.x * 32, k0 = blockIdx.y * 32;
    const int tx = threadIdx.x & 31, ty = threadIdx.x >> 5;
    const int n = n0 + tx;
    #pragma unroll
    for (int r = 0; r < 4; r++) {
        int k = k0 + ty + r * 8;
        t[ty + r * 8][tx] = (n < D_) ? Wsc[(size_t)k * D_ + n]
                                     : Wqkv[(size_t)k * QKV_N + (n - D_)];
    }
    if (blockIdx.y == 0 && threadIdx.x < 32) {
        int nb = n0 + threadIdx.x;
        g_bias[nb] = (nb < D_) ? bsc[nb] : bqkv[nb - D_];
    }
    __syncthreads();
    uint16_t* p16 = (uint16_t*)g_wtp;
    const int kc = k0 >> 5;
    #pragma unroll
    for (int r = 0; r < 4; r++) {
        const int nn = n0 + ty + r * 8;
        float v = t[tx][ty + r * 8];
        __nv_bfloat16 h = __float2bfloat16(v);
        __nv_bfloat16 l = __float2bfloat16(v - __bfloat162float(h));
        size_t b16 = 2 * ((size_t)nn * D_ + (size_t)kc * 32);
        p16[b16 + tx]      = *(uint16_t*)&h;
        p16[b16 + 32 + tx] = *(uint16_t*)&l;
    }
}

// prep: v transpose + split-pack -> g_vtp[b][d][tchunk]
__global__ void __launch_bounds__(256) trans_v()
{
    __shared__ float t[32][33];
    const int b = blockIdx.z;
    const int t0 = blockIdx.x * 32, d0 = blockIdx.y * 32;
    const int tx = threadIdx.x & 31, ty = threadIdx.x >> 5;
    #pragma unroll
    for (int r = 0; r < 4; r++)
        t[ty + r * 8][tx] = g_v[(size_t)(b * S_ + t0 + ty + r * 8) * KD + d0 + tx];
    __syncthreads();
    uint16_t* p16 = (uint16_t*)g_vtp;
    const int tc = t0 >> 5;
    #pragma unroll
    for (int r = 0; r < 4; r++) {
        const int d = d0 + ty + r * 8;
        float v = t[tx][ty + r * 8];
        __nv_bfloat16 h = __float2bfloat16(v);
        __nv_bfloat16 l = __float2bfloat16(v - __bfloat162float(h));
        size_t b16 = 2 * ((size_t)b * KD * S_ + (size_t)d * S_ + (size_t)tc * 32);
        p16[b16 + tx]      = *(uint16_t*)&h;
        p16[b16 + 32 + tx] = *(uint16_t*)&l;
    }
}

__global__ void __launch_bounds__(256) reduce_sums()
{
    const int r = blockIdx.x * 256 + threadIdx.x;
    float s = 0.0f;
    #pragma unroll
    for (int p = 0; p < 64; p++)
        s += g_partial[(size_t)p * (BH_ * S_) + r];
    g_sum[r] = s;
}

// ---------------------------------------------------------------------------
// bf16x3 mma.sync GEMM, cp.async mainloop over preconverted operands.
// 512 thr, warp grid 4x4, warp tile 32x32, BM=BN=128, BK=32, 2-stage smem.
// Stage layout (bytes): A[128 rows x 144] | B[128 rows x 144]; row = 64B hi | 64B lo | 16B pad
// MODE 0: C = X @ Wt^T + bias            -> shortcut fp32 / q,k packed + v fp32
// MODE 1: score = q k^T / 16384          -> score + partial sums of exp
// MODE 2: atten = exp(score) @ v^T / sum -> atten + res
// ---------------------------------------------------------------------------
#define RSB    144                    // smem row stride bytes
#define ABYTES (128 * RSB)            // 18432
#define STAGEB (2 * ABYTES)           // 36864
#define SMEMB  (2 * STAGEB)           // 73728

template <int MODE>
__global__ void __launch_bounds__(512, 1) gemm_mma(
    const float* __restrict__ score_in, float* __restrict__ score,
    float* __restrict__ atten, float* __restrict__ res,
    float* __restrict__ shortcut)
{
    extern __shared__ uint32_t smw[];
    char* smc = (char*)smw;

    const int tid = threadIdx.x;
    const int warp = tid >> 5, lane = tid & 31;
    const int gid = lane >> 2, tig = lane & 3;
    const int wm = warp >> 2, wn = warp & 3;

    int m0, n0, bh = 0, bb = 0;
    const uint32_t *ApU = nullptr, *BpU = nullptr;
    const float* Af = nullptr;          // MODE2 fp32 A (score)
    int ldaU = 0, ldbU = 0, kcA0 = 0, kcB0 = 0;
    constexpr int K = (MODE == 1) ? KD : ((MODE == 2) ? S_ : D_);
    constexpr int NITER = K / 32;

    if (MODE == 0) {
        m0 = blockIdx.y * 128; n0 = blockIdx.x * 128;
        ApU = g_xp;  ldaU = D_; kcA0 = 0;
        BpU = g_wtp; ldbU = D_; kcB0 = 0;
    } else if (MODE == 1) {
        bh = blockIdx.z; bb = bh >> 4;
        m0 = blockIdx.y * 128; n0 = blockIdx.x * 128;
        ApU = g_qkvp + (size_t)bb * S_ * QKV_N; ldaU = QKV_N; kcA0 = 4 * (bh & 15);
        BpU = ApU;                              ldbU = QKV_N; kcB0 = 64;
    } else {
        bh = blockIdx.y; bb = bh >> 4;
        m0 = blockIdx.x * 128; n0 = 0;
        Af  = score_in + (size_t)bh * S_ * S_;
        BpU = g_vtp + (size_t)bb * KD * S_; ldbU = S_; kcB0 = 0;
    }

    // ldmatrix per-lane base addresses (stage 0, ks=0, hi plane)
    const uint32_t smb = smem_u32(smw);
    const int lr = lane & 7;
    const int a_r8 = (lane >> 3) & 1, a_kh = lane >> 4;
    const int b_r8 = lane >> 4,       b_kh = (lane >> 3) & 1;
    uint32_t aAddr[2], bAddr[2];
    #pragma unroll
    for (int mt = 0; mt < 2; mt++)
        aAddr[mt] = smb + (uint32_t)(wm * 32 + mt * 16 + lr + a_r8 * 8) * RSB
                  + (uint32_t)(a_kh * 16);
    #pragma unroll
    for (int np = 0; np < 2; np++)
        bAddr[np] = smb + (uint32_t)ABYTES
                  + (uint32_t)(wn * 32 + np * 16 + lr + b_r8 * 8) * RSB
                  + (uint32_t)(b_kh * 16);

    float c[2][4][4];
    #pragma unroll
    for (int mt = 0; mt < 2; mt++)
        #pragma unroll
        for (int nt = 0; nt < 4; nt++)
            #pragma unroll
            for (int q = 0; q < 4; q++) c[mt][nt][q] = 0.0f;

    // per-thread cp.async coordinates (2 chunks per operand)
    const int c_row0 = tid >> 3,        c16_0 = tid & 7;
    const int c_row1 = (tid + 512) >> 3, c16_1 = (tid + 512) & 7;

    // ---- fill one stage via cp.async (A for MODE 0/1, B always) ----
    auto issue_stage = [&](int it, int st) {
        const uint32_t sbase = smb + (uint32_t)(st * STAGEB);
        if (MODE != 2) {
            cpa16(sbase + (uint32_t)c_row0 * RSB + c16_0 * 16,
                  ApU + (size_t)(m0 + c_row0) * ldaU + (kcA0 + it) * 32 + c16_0 * 4);
            cpa16(sbase + (uint32_t)c_row1 * RSB + c16_1 * 16,
                  ApU + (size_t)(m0 + c_row1) * ldaU + (kcA0 + it) * 32 + c16_1 * 4);
        }
        cpa16(sbase + ABYTES + (uint32_t)c_row0 * RSB + c16_0 * 16,
              BpU + (size_t)(n0 + c_row0) * ldbU + (kcB0 + it) * 32 + c16_0 * 4);
        cpa16(sbase + ABYTES + (uint32_t)c_row1 * RSB + c16_1 * 16,
              BpU + (size_t)(n0 + c_row1) * ldbU + (kcB0 + it) * 32 + c16_1 * 4);
        cpa_commit();
    };

    // MODE2: A tile (exp(score) split) register path
    float4 pa[2];
    auto load_a2 = [&](int it) {
        #pragma unroll
        for (int l = 0; l < 2; l++) {
            int idx = tid + l * 512, row = idx >> 3, f4 = idx & 7;
            pa[l] = *(const float4*)(Af + (size_t)(m0 + row) * S_ + it * 32 + f4 * 4);
        }
    };
    auto store_a2 = [&](int st) {
        char* base = smc + st * STAGEB;
        #pragma unroll
        for (int l = 0; l < 2; l++) {
            int idx = tid + l * 512, row = idx >> 3, f4 = idx & 7;
            float4 v = pa[l];
            v.x = __expf(v.x); v.y = __expf(v.y);
            v.z = __expf(v.z); v.w = __expf(v.w);
            uint32_t h01, h23, l01, l23;
            split4u(v, h01, h23, l01, l23);
            *(uint2*)(base + row * RSB + f4 * 8)      = make_uint2(h01, h23);
            *(uint2*)(base + row * RSB + 64 + f4 * 8) = make_uint2(l01, l23);
        }
    };

    // -------- prologue: stage 0 --------
    if (MODE == 2) { load_a2(0); store_a2(0); }
    issue_stage(0, 0);

    for (int it = 0; it < NITER; it++) {
        if (it + 1 < NITER) {
            if (MODE == 2) load_a2(it + 1);
            issue_stage(it + 1, (it + 1) & 1);
            cpa_wait1();
        } else {
            cpa_wait0();
        }
        __syncthreads();   // stage it fully visible

        // -------- compute from stage it&1 --------
        {
            const uint32_t so = (uint32_t)((it & 1) * STAGEB);
            #pragma unroll
            for (int ks = 0; ks < 2; ks++) {
                const uint32_t ko = so + (uint32_t)(ks * 32);
                uint32_t ah[2][4], alo[2][4], bh2[2][4], bl2[2][4];
                #pragma unroll
                for (int mt = 0; mt < 2; mt++) {
                    ldsm4(ah[mt],  aAddr[mt] + ko);
                    ldsm4(alo[mt], aAddr[mt] + ko + 64);
                }
                #pragma unroll
                for (int np = 0; np < 2; np++) {
                    ldsm4(bh2[np], bAddr[np] + ko);
                    ldsm4(bl2[np], bAddr[np] + ko + 64);
                }
                #pragma unroll
                for (int mt = 0; mt < 2; mt++)
                    #pragma unroll
                    for (int nt = 0; nt < 4; nt++) {
                        const uint32_t* bh = &bh2[nt >> 1][(nt & 1) * 2];
                        const uint32_t* bl = &bl2[nt >> 1][(nt & 1) * 2];
                        mma_bf16(c[mt][nt], ah[mt],  bh);
                        mma_bf16(c[mt][nt], ah[mt],  bl);
                        mma_bf16(c[mt][nt], alo[mt], bh);
                    }
            }
        }

        if (it + 1 < NITER) {
            __syncthreads();   // all reads of stage (it+1)&1's old data done
            if (MODE == 2) store_a2((it + 1) & 1);
        }
    }

    // ------------------------------ epilogue --------------------------------
    if (MODE == 0) {
        #pragma unroll
        for (int mt = 0; mt < 2; mt++) {
            const int r0 = m0 + wm * 32 + mt * 16 + gid;
            #pragma unroll
            for (int nt = 0; nt < 4; nt++) {
                const int n = n0 + wn * 32 + nt * 8 + 2 * tig;
                const float b0 = g_bias[n], b1 = g_bias[n + 1];
                float v00 = c[mt][nt][0] + b0, v01 = c[mt][nt][1] + b1;
                float v10 = c[mt][nt][2] + b0, v11 = c[mt][nt][3] + b1;
                if (n < D_) {
                    *(float2*)(shortcut + (size_t)r0 * D_ + n)       = make_float2(v00, v01);
                    *(float2*)(shortcut + (size_t)(r0 + 8) * D_ + n) = make_float2(v10, v11);
                } else {
                    const int col = n - D_;
                    const int chunk = col >> 5, w = col & 31;
                    // packed bf16 hi/lo write for q,k,v
                    __nv_bfloat162 h0 = __floats2bfloat162_rn(v00, v01);
                    __nv_bfloat162 l0 = __floats2bfloat162_rn(
                        v00 - __bfloat162float(h0.x), v01 - __bfloat162float(h0.y));
                    __nv_bfloat162 h1 = __floats2bfloat162_rn(v10, v11);
                    __nv_bfloat162 l1 = __floats2bfloat162_rn(
                        v10 - __bfloat162float(h1.x), v11 - __bfloat162float(h1.y));
                    size_t q0 = (size_t)r0 * QKV_N + (size_t)chunk * 32 + (w >> 1);
                    size_t q1 = (size_t)(r0 + 8) * QKV_N + (size_t)chunk * 32 + (w >> 1);
                    g_qkvp[q0]      = *(uint32_t*)&h0;
                    g_qkvp[q0 + 16] = *(uint32_t*)&l0;
                    g_qkvp[q1]      = *(uint32_t*)&h1;
                    g_qkvp[q1 + 16] = *(uint32_t*)&l1;
                    if (col >= D_ + KD) {   // v region: also fp32 for transpose
                        const int d = col - (D_ + KD);
                        *(float2*)(g_v + (size_t)r0 * KD + d)       = make_float2(v00, v01);
                        *(float2*)(g_v + (size_t)(r0 + 8) * KD + d) = make_float2(v10, v11);
                    }
                }
            }
        }
    } else if (MODE == 1) {
        const float inv = 1.0f / 16384.0f;
        float* Cp = score + (size_t)bh * S_ * S_;
        #pragma unroll
        for (int mt = 0; mt < 2; mt++) {
            const int r0 = m0 + wm * 32 + mt * 16 + gid;
            float rs0 = 0.0f, rs1 = 0.0f;
            #pragma unroll
            for (int nt = 0; nt < 4; nt++) {
                const int n = n0 + wn * 32 + nt * 8 + 2 * tig;
                float v0 = c[mt][nt][0] * inv, v1 = c[mt][nt][1] * inv;
                float v2 = c[mt][nt][2] * inv, v3 = c[mt][nt][3] * inv;
                *(float2*)(Cp + (size_t)r0 * S_ + n)       = make_float2(v0, v1);
                *(float2*)(Cp + (size_t)(r0 + 8) * S_ + n) = make_float2(v2, v3);
                rs0 += __expf(v0) + __expf(v1);
                rs1 += __expf(v2) + __expf(v3);
            }
            rs0 += __shfl_xor_sync(0xFFFFFFFFu, rs0, 1);
            rs0 += __shfl_xor_sync(0xFFFFFFFFu, rs0, 2);
            rs1 += __shfl_xor_sync(0xFFFFFFFFu, rs1, 1);
            rs1 += __shfl_xor_sync(0xFFFFFFFFu, rs1, 2);
            if (tig == 0) {
                const size_t pidx = (size_t)(blockIdx.x * 4 + wn) * (BH_ * S_)
                                  + (size_t)bh * S_;
                g_partial[pidx + r0]     = rs0;
                g_partial[pidx + r0 + 8] = rs1;
            }
        }
    } else {
        #pragma unroll
        for (int mt = 0; mt < 2; mt++) {
            const int r0 = m0 + wm * 32 + mt * 16 + gid;
            const float il0 = 1.0f / g_sum[(size_t)bh * S_ + r0];
            const float il1 = 1.0f / g_sum[(size_t)bh * S_ + r0 + 8];
            #pragma unroll
            for (int nt = 0; nt < 4; nt++) {
                const int col = wn * 32 + nt * 8 + 2 * tig;
                float2 o0 = make_float2(c[mt][nt][0] * il0, c[mt][nt][1] * il0);
                float2 o1 = make_float2(c[mt][nt][2] * il1, c[mt][nt][3] * il1);
                *(float2*)(atten + (size_t)bh * S_ * KD + (size_t)r0 * KD + col) = o0;
                *(float2*)(atten + (size_t)bh * S_ * KD + (size_t)(r0 + 8) * KD + col) = o1;
                *(float2*)(res + (size_t)(bb * S_ + r0) * D_ + (bh & 15) * KD + col) = o0;
                *(float2*)(res + (size_t)(bb * S_ + r0 + 8) * D_ + (bh & 15) * KD + col) = o1;
            }
        }
    }
}

// ---------------------------------------------------------------------------
extern "C" void kernel_launch(void* const* d_in, const int* in_sizes, int n_in,
                              void* d_out, int out_size)
{
    const float* in_x  = (const float*)d_in[0];
    const float* W_sc  = (const float*)d_in[1];
    const float* b_sc  = (const float*)d_in[2];
    const float* W_qkv = (const float*)d_in[3];
    const float* b_qkv = (const float*)d_in[4];

    float* out       = (float*)d_out;
    float* score     = out;
    float* atten     = score + (size_t)BH_ * S_ * S_;
    float* res       = atten + (size_t)BH_ * S_ * KD;
    float* short_cut = res   + (size_t)B_ * S_ * D_;

    cudaFuncSetAttribute(gemm_mma<0>, cudaFuncAttributeMaxDynamicSharedMemorySize, SMEMB);
    cudaFuncSetAttribute(gemm_mma<1>, cudaFuncAttributeMaxDynamicSharedMemorySize, SMEMB);
    cudaFuncSetAttribute(gemm_mma<2>, cudaFuncAttributeMaxDynamicSharedMemorySize, SMEMB);

    // prep: pack X, pack W^T (+bias)
    pack_x<<<(unsigned)(((size_t)B_ * S_ * D_ / 4) / 256), 256>>>(in_x);
    trans_w<<<dim3(NTOT / 32, D_ / 32), 256>>>(W_sc, W_qkv, b_sc, b_qkv);
    // fused shortcut+qkv GEMM (writes q,k,v packed + v fp32 + shortcut)
    gemm_mma<0><<<dim3(NTOT / 128, (B_ * S_) / 128), 512, SMEMB>>>(
        nullptr, score, atten, res, short_cut);
    // v^T pack
    trans_v<<<dim3(S_ / 32, KD / 32, B_), 256>>>();
    // score GEMM (+ partial exp sums)
    gemm_mma<1><<<dim3(S_ / 128, S_ / 128, BH_), 512, SMEMB>>>(
        nullptr, score, atten, res, short_cut);
    // softmax denominators
    reduce_sums<<<(BH_ * S_) / 256, 256>>>();
    // PV GEMM
    gemm_mma<2><<<dim3(S_ / 128, BH_), 512, SMEMB>>>(
        score, score, atten, res, short_cut);
}

// round 8
// speedup vs baseline: 2.6601x; 1.0001x over previous
#include <cuda_runtime.h>
#include <cuda_bf16.h>
#include <cstdint>
#include <cstddef>

#define S_    2048
#define D_    2048
#define QKV_N 2304
#define KD    128
#define NTOT  4352   // D + QKV_N
#define BH_   32
#define B_    2
#define H_    16

// ---------------- scratch (__device__ globals; no allocations) --------------
// packed format per 32-k chunk (u32 units): [0..15] = 32 bf16 hi, [16..31] = 32 bf16 lo
__device__ __align__(128) uint32_t g_xp[(size_t)B_ * S_ * D_];       // 33.5 MB
__device__ __align__(128) uint32_t g_wtp[(size_t)NTOT * D_];         // 35.7 MB
__device__ __align__(128) uint32_t g_qkvp[(size_t)B_ * S_ * QKV_N]; // 37.7 MB
__device__ __align__(128) uint32_t g_vtp[(size_t)B_ * KD * S_];     // 2 MB
__device__ float g_v[(size_t)B_ * S_ * KD];                          // 2 MB (v fp32 for transpose)
__device__ float g_bias[NTOT];
__device__ float g_partial[(size_t)64 * BH_ * S_];                   // 16.8 MB
__device__ float g_sum[(size_t)BH_ * S_];

// ---------------- helpers ----------------------------------------------------
__device__ __forceinline__ uint32_t smem_u32(const void* p) {
    uint32_t a;
    asm("{ .reg .u64 t; cvta.to.shared.u64 t, %1; cvt.u32.u64 %0, t; }" : "=r"(a) : "l"(p));
    return a;
}
__device__ __forceinline__ void mma_bf16(float c[4], const uint32_t a[4],
                                         const uint32_t b[2]) {
    asm volatile(
        "mma.sync.aligned.m16n8k16.row.col.f32.bf16.bf16.f32 "
        "{%0,%1,%2,%3}, {%4,%5,%6,%7}, {%8,%9}, {%0,%1,%2,%3};"
        : "+f"(c[0]), "+f"(c[1]), "+f"(c[2]), "+f"(c[3])
        : "r"(a[0]), "r"(a[1]), "r"(a[2]), "r"(a[3]), "r"(b[0]), "r"(b[1]));
}
__device__ __forceinline__ void ldsm4(uint32_t r[4], uint32_t addr) {
    asm volatile("ldmatrix.sync.aligned.m8n8.x4.shared.b16 {%0,%1,%2,%3}, [%4];"
        : "=r"(r[0]), "=r"(r[1]), "=r"(r[2]), "=r"(r[3]) : "r"(addr));
}
__device__ __forceinline__ void cpa16(uint32_t s, const void* g) {
    asm volatile("cp.async.cg.shared.global [%0], [%1], 16;" :: "r"(s), "l"(g) : "memory");
}
__device__ __forceinline__ void cpa_commit() {
    asm volatile("cp.async.commit_group;" ::: "memory");
}
__device__ __forceinline__ void cpa_wait1() {
    asm volatile("cp.async.wait_group 1;" ::: "memory");
}
__device__ __forceinline__ void cpa_wait0() {
    asm volatile("cp.async.wait_group 0;" ::: "memory");
}
// split 4 fp32 into hi/lo bf16x2 u32 pairs
__device__ __forceinline__ void split4u(float4 v, uint32_t& h01, uint32_t& h23,
                                        uint32_t& l01, uint32_t& l23) {
    __nv_bfloat162 h0 = __floats2bfloat162_rn(v.x, v.y);
    __nv_bfloat162 h1 = __floats2bfloat162_rn(v.z, v.w);
    __nv_bfloat162 l0 = __floats2bfloat162_rn(v.x - __bfloat162float(h0.x),
                                              v.y - __bfloat162float(h0.y));
    __nv_bfloat162 l1 = __floats2bfloat162_rn(v.z - __bfloat162float(h1.x),
                                              v.w - __bfloat162float(h1.y));
    h01 = *(uint32_t*)&h0; h23 = *(uint32_t*)&h1;
    l01 = *(uint32_t*)&l0; l23 = *(uint32_t*)&l1;
}

// ---------------------------------------------------------------------------
// prep: pack X into hi/lo chunk layout
// ---------------------------------------------------------------------------
__global__ void __launch_bounds__(256) pack_x(const float* __restrict__ in_x)
{
    const size_t fid = (size_t)blockIdx.x * 256 + threadIdx.x; // one float4 each
    const size_t row = fid >> 9;         // 512 float4 per row (D=2048)
    const int r = (int)(fid & 511);
    const int kc = r >> 3, f4 = r & 7, w = f4 * 4;
    float4 v = *(const float4*)(in_x + row * D_ + kc * 32 + w);
    uint32_t h01, h23, l01, l23;
    split4u(v, h01, h23, l01, l23);
    const size_t b32 = row * D_ + kc * 32;
    g_xp[b32 + (w >> 1)]      = h01;
    g_xp[b32 + (w >> 1) + 1]  = h23;
    g_xp[b32 + 16 + (w >> 1)] = l01;
    g_xp[b32 + 17 + (w >> 1)] = l23;
}

// prep: W concat + transpose + split-pack -> g_wtp[n][k], bias concat
__global__ void __launch_bounds__(256) trans_w(
    const float* __restrict__ Wsc, const float* __restrict__ Wqkv,
    const float* __restrict__ bsc, const float* __restrict__ bqkv)
{
    __shared__ float t[32][33];
    const int n0 = blockIdx.x * 32, k0 = blockIdx.y * 32;
    const int tx = threadIdx.x & 31, ty = threadIdx.x >> 5;
    const int n = n0 + tx;
    #pragma unroll
    for (int r = 0; r < 4; r++) {
        int k = k0 + ty + r * 8;
        t[ty + r * 8][tx] = (n < D_) ? Wsc[(size_t)k * D_ + n]
                                     : Wqkv[(size_t)k * QKV_N + (n - D_)];
    }
    if (blockIdx.y == 0 && threadIdx.x < 32) {
        int nb = n0 + threadIdx.x;
        g_bias[nb] = (nb < D_) ? bsc[nb] : bqkv[nb - D_];
    }
    __syncthreads();
    uint16_t* p16 = (uint16_t*)g_wtp;
    const int kc = k0 >> 5;
    #pragma unroll
    for (int r = 0; r < 4; r++) {
        const int nn = n0 + ty + r * 8;
        float v = t[tx][ty + r * 8];
        __nv_bfloat16 h = __float2bfloat16(v);
        __nv_bfloat16 l = __float2bfloat16(v - __bfloat162float(h));
        size_t b16 = 2 * ((size_t)nn * D_ + (size_t)kc * 32);
        p16[b16 + tx]      = *(uint16_t*)&h;
        p16[b16 + 32 + tx] = *(uint16_t*)&l;
    }
}

// prep: v transpose + split-pack -> g_vtp[b][d][tchunk]
__global__ void __launch_bounds__(256) trans_v()
{
    __shared__ float t[32][33];
    const int b = blockIdx.z;
    const int t0 = blockIdx.x * 32, d0 = blockIdx.y * 32;
    const int tx = threadIdx.x & 31, ty = threadIdx.x >> 5;
    #pragma unroll
    for (int r = 0; r < 4; r++)
        t[ty + r * 8][tx] = g_v[(size_t)(b * S_ + t0 + ty + r * 8) * KD + d0 + tx];
    __syncthreads();
    uint16_t* p16 = (uint16_t*)g_vtp;
    const int tc = t0 >> 5;
    #pragma unroll
    for (int r = 0; r < 4; r++) {
        const int d = d0 + ty + r * 8;
        float v = t[tx][ty + r * 8];
        __nv_bfloat16 h = __float2bfloat16(v);
        __nv_bfloat16 l = __float2bfloat16(v - __bfloat162float(h));
        size_t b16 = 2 * ((size_t)b * KD * S_ + (size_t)d * S_ + (size_t)tc * 32);
        p16[b16 + tx]      = *(uint16_t*)&h;
        p16[b16 + 32 + tx] = *(uint16_t*)&l;
    }
}

__global__ void __launch_bounds__(256) reduce_sums()
{
    const int r = blockIdx.x * 256 + threadIdx.x;
    float s = 0.0f;
    #pragma unroll
    for (int p = 0; p < 64; p++)
        s += g_partial[(size_t)p * (BH_ * S_) + r];
    g_sum[r] = s;
}

// ---------------------------------------------------------------------------
// bf16x3 mma.sync GEMM, cp.async mainloop over preconverted operands.
// 512 thr, warp grid 4x4, warp tile 32x32, BM=BN=128, BK=32, 2-stage smem.
// Stage layout (bytes): A[128 rows x 144] | B[128 rows x 144]; row = 64B hi | 64B lo | 16B pad
// MODE 0: C = X @ Wt^T + bias            -> shortcut fp32 / q,k packed + v fp32
// MODE 1: score = q k^T / 16384          -> score + partial sums of exp
// MODE 2: atten = exp(score) @ v^T / sum -> atten + res
// ---------------------------------------------------------------------------
#define RSB    144                    // smem row stride bytes
#define ABYTES (128 * RSB)            // 18432
#define STAGEB (2 * ABYTES)           // 36864
#define SMEMB  (2 * STAGEB)           // 73728

template <int MODE>
__global__ void __launch_bounds__(512, 1) gemm_mma(
    const float* __restrict__ score_in, float* __restrict__ score,
    float* __restrict__ atten, float* __restrict__ res,
    float* __restrict__ shortcut)
{
    extern __shared__ uint32_t smw[];
    char* smc = (char*)smw;

    const int tid = threadIdx.x;
    const int warp = tid >> 5, lane = tid & 31;
    const int gid = lane >> 2, tig = lane & 3;
    const int wm = warp >> 2, wn = warp & 3;

    int m0, n0, bh = 0, bb = 0;
    const uint32_t *ApU = nullptr, *BpU = nullptr;
    const float* Af = nullptr;          // MODE2 fp32 A (score)
    int ldaU = 0, ldbU = 0, kcA0 = 0, kcB0 = 0;
    constexpr int K = (MODE == 1) ? KD : ((MODE == 2) ? S_ : D_);
    constexpr int NITER = K / 32;

    if (MODE == 0) {
        m0 = blockIdx.y * 128; n0 = blockIdx.x * 128;
        ApU = g_xp;  ldaU = D_; kcA0 = 0;
        BpU = g_wtp; ldbU = D_; kcB0 = 0;
    } else if (MODE == 1) {
        bh = blockIdx.z; bb = bh >> 4;
        m0 = blockIdx.y * 128; n0 = blockIdx.x * 128;
        ApU = g_qkvp + (size_t)bb * S_ * QKV_N; ldaU = QKV_N; kcA0 = 4 * (bh & 15);
        BpU = ApU;                              ldbU = QKV_N; kcB0 = 64;
    } else {
        bh = blockIdx.y; bb = bh >> 4;
        m0 = blockIdx.x * 128; n0 = 0;
        Af  = score_in + (size_t)bh * S_ * S_;
        BpU = g_vtp + (size_t)bb * KD * S_; ldbU = S_; kcB0 = 0;
    }

    // ldmatrix per-lane base addresses (stage 0, ks=0, hi plane)
    const uint32_t smb = smem_u32(smw);
    const int lr = lane & 7;
    const int a_r8 = (lane >> 3) & 1, a_kh = lane >> 4;
    const int b_r8 = lane >> 4,       b_kh = (lane >> 3) & 1;
    uint32_t aAddr[2], bAddr[2];
    #pragma unroll
    for (int mt = 0; mt < 2; mt++)
        aAddr[mt] = smb + (uint32_t)(wm * 32 + mt * 16 + lr + a_r8 * 8) * RSB
                  + (uint32_t)(a_kh * 16);
    #pragma unroll
    for (int np = 0; np < 2; np++)
        bAddr[np] = smb + (uint32_t)ABYTES
                  + (uint32_t)(wn * 32 + np * 16 + lr + b_r8 * 8) * RSB
                  + (uint32_t)(b_kh * 16);

    float c[2][4][4];
    #pragma unroll
    for (int mt = 0; mt < 2; mt++)
        #pragma unroll
        for (int nt = 0; nt < 4; nt++)
            #pragma unroll
            for (int q = 0; q < 4; q++) c[mt][nt][q] = 0.0f;

    // per-thread cp.async coordinates (2 chunks per operand)
    const int c_row0 = tid >> 3,        c16_0 = tid & 7;
    const int c_row1 = (tid + 512) >> 3, c16_1 = (tid + 512) & 7;

    // ---- fill one stage via cp.async (A for MODE 0/1, B always) ----
    auto issue_stage = [&](int it, int st) {
        const uint32_t sbase = smb + (uint32_t)(st * STAGEB);
        if (MODE != 2) {
            cpa16(sbase + (uint32_t)c_row0 * RSB + c16_0 * 16,
                  ApU + (size_t)(m0 + c_row0) * ldaU + (kcA0 + it) * 32 + c16_0 * 4);
            cpa16(sbase + (uint32_t)c_row1 * RSB + c16_1 * 16,
                  ApU + (size_t)(m0 + c_row1) * ldaU + (kcA0 + it) * 32 + c16_1 * 4);
        }
        cpa16(sbase + ABYTES + (uint32_t)c_row0 * RSB + c16_0 * 16,
              BpU + (size_t)(n0 + c_row0) * ldbU + (kcB0 + it) * 32 + c16_0 * 4);
        cpa16(sbase + ABYTES + (uint32_t)c_row1 * RSB + c16_1 * 16,
              BpU + (size_t)(n0 + c_row1) * ldbU + (kcB0 + it) * 32 + c16_1 * 4);
        cpa_commit();
    };

    // MODE2: A tile (exp(score) split) register path
    float4 pa[2];
    auto load_a2 = [&](int it) {
        #pragma unroll
        for (int l = 0; l < 2; l++) {
            int idx = tid + l * 512, row = idx >> 3, f4 = idx & 7;
            pa[l] = *(const float4*)(Af + (size_t)(m0 + row) * S_ + it * 32 + f4 * 4);
        }
    };
    auto store_a2 = [&](int st) {
        char* base = smc + st * STAGEB;
        #pragma unroll
        for (int l = 0; l < 2; l++) {
            int idx = tid + l * 512, row = idx >> 3, f4 = idx & 7;
            float4 v = pa[l];
            v.x = __expf(v.x); v.y = __expf(v.y);
            v.z = __expf(v.z); v.w = __expf(v.w);
            uint32_t h01, h23, l01, l23;
            split4u(v, h01, h23, l01, l23);
            *(uint2*)(base + row * RSB + f4 * 8)      = make_uint2(h01, h23);
            *(uint2*)(base + row * RSB + 64 + f4 * 8) = make_uint2(l01, l23);
        }
    };

    // -------- prologue: stage 0 --------
    if (MODE == 2) { load_a2(0); store_a2(0); }
    issue_stage(0, 0);

    for (int it = 0; it < NITER; it++) {
        if (it + 1 < NITER) {
            if (MODE == 2) load_a2(it + 1);
            issue_stage(it + 1, (it + 1) & 1);
            cpa_wait1();
        } else {
            cpa_wait0();
        }
        __syncthreads();   // stage it fully visible

        // -------- compute from stage it&1 --------
        {
            const uint32_t so = (uint32_t)((it & 1) * STAGEB);
            #pragma unroll
            for (int ks = 0; ks < 2; ks++) {
                const uint32_t ko = so + (uint32_t)(ks * 32);
                uint32_t ah[2][4], alo[2][4], bh2[2][4], bl2[2][4];
                #pragma unroll
                for (int mt = 0; mt < 2; mt++) {
                    ldsm4(ah[mt],  aAddr[mt] + ko);
                    ldsm4(alo[mt], aAddr[mt] + ko + 64);
                }
                #pragma unroll
                for (int np = 0; np < 2; np++) {
                    ldsm4(bh2[np], bAddr[np] + ko);
                    ldsm4(bl2[np], bAddr[np] + ko + 64);
                }
                #pragma unroll
                for (int mt = 0; mt < 2; mt++)
                    #pragma unroll
                    for (int nt = 0; nt < 4; nt++) {
                        const uint32_t* bh = &bh2[nt >> 1][(nt & 1) * 2];
                        const uint32_t* bl = &bl2[nt >> 1][(nt & 1) * 2];
                        mma_bf16(c[mt][nt], ah[mt],  bh);
                        mma_bf16(c[mt][nt], ah[mt],  bl);
                        mma_bf16(c[mt][nt], alo[mt], bh);
                    }
            }
        }

        if (it + 1 < NITER) {
            __syncthreads();   // all reads of stage (it+1)&1's old data done
            if (MODE == 2) store_a2((it + 1) & 1);
        }
    }

    // ------------------------------ epilogue --------------------------------
    if (MODE == 0) {
        #pragma unroll
        for (int mt = 0; mt < 2; mt++) {
            const int r0 = m0 + wm * 32 + mt * 16 + gid;
            #pragma unroll
            for (int nt = 0; nt < 4; nt++) {
                const int n = n0 + wn * 32 + nt * 8 + 2 * tig;
                const float b0 = g_bias[n], b1 = g_bias[n + 1];
                float v00 = c[mt][nt][0] + b0, v01 = c[mt][nt][1] + b1;
                float v10 = c[mt][nt][2] + b0, v11 = c[mt][nt][3] + b1;
                if (n < D_) {
                    *(float2*)(shortcut + (size_t)r0 * D_ + n)       = make_float2(v00, v01);
                    *(float2*)(shortcut + (size_t)(r0 + 8) * D_ + n) = make_float2(v10, v11);
                } else {
                    const int col = n - D_;
                    const int chunk = col >> 5, w = col & 31;
                    // packed bf16 hi/lo write for q,k,v
                    __nv_bfloat162 h0 = __floats2bfloat162_rn(v00, v01);
                    __nv_bfloat162 l0 = __floats2bfloat162_rn(
                        v00 - __bfloat162float(h0.x), v01 - __bfloat162float(h0.y));
                    __nv_bfloat162 h1 = __floats2bfloat162_rn(v10, v11);
                    __nv_bfloat162 l1 = __floats2bfloat162_rn(
                        v10 - __bfloat162float(h1.x), v11 - __bfloat162float(h1.y));
                    size_t q0 = (size_t)r0 * QKV_N + (size_t)chunk * 32 + (w >> 1);
                    size_t q1 = (size_t)(r0 + 8) * QKV_N + (size_t)chunk * 32 + (w >> 1);
                    g_qkvp[q0]      = *(uint32_t*)&h0;
                    g_qkvp[q0 + 16] = *(uint32_t*)&l0;
                    g_qkvp[q1]      = *(uint32_t*)&h1;
                    g_qkvp[q1 + 16] = *(uint32_t*)&l1;
                    if (col >= D_ + KD) {   // v region: also fp32 for transpose
                        const int d = col - (D_ + KD);
                        *(float2*)(g_v + (size_t)r0 * KD + d)       = make_float2(v00, v01);
                        *(float2*)(g_v + (size_t)(r0 + 8) * KD + d) = make_float2(v10, v11);
                    }
                }
            }
        }
    } else if (MODE == 1) {
        const float inv = 1.0f / 16384.0f;
        float* Cp = score + (size_t)bh * S_ * S_;
        #pragma unroll
        for (int mt = 0; mt < 2; mt++) {
            const int r0 = m0 + wm * 32 + mt * 16 + gid;
            float rs0 = 0.0f, rs1 = 0.0f;
            #pragma unroll
            for (int nt = 0; nt < 4; nt++) {
                const int n = n0 + wn * 32 + nt * 8 + 2 * tig;
                float v0 = c[mt][nt][0] * inv, v1 = c[mt][nt][1] * inv;
                float v2 = c[mt][nt][2] * inv, v3 = c[mt][nt][3] * inv;
                *(float2*)(Cp + (size_t)r0 * S_ + n)       = make_float2(v0, v1);
                *(float2*)(Cp + (size_t)(r0 + 8) * S_ + n) = make_float2(v2, v3);
                rs0 += __expf(v0) + __expf(v1);
                rs1 += __expf(v2) + __expf(v3);
            }
            rs0 += __shfl_xor_sync(0xFFFFFFFFu, rs0, 1);
            rs0 += __shfl_xor_sync(0xFFFFFFFFu, rs0, 2);
            rs1 += __shfl_xor_sync(0xFFFFFFFFu, rs1, 1);
            rs1 += __shfl_xor_sync(0xFFFFFFFFu, rs1, 2);
            if (tig == 0) {
                const size_t pidx = (size_t)(blockIdx.x * 4 + wn) * (BH_ * S_)
                                  + (size_t)bh * S_;
                g_partial[pidx + r0]     = rs0;
                g_partial[pidx + r0 + 8] = rs1;
            }
        }
    } else {
        #pragma unroll
        for (int mt = 0; mt < 2; mt++) {
            const int r0 = m0 + wm * 32 + mt * 16 + gid;
            const float il0 = 1.0f / g_sum[(size_t)bh * S_ + r0];
            const float il1 = 1.0f / g_sum[(size_t)bh * S_ + r0 + 8];
            #pragma unroll
            for (int nt = 0; nt < 4; nt++) {
                const int col = wn * 32 + nt * 8 + 2 * tig;
                float2 o0 = make_float2(c[mt][nt][0] * il0, c[mt][nt][1] * il0);
                float2 o1 = make_float2(c[mt][nt][2] * il1, c[mt][nt][3] * il1);
                *(float2*)(atten + (size_t)bh * S_ * KD + (size_t)r0 * KD + col) = o0;
                *(float2*)(atten + (size_t)bh * S_ * KD + (size_t)(r0 + 8) * KD + col) = o1;
                *(float2*)(res + (size_t)(bb * S_ + r0) * D_ + (bh & 15) * KD + col) = o0;
                *(float2*)(res + (size_t)(bb * S_ + r0 + 8) * D_ + (bh & 15) * KD + col) = o1;
            }
        }
    }
}

// ---------------------------------------------------------------------------
extern "C" void kernel_launch(void* const* d_in, const int* in_sizes, int n_in,
                              void* d_out, int out_size)
{
    const float* in_x  = (const float*)d_in[0];
    const float* W_sc  = (const float*)d_in[1];
    const float* b_sc  = (const float*)d_in[2];
    const float* W_qkv = (const float*)d_in[3];
    const float* b_qkv = (const float*)d_in[4];

    float* out       = (float*)d_out;
    float* score     = out;
    float* atten     = score + (size_t)BH_ * S_ * S_;
    float* res       = atten + (size_t)BH_ * S_ * KD;
    float* short_cut = res   + (size_t)B_ * S_ * D_;

    cudaFuncSetAttribute(gemm_mma<0>, cudaFuncAttributeMaxDynamicSharedMemorySize, SMEMB);
    cudaFuncSetAttribute(gemm_mma<1>, cudaFuncAttributeMaxDynamicSharedMemorySize, SMEMB);
    cudaFuncSetAttribute(gemm_mma<2>, cudaFuncAttributeMaxDynamicSharedMemorySize, SMEMB);

    // prep: pack X, pack W^T (+bias)
    pack_x<<<(unsigned)(((size_t)B_ * S_ * D_ / 4) / 256), 256>>>(in_x);
    trans_w<<<dim3(NTOT / 32, D_ / 32), 256>>>(W_sc, W_qkv, b_sc, b_qkv);
    // fused shortcut+qkv GEMM (writes q,k,v packed + v fp32 + shortcut)
    gemm_mma<0><<<dim3(NTOT / 128, (B_ * S_) / 128), 512, SMEMB>>>(
        nullptr, score, atten, res, short_cut);
    // v^T pack
    trans_v<<<dim3(S_ / 32, KD / 32, B_), 256>>>();
    // score GEMM (+ partial exp sums)
    gemm_mma<1><<<dim3(S_ / 128, S_ / 128, BH_), 512, SMEMB>>>(
        nullptr, score, atten, res, short_cut);
    // softmax denominators
    reduce_sums<<<(BH_ * S_) / 256, 256>>>();
    // PV GEMM
    gemm_mma<2><<<dim3(S_ / 128, BH_), 512, SMEMB>>>(
        score, score, atten, res, short_cut);
}

// round 9
// speedup vs baseline: 2.6626x; 1.0009x over previous
#include <cuda_runtime.h>
#include <cuda_bf16.h>
#include <cstdint>
#include <cstddef>

#define S_    2048
#define D_    2048
#define QKV_N 2304
#define KD    128
#define NTOT  4352   // D + QKV_N
#define BH_   32
#define B_    2
#define H_    16

// ---------------- scratch (__device__ globals; no allocations) --------------
// packed format per 32-k chunk (u32 units): [0..15] = 32 bf16 hi, [16..31] = 32 bf16 lo
__device__ __align__(128) uint32_t g_xp[(size_t)B_ * S_ * D_];       // 33.5 MB
__device__ __align__(128) uint32_t g_wtp[(size_t)NTOT * D_];         // 35.7 MB
__device__ __align__(128) uint32_t g_qkvp[(size_t)B_ * S_ * QKV_N]; // 37.7 MB
__device__ __align__(128) uint32_t g_vtp[(size_t)B_ * KD * S_];     // 2 MB
__device__ float g_v[(size_t)B_ * S_ * KD];                          // 2 MB (v fp32 for transpose)
__device__ float g_bias[NTOT];
__device__ float g_partial[(size_t)64 * BH_ * S_];                   // 16.8 MB
__device__ float g_sum[(size_t)BH_ * S_];

// ---------------- helpers ----------------------------------------------------
__device__ __forceinline__ uint32_t smem_u32(const void* p) {
    uint32_t a;
    asm("{ .reg .u64 t; cvta.to.shared.u64 t, %1; cvt.u32.u64 %0, t; }" : "=r"(a) : "l"(p));
    return a;
}
__device__ __forceinline__ void mma_bf16(float c[4], const uint32_t a[4],
                                         const uint32_t b[2]) {
    asm volatile(
        "mma.sync.aligned.m16n8k16.row.col.f32.bf16.bf16.f32 "
        "{%0,%1,%2,%3}, {%4,%5,%6,%7}, {%8,%9}, {%0,%1,%2,%3};"
        : "+f"(c[0]), "+f"(c[1]), "+f"(c[2]), "+f"(c[3])
        : "r"(a[0]), "r"(a[1]), "r"(a[2]), "r"(a[3]), "r"(b[0]), "r"(b[1]));
}
__device__ __forceinline__ void ldsm4(uint32_t r[4], uint32_t addr) {
    asm volatile("ldmatrix.sync.aligned.m8n8.x4.shared.b16 {%0,%1,%2,%3}, [%4];"
        : "=r"(r[0]), "=r"(r[1]), "=r"(r[2]), "=r"(r[3]) : "r"(addr));
}
__device__ __forceinline__ void cpa16(uint32_t s, const void* g) {
    asm volatile("cp.async.cg.shared.global [%0], [%1], 16;" :: "r"(s), "l"(g) : "memory");
}
__device__ __forceinline__ void cpa_commit() {
    asm volatile("cp.async.commit_group;" ::: "memory");
}
__device__ __forceinline__ void cpa_wait1() {
    asm volatile("cp.async.wait_group 1;" ::: "memory");
}
__device__ __forceinline__ void cpa_wait0() {
    asm volatile("cp.async.wait_group 0;" ::: "memory");
}
// split 4 fp32 into hi/lo bf16x2 u32 pairs
__device__ __forceinline__ void split4u(float4 v, uint32_t& h01, uint32_t& h23,
                                        uint32_t& l01, uint32_t& l23) {
    __nv_bfloat162 h0 = __floats2bfloat162_rn(v.x, v.y);
    __nv_bfloat162 h1 = __floats2bfloat162_rn(v.z, v.w);
    __nv_bfloat162 l0 = __floats2bfloat162_rn(v.x - __bfloat162float(h0.x),
                                              v.y - __bfloat162float(h0.y));
    __nv_bfloat162 l1 = __floats2bfloat162_rn(v.z - __bfloat162float(h1.x),
                                              v.w - __bfloat162float(h1.y));
    h01 = *(uint32_t*)&h0; h23 = *(uint32_t*)&h1;
    l01 = *(uint32_t*)&l0; l23 = *(uint32_t*)&l1;
}

// ---------------------------------------------------------------------------
// prep: pack X into hi/lo chunk layout
// ---------------------------------------------------------------------------
__global__ void __launch_bounds__(256) pack_x(const float* __restrict__ in_x)
{
    const size_t fid = (size_t)blockIdx.x * 256 + threadIdx.x; // one float4 each
    const size_t row = fid >> 9;         // 512 float4 per row (D=2048)
    const int r = (int)(fid & 511);
    const int kc = r >> 3, f4 = r & 7, w = f4 * 4;
    float4 v = *(const float4*)(in_x + row * D_ + kc * 32 + w);
    uint32_t h01, h23, l01, l23;
    split4u(v, h01, h23, l01, l23);
    const size_t b32 = row * D_ + kc * 32;
    g_xp[b32 + (w >> 1)]      = h01;
    g_xp[b32 + (w >> 1) + 1]  = h23;
    g_xp[b32 + 16 + (w >> 1)] = l01;
    g_xp[b32 + 17 + (w >> 1)] = l23;
}

// prep: W concat + transpose + split-pack -> g_wtp[n][k], bias concat
__global__ void __launch_bounds__(256) trans_w(
    const float* __restrict__ Wsc, const float* __restrict__ Wqkv,
    const float* __restrict__ bsc, const float* __restrict__ bqkv)
{
    __shared__ float t[32][33];
    const int n0 = blockIdx.x * 32, k0 = blockIdx.y * 32;
    const int tx = threadIdx.x & 31, ty = threadIdx.x >> 5;
    const int n = n0 + tx;
    #pragma unroll
    for (int r = 0; r < 4; r++) {
        int k = k0 + ty + r * 8;
        t[ty + r * 8][tx] = (n < D_) ? Wsc[(size_t)k * D_ + n]
                                     : Wqkv[(size_t)k * QKV_N + (n - D_)];
    }
    if (blockIdx.y == 0 && threadIdx.x < 32) {
        int nb = n0 + threadIdx.x;
        g_bias[nb] = (nb < D_) ? bsc[nb] : bqkv[nb - D_];
    }
    __syncthreads();
    uint16_t* p16 = (uint16_t*)g_wtp;
    const int kc = k0 >> 5;
    #pragma unroll
    for (int r = 0; r < 4; r++) {
        const int nn = n0 + ty + r * 8;
        float v = t[tx][ty + r * 8];
        __nv_bfloat16 h = __float2bfloat16(v);
        __nv_bfloat16 l = __float2bfloat16(v - __bfloat162float(h));
        size_t b16 = 2 * ((size_t)nn * D_ + (size_t)kc * 32);
        p16[b16 + tx]      = *(uint16_t*)&h;
        p16[b16 + 32 + tx] = *(uint16_t*)&l;
    }
}

// prep: v transpose + split-pack -> g_vtp[b][d][tchunk]
__global__ void __launch_bounds__(256) trans_v()
{
    __shared__ float t[32][33];
    const int b = blockIdx.z;
    const int t0 = blockIdx.x * 32, d0 = blockIdx.y * 32;
    const int tx = threadIdx.x & 31, ty = threadIdx.x >> 5;
    #pragma unroll
    for (int r = 0; r < 4; r++)
        t[ty + r * 8][tx] = g_v[(size_t)(b * S_ + t0 + ty + r * 8) * KD + d0 + tx];
    __syncthreads();
    uint16_t* p16 = (uint16_t*)g_vtp;
    const int tc = t0 >> 5;
    #pragma unroll
    for (int r = 0; r < 4; r++) {
        const int d = d0 + ty + r * 8;
        float v = t[tx][ty + r * 8];
        __nv_bfloat16 h = __float2bfloat16(v);
        __nv_bfloat16 l = __float2bfloat16(v - __bfloat162float(h));
        size_t b16 = 2 * ((size_t)b * KD * S_ + (size_t)d * S_ + (size_t)tc * 32);
        p16[b16 + tx]      = *(uint16_t*)&h;
        p16[b16 + 32 + tx] = *(uint16_t*)&l;
    }
}

__global__ void __launch_bounds__(256) reduce_sums()
{
    const int r = blockIdx.x * 256 + threadIdx.x;
    float s = 0.0f;
    #pragma unroll
    for (int p = 0; p < 64; p++)
        s += g_partial[(size_t)p * (BH_ * S_) + r];
    g_sum[r] = s;
}

// ---------------------------------------------------------------------------
// bf16x3 mma.sync GEMM, cp.async mainloop over preconverted operands.
// 512 thr, warp grid 4x4, warp tile 32x32, BM=BN=128, BK=32, 2-stage smem.
// Stage layout (bytes): A[128 rows x 144] | B[128 rows x 144]; row = 64B hi | 64B lo | 16B pad
// MODE 0: C = X @ Wt^T + bias            -> shortcut fp32 / q,k packed + v fp32
// MODE 1: score = q k^T / 16384          -> score + partial sums of exp
// MODE 2: atten = exp(score) @ v^T / sum -> atten + res
// ---------------------------------------------------------------------------
#define RSB    144                    // smem row stride bytes
#define ABYTES (128 * RSB)            // 18432
#define STAGEB (2 * ABYTES)           // 36864
#define SMEMB  (2 * STAGEB)           // 73728

template <int MODE>
__global__ void __launch_bounds__(512, 1) gemm_mma(
    const float* __restrict__ score_in, float* __restrict__ score,
    float* __restrict__ atten, float* __restrict__ res,
    float* __restrict__ shortcut)
{
    extern __shared__ uint32_t smw[];
    char* smc = (char*)smw;

    const int tid = threadIdx.x;
    const int warp = tid >> 5, lane = tid & 31;
    const int gid = lane >> 2, tig = lane & 3;
    const int wm = warp >> 2, wn = warp & 3;

    int m0, n0, bh = 0, bb = 0;
    const uint32_t *ApU = nullptr, *BpU = nullptr;
    const float* Af = nullptr;          // MODE2 fp32 A (score)
    int ldaU = 0, ldbU = 0, kcA0 = 0, kcB0 = 0;
    constexpr int K = (MODE == 1) ? KD : ((MODE == 2) ? S_ : D_);
    constexpr int NITER = K / 32;

    if (MODE == 0) {
        m0 = blockIdx.y * 128; n0 = blockIdx.x * 128;
        ApU = g_xp;  ldaU = D_; kcA0 = 0;
        BpU = g_wtp; ldbU = D_; kcB0 = 0;
    } else if (MODE == 1) {
        bh = blockIdx.z; bb = bh >> 4;
        m0 = blockIdx.y * 128; n0 = blockIdx.x * 128;
        ApU = g_qkvp + (size_t)bb * S_ * QKV_N; ldaU = QKV_N; kcA0 = 4 * (bh & 15);
        BpU = ApU;                              ldbU = QKV_N; kcB0 = 64;
    } else {
        bh = blockIdx.y; bb = bh >> 4;
        m0 = blockIdx.x * 128; n0 = 0;
        Af  = score_in + (size_t)bh * S_ * S_;
        BpU = g_vtp + (size_t)bb * KD * S_; ldbU = S_; kcB0 = 0;
    }

    // ldmatrix per-lane base addresses (stage 0, ks=0, hi plane)
    const uint32_t smb = smem_u32(smw);
    const int lr = lane & 7;
    const int a_r8 = (lane >> 3) & 1, a_kh = lane >> 4;
    const int b_r8 = lane >> 4,       b_kh = (lane >> 3) & 1;
    uint32_t aAddr[2], bAddr[2];
    #pragma unroll
    for (int mt = 0; mt < 2; mt++)
        aAddr[mt] = smb + (uint32_t)(wm * 32 + mt * 16 + lr + a_r8 * 8) * RSB
                  + (uint32_t)(a_kh * 16);
    #pragma unroll
    for (int np = 0; np < 2; np++)
        bAddr[np] = smb + (uint32_t)ABYTES
                  + (uint32_t)(wn * 32 + np * 16 + lr + b_r8 * 8) * RSB
                  + (uint32_t)(b_kh * 16);

    float c[2][4][4];
    #pragma unroll
    for (int mt = 0; mt < 2; mt++)
        #pragma unroll
        for (int nt = 0; nt < 4; nt++)
            #pragma unroll
            for (int q = 0; q < 4; q++) c[mt][nt][q] = 0.0f;

    // per-thread cp.async coordinates (2 chunks per operand)
    const int c_row0 = tid >> 3,        c16_0 = tid & 7;
    const int c_row1 = (tid + 512) >> 3, c16_1 = (tid + 512) & 7;

    // ---- fill one stage via cp.async (A for MODE 0/1, B always) ----
    auto issue_stage = [&](int it, int st) {
        const uint32_t sbase = smb + (uint32_t)(st * STAGEB);
        if (MODE != 2) {
            cpa16(sbase + (uint32_t)c_row0 * RSB + c16_0 * 16,
                  ApU + (size_t)(m0 + c_row0) * ldaU + (kcA0 + it) * 32 + c16_0 * 4);
            cpa16(sbase + (uint32_t)c_row1 * RSB + c16_1 * 16,
                  ApU + (size_t)(m0 + c_row1) * ldaU + (kcA0 + it) * 32 + c16_1 * 4);
        }
        cpa16(sbase + ABYTES + (uint32_t)c_row0 * RSB + c16_0 * 16,
              BpU + (size_t)(n0 + c_row0) * ldbU + (kcB0 + it) * 32 + c16_0 * 4);
        cpa16(sbase + ABYTES + (uint32_t)c_row1 * RSB + c16_1 * 16,
              BpU + (size_t)(n0 + c_row1) * ldbU + (kcB0 + it) * 32 + c16_1 * 4);
        cpa_commit();
    };

    // MODE2: A tile (exp(score) split) register path
    float4 pa[2];
    auto load_a2 = [&](int it) {
        #pragma unroll
        for (int l = 0; l < 2; l++) {
            int idx = tid + l * 512, row = idx >> 3, f4 = idx & 7;
            pa[l] = *(const float4*)(Af + (size_t)(m0 + row) * S_ + it * 32 + f4 * 4);
        }
    };
    auto store_a2 = [&](int st) {
        char* base = smc + st * STAGEB;
        #pragma unroll
        for (int l = 0; l < 2; l++) {
            int idx = tid + l * 512, row = idx >> 3, f4 = idx & 7;
            float4 v = pa[l];
            v.x = __expf(v.x); v.y = __expf(v.y);
            v.z = __expf(v.z); v.w = __expf(v.w);
            uint32_t h01, h23, l01, l23;
            split4u(v, h01, h23, l01, l23);
            *(uint2*)(base + row * RSB + f4 * 8)      = make_uint2(h01, h23);
            *(uint2*)(base + row * RSB + 64 + f4 * 8) = make_uint2(l01, l23);
        }
    };

    // -------- prologue: stage 0 --------
    if (MODE == 2) { load_a2(0); store_a2(0); }
    issue_stage(0, 0);

    for (int it = 0; it < NITER; it++) {
        if (it + 1 < NITER) {
            if (MODE == 2) load_a2(it + 1);
            issue_stage(it + 1, (it + 1) & 1);
            cpa_wait1();
        } else {
            cpa_wait0();
        }
        __syncthreads();   // stage it fully visible

        // -------- compute from stage it&1 --------
        {
            const uint32_t so = (uint32_t)((it & 1) * STAGEB);
            #pragma unroll
            for (int ks = 0; ks < 2; ks++) {
                const uint32_t ko = so + (uint32_t)(ks * 32);
                uint32_t ah[2][4], alo[2][4], bh2[2][4], bl2[2][4];
                #pragma unroll
                for (int mt = 0; mt < 2; mt++) {
                    ldsm4(ah[mt],  aAddr[mt] + ko);
                    ldsm4(alo[mt], aAddr[mt] + ko + 64);
                }
                #pragma unroll
                for (int np = 0; np < 2; np++) {
                    ldsm4(bh2[np], bAddr[np] + ko);
                    ldsm4(bl2[np], bAddr[np] + ko + 64);
                }
                #pragma unroll
                for (int mt = 0; mt < 2; mt++)
                    #pragma unroll
                    for (int nt = 0; nt < 4; nt++) {
                        const uint32_t* bh = &bh2[nt >> 1][(nt & 1) * 2];
                        const uint32_t* bl = &bl2[nt >> 1][(nt & 1) * 2];
                        mma_bf16(c[mt][nt], ah[mt],  bh);
                        mma_bf16(c[mt][nt], ah[mt],  bl);
                        mma_bf16(c[mt][nt], alo[mt], bh);
                    }
            }
        }

        if (it + 1 < NITER) {
            __syncthreads();   // all reads of stage (it+1)&1's old data done
            if (MODE == 2) store_a2((it + 1) & 1);
        }
    }

    // ------------------------------ epilogue --------------------------------
    if (MODE == 0) {
        #pragma unroll
        for (int mt = 0; mt < 2; mt++) {
            const int r0 = m0 + wm * 32 + mt * 16 + gid;
            #pragma unroll
            for (int nt = 0; nt < 4; nt++) {
                const int n = n0 + wn * 32 + nt * 8 + 2 * tig;
                const float b0 = g_bias[n], b1 = g_bias[n + 1];
                float v00 = c[mt][nt][0] + b0, v01 = c[mt][nt][1] + b1;
                float v10 = c[mt][nt][2] + b0, v11 = c[mt][nt][3] + b1;
                if (n < D_) {
                    *(float2*)(shortcut + (size_t)r0 * D_ + n)       = make_float2(v00, v01);
                    *(float2*)(shortcut + (size_t)(r0 + 8) * D_ + n) = make_float2(v10, v11);
                } else {
                    const int col = n - D_;
                    const int chunk = col >> 5, w = col & 31;
                    // packed bf16 hi/lo write for q,k,v
                    __nv_bfloat162 h0 = __floats2bfloat162_rn(v00, v01);
                    __nv_bfloat162 l0 = __floats2bfloat162_rn(
                        v00 - __bfloat162float(h0.x), v01 - __bfloat162float(h0.y));
                    __nv_bfloat162 h1 = __floats2bfloat162_rn(v10, v11);
                    __nv_bfloat162 l1 = __floats2bfloat162_rn(
                        v10 - __bfloat162float(h1.x), v11 - __bfloat162float(h1.y));
                    size_t q0 = (size_t)r0 * QKV_N + (size_t)chunk * 32 + (w >> 1);
                    size_t q1 = (size_t)(r0 + 8) * QKV_N + (size_t)chunk * 32 + (w >> 1);
                    g_qkvp[q0]      = *(uint32_t*)&h0;
                    g_qkvp[q0 + 16] = *(uint32_t*)&l0;
                    g_qkvp[q1]      = *(uint32_t*)&h1;
                    g_qkvp[q1 + 16] = *(uint32_t*)&l1;
                    if (col >= D_ + KD) {   // v region: also fp32 for transpose
                        const int d = col - (D_ + KD);
                        *(float2*)(g_v + (size_t)r0 * KD + d)       = make_float2(v00, v01);
                        *(float2*)(g_v + (size_t)(r0 + 8) * KD + d) = make_float2(v10, v11);
                    }
                }
            }
        }
    } else if (MODE == 1) {
        const float inv = 1.0f / 16384.0f;
        float* Cp = score + (size_t)bh * S_ * S_;
        #pragma unroll
        for (int mt = 0; mt < 2; mt++) {
            const int r0 = m0 + wm * 32 + mt * 16 + gid;
            float rs0 = 0.0f, rs1 = 0.0f;
            #pragma unroll
            for (int nt = 0; nt < 4; nt++) {
                const int n = n0 + wn * 32 + nt * 8 + 2 * tig;
                float v0 = c[mt][nt][0] * inv, v1 = c[mt][nt][1] * inv;
                float v2 = c[mt][nt][2] * inv, v3 = c[mt][nt][3] * inv;
                *(float2*)(Cp + (size_t)r0 * S_ + n)       = make_float2(v0, v1);
                *(float2*)(Cp + (size_t)(r0 + 8) * S_ + n) = make_float2(v2, v3);
                rs0 += __expf(v0) + __expf(v1);
                rs1 += __expf(v2) + __expf(v3);
            }
            rs0 += __shfl_xor_sync(0xFFFFFFFFu, rs0, 1);
            rs0 += __shfl_xor_sync(0xFFFFFFFFu, rs0, 2);
            rs1 += __shfl_xor_sync(0xFFFFFFFFu, rs1, 1);
            rs1 += __shfl_xor_sync(0xFFFFFFFFu, rs1, 2);
            if (tig == 0) {
                const size_t pidx = (size_t)(blockIdx.x * 4 + wn) * (BH_ * S_)
                                  + (size_t)bh * S_;
                g_partial[pidx + r0]     = rs0;
                g_partial[pidx + r0 + 8] = rs1;
            }
        }
    } else {
        #pragma unroll
        for (int mt = 0; mt < 2; mt++) {
            const int r0 = m0 + wm * 32 + mt * 16 + gid;
            const float il0 = 1.0f / g_sum[(size_t)bh * S_ + r0];
            const float il1 = 1.0f / g_sum[(size_t)bh * S_ + r0 + 8];
            #pragma unroll
            for (int nt = 0; nt < 4; nt++) {
                const int col = wn * 32 + nt * 8 + 2 * tig;
                float2 o0 = make_float2(c[mt][nt][0] * il0, c[mt][nt][1] * il0);
                float2 o1 = make_float2(c[mt][nt][2] * il1, c[mt][nt][3] * il1);
                *(float2*)(atten + (size_t)bh * S_ * KD + (size_t)r0 * KD + col) = o0;
                *(float2*)(atten + (size_t)bh * S_ * KD + (size_t)(r0 + 8) * KD + col) = o1;
                *(float2*)(res + (size_t)(bb * S_ + r0) * D_ + (bh & 15) * KD + col) = o0;
                *(float2*)(res + (size_t)(bb * S_ + r0 + 8) * D_ + (bh & 15) * KD + col) = o1;
            }
        }
    }
}

// ---------------------------------------------------------------------------
extern "C" void kernel_launch(void* const* d_in, const int* in_sizes, int n_in,
                              void* d_out, int out_size)
{
    const float* in_x  = (const float*)d_in[0];
    const float* W_sc  = (const float*)d_in[1];
    const float* b_sc  = (const float*)d_in[2];
    const float* W_qkv = (const float*)d_in[3];
    const float* b_qkv = (const float*)d_in[4];

    float* out       = (float*)d_out;
    float* score     = out;
    float* atten     = score + (size_t)BH_ * S_ * S_;
    float* res       = atten + (size_t)BH_ * S_ * KD;
    float* short_cut = res   + (size_t)B_ * S_ * D_;

    cudaFuncSetAttribute(gemm_mma<0>, cudaFuncAttributeMaxDynamicSharedMemorySize, SMEMB);
    cudaFuncSetAttribute(gemm_mma<1>, cudaFuncAttributeMaxDynamicSharedMemorySize, SMEMB);
    cudaFuncSetAttribute(gemm_mma<2>, cudaFuncAttributeMaxDynamicSharedMemorySize, SMEMB);

    // prep: pack X, pack W^T (+bias)
    pack_x<<<(unsigned)(((size_t)B_ * S_ * D_ / 4) / 256), 256>>>(in_x);
    trans_w<<<dim3(NTOT / 32, D_ / 32), 256>>>(W_sc, W_qkv, b_sc, b_qkv);
    // fused shortcut+qkv GEMM (writes q,k,v packed + v fp32 + shortcut)
    gemm_mma<0><<<dim3(NTOT / 128, (B_ * S_) / 128), 512, SMEMB>>>(
        nullptr, score, atten, res, short_cut);
    // v^T pack
    trans_v<<<dim3(S_ / 32, KD / 32, B_), 256>>>();
    // score GEMM (+ partial exp sums)
    gemm_mma<1><<<dim3(S_ / 128, S_ / 128, BH_), 512, SMEMB>>>(
        nullptr, score, atten, res, short_cut);
    // softmax denominators
    reduce_sums<<<(BH_ * S_) / 256, 256>>>();
    // PV GEMM
    gemm_mma<2><<<dim3(S_ / 128, BH_), 512, SMEMB>>>(
        score, score, atten, res, short_cut);
}

// round 10
// speedup vs baseline: 3.6173x; 1.3586x over previous
#include <cuda_runtime.h>
#include <cuda_fp16.h>
#include <cstdint>
#include <cstddef>

#define S_    2048
#define D_    2048
#define QKV_N 2304
#define KD    128
#define NTOT  4352   // D + QKV_N
#define BH_   32
#define B_    2
#define H_    16

// ---------------- scratch (__device__ globals; no allocations) --------------
// A-side packed per 32-k chunk (u32): [0..15] = 32 fp16 hi, [16..31] = 32 fp16 lo
// B-side packed per 32-k chunk (u32): [0..15] = 32 fp16 hi (hi only)
__device__ __align__(128) uint32_t g_xp[(size_t)B_ * S_ * D_];        // X hi/lo, 33.5 MB
__device__ __align__(128) uint32_t g_wtp[(size_t)NTOT * 1024];        // W^T hi, 17.8 MB
__device__ __align__(128) uint32_t g_qp[(size_t)B_ * S_ * D_];        // q hi/lo, 33.5 MB
__device__ __align__(128) uint32_t g_kp[(size_t)B_ * S_ * 64];        // k hi, 1 MB
__device__ __align__(128) uint32_t g_vtp[(size_t)B_ * KD * 1024];     // v^T hi, 1 MB
__device__ float g_v[(size_t)B_ * S_ * KD];                           // v fp32, 2 MB
__device__ float g_bias[NTOT];
__device__ float g_partial[(size_t)64 * BH_ * S_];                    // 16.8 MB
__device__ float g_sum[(size_t)BH_ * S_];
__device__ float g_v1p[(size_t)B_ * 16 * KD];                         // V1 partials
__device__ float g_v1[(size_t)B_ * KD];                               // V1 = sum_t v[t,d]

// ---------------- helpers ----------------------------------------------------
__device__ __forceinline__ uint32_t smem_u32(const void* p) {
    uint32_t a;
    asm("{ .reg .u64 t; cvta.to.shared.u64 t, %1; cvt.u32.u64 %0, t; }" : "=r"(a) : "l"(p));
    return a;
}
__device__ __forceinline__ void mma_f16(float c[4], const uint32_t a[4],
                                        const uint32_t b[2]) {
    asm volatile(
        "mma.sync.aligned.m16n8k16.row.col.f32.f16.f16.f32 "
        "{%0,%1,%2,%3}, {%4,%5,%6,%7}, {%8,%9}, {%0,%1,%2,%3};"
        : "+f"(c[0]), "+f"(c[1]), "+f"(c[2]), "+f"(c[3])
        : "r"(a[0]), "r"(a[1]), "r"(a[2]), "r"(a[3]), "r"(b[0]), "r"(b[1]));
}
__device__ __forceinline__ void ldsm4(uint32_t r[4], uint32_t addr) {
    asm volatile("ldmatrix.sync.aligned.m8n8.x4.shared.b16 {%0,%1,%2,%3}, [%4];"
        : "=r"(r[0]), "=r"(r[1]), "=r"(r[2]), "=r"(r[3]) : "r"(addr));
}
__device__ __forceinline__ void cpa16(uint32_t s, const void* g) {
    asm volatile("cp.async.cg.shared.global [%0], [%1], 16;" :: "r"(s), "l"(g) : "memory");
}
__device__ __forceinline__ void cpa_commit() {
    asm volatile("cp.async.commit_group;" ::: "memory");
}
__device__ __forceinline__ void cpa_wait1() {
    asm volatile("cp.async.wait_group 1;" ::: "memory");
}
__device__ __forceinline__ void cpa_wait0() {
    asm volatile("cp.async.wait_group 0;" ::: "memory");
}
// split 4 fp32 into fp16 hi pair-words and lo pair-words
__device__ __forceinline__ void split4h(float4 v, uint32_t& h01, uint32_t& h23,
                                        uint32_t& l01, uint32_t& l23) {
    __half hx = __float2half_rn(v.x), hy = __float2half_rn(v.y);
    __half hz = __float2half_rn(v.z), hw = __float2half_rn(v.w);
    __half lx = __float2half_rn(v.x - __half2float(hx));
    __half ly = __float2half_rn(v.y - __half2float(hy));
    __half lz = __float2half_rn(v.z - __half2float(hz));
    __half lw = __float2half_rn(v.w - __half2float(hw));
    __half2 H0 = __halves2half2(hx, hy), H1 = __halves2half2(hz, hw);
    __half2 L0 = __halves2half2(lx, ly), L1 = __halves2half2(lz, lw);
    h01 = *(uint32_t*)&H0; h23 = *(uint32_t*)&H1;
    l01 = *(uint32_t*)&L0; l23 = *(uint32_t*)&L1;
}

// ---------------------------------------------------------------------------
// prep kernels
// ---------------------------------------------------------------------------
__global__ void __launch_bounds__(256) pack_x(const float* __restrict__ in_x)
{
    const size_t fid = (size_t)blockIdx.x * 256 + threadIdx.x;
    const size_t row = fid >> 9;              // 512 float4 per row
    const int r = (int)(fid & 511);
    const int kc = r >> 3, f4 = r & 7, w = f4 * 4;
    float4 v = *(const float4*)(in_x + row * D_ + kc * 32 + w);
    uint32_t h01, h23, l01, l23;
    split4h(v, h01, h23, l01, l23);
    const size_t b32 = row * D_ + kc * 32;
    g_xp[b32 + (w >> 1)]      = h01;
    g_xp[b32 + (w >> 1) + 1]  = h23;
    g_xp[b32 + 16 + (w >> 1)] = l01;
    g_xp[b32 + 17 + (w >> 1)] = l23;
}

__global__ void __launch_bounds__(256) trans_w(
    const float* __restrict__ Wsc, const float* __restrict__ Wqkv,
    const float* __restrict__ bsc, const float* __restrict__ bqkv)
{
    __shared__ float t[32][33];
    const int n0 = blockIdx.x * 32, k0 = blockIdx.y * 32;
    const int tx = threadIdx.x & 31, ty = threadIdx.x >> 5;
    const int n = n0 + tx;
    #pragma unroll
    for (int r = 0; r < 4; r++) {
        int k = k0 + ty + r * 8;
        t[ty + r * 8][tx] = (n < D_) ? Wsc[(size_t)k * D_ + n]
                                     : Wqkv[(size_t)k * QKV_N + (n - D_)];
    }
    if (blockIdx.y == 0 && threadIdx.x < 32) {
        int nb = n0 + threadIdx.x;
        g_bias[nb] = (nb < D_) ? bsc[nb] : bqkv[nb - D_];
    }
    __syncthreads();
    uint16_t* p16 = (uint16_t*)g_wtp;
    const int kc = k0 >> 5;
    #pragma unroll
    for (int r = 0; r < 4; r++) {
        const int nn = n0 + ty + r * 8;
        __half h = __float2half_rn(t[tx][ty + r * 8]);
        p16[(size_t)nn * 2048 + kc * 32 + tx] = *(uint16_t*)&h;
    }
}

// v^T hi pack -> g_vtp[b][d][tchunk]
__global__ void __launch_bounds__(256) trans_v()
{
    __shared__ float t[32][33];
    const int b = blockIdx.z;
    const int t0 = blockIdx.x * 32, d0 = blockIdx.y * 32;
    const int tx = threadIdx.x & 31, ty = threadIdx.x >> 5;
    #pragma unroll
    for (int r = 0; r < 4; r++)
        t[ty + r * 8][tx] = g_v[(size_t)(b * S_ + t0 + ty + r * 8) * KD + d0 + tx];
    __syncthreads();
    uint16_t* p16 = (uint16_t*)g_vtp;
    const int tc = t0 >> 5;
    #pragma unroll
    for (int r = 0; r < 4; r++) {
        const int d = d0 + ty + r * 8;
        __half h = __float2half_rn(t[tx][ty + r * 8]);
        p16[((size_t)b * KD + d) * 2048 + tc * 32 + tx] = *(uint16_t*)&h;
    }
}

// V1 partials: grid (B_*16), block 128: sum 128 t-rows
__global__ void __launch_bounds__(128) colsum_v()
{
    const int g = blockIdx.x, b = g >> 4, tc = g & 15, d = threadIdx.x;
    float s = 0.0f;
    #pragma unroll 8
    for (int t = 0; t < 128; t++)
        s += g_v[(size_t)(b * S_ + tc * 128 + t) * KD + d];
    g_v1p[(size_t)g * KD + d] = s;
}
__global__ void __launch_bounds__(128) reduce_v1()
{
    const int b = blockIdx.x, d = threadIdx.x;
    float s = 0.0f;
    #pragma unroll
    for (int c = 0; c < 16; c++)
        s += g_v1p[(size_t)(b * 16 + c) * KD + d];
    g_v1[b * KD + d] = s;
}

__global__ void __launch_bounds__(256) reduce_sums()
{
    const int r = blockIdx.x * 256 + threadIdx.x;
    float s = 0.0f;
    #pragma unroll
    for (int p = 0; p < 64; p++)
        s += g_partial[(size_t)p * (BH_ * S_) + r];
    g_sum[r] = s;
}

// ---------------------------------------------------------------------------
// fp16 mma.sync GEMM. 512 thr, warp grid 4x4, warp tile 32x32, BM=BN=128,
// BK=32, 2-stage cp.async pipeline.
// A smem: 128 rows x 144B (hi 64 | lo 64 | pad).  B smem: 128 rows x 80B (hi).
// MODE 0 (2-term): C = X @ Wt^T + bias -> shortcut fp32 / q hi+lo / k hi / v fp32
// MODE 1 (2-term): score = q k^T / 16384 -> score + partial sums of exp
// MODE 2 (1-term): Sv = score @ v^T;  atten = (V1 + Sv)/sum -> atten + res
// ---------------------------------------------------------------------------
#define RSA    144
#define RSB    80
#define ABYT   (128 * RSA)            // 18432
#define BBYT   (128 * RSB)            // 10240
#define STAGEB (ABYT + BBYT)          // 28672
#define SMEMB  (2 * STAGEB)           // 57344

template <int MODE>
__global__ void __launch_bounds__(512, 1) gemm_mma(
    const float* __restrict__ score_in, float* __restrict__ score,
    float* __restrict__ atten, float* __restrict__ res,
    float* __restrict__ shortcut)
{
    extern __shared__ uint32_t smw[];
    char* smc = (char*)smw;

    const int tid = threadIdx.x;
    const int warp = tid >> 5, lane = tid & 31;
    const int gid = lane >> 2, tig = lane & 3;
    const int wm = warp >> 2, wn = warp & 3;

    int m0, n0, bh = 0, bb = 0;
    const uint32_t *ApU = nullptr, *BpU = nullptr;
    const float* Af = nullptr;
    int ldaU = 0, ldbU = 0, kcA0 = 0;
    constexpr int K = (MODE == 1) ? KD : ((MODE == 2) ? S_ : D_);
    constexpr int NITER = K / 32;

    if (MODE == 0) {
        m0 = blockIdx.y * 128; n0 = blockIdx.x * 128;
        ApU = g_xp;  ldaU = D_;
        BpU = g_wtp; ldbU = 1024;
    } else if (MODE == 1) {
        bh = blockIdx.z; bb = bh >> 4;
        m0 = blockIdx.y * 128; n0 = blockIdx.x * 128;
        ApU = g_qp + (size_t)bb * S_ * D_; ldaU = D_; kcA0 = 4 * (bh & 15);
        BpU = g_kp + (size_t)bb * S_ * 64; ldbU = 64;
    } else {
        bh = blockIdx.y; bb = bh >> 4;
        m0 = blockIdx.x * 128; n0 = 0;
        Af  = score_in + (size_t)bh * S_ * S_;
        BpU = g_vtp + (size_t)bb * KD * 1024; ldbU = 1024;
    }

    // ldmatrix per-lane base addresses (stage 0, ks=0)
    const uint32_t smb = smem_u32(smw);
    const int lr = lane & 7;
    const int a_r8 = (lane >> 3) & 1, a_kh = lane >> 4;
    const int b_r8 = lane >> 4,       b_kh = (lane >> 3) & 1;
    uint32_t aAddr[2], bAddr[2];
    #pragma unroll
    for (int mt = 0; mt < 2; mt++)
        aAddr[mt] = smb + (uint32_t)(wm * 32 + mt * 16 + lr + a_r8 * 8) * RSA
                  + (uint32_t)(a_kh * 16);
    #pragma unroll
    for (int np = 0; np < 2; np++)
        bAddr[np] = smb + (uint32_t)ABYT
                  + (uint32_t)(wn * 32 + np * 16 + lr + b_r8 * 8) * RSB
                  + (uint32_t)(b_kh * 16);

    float c[2][4][4];
    #pragma unroll
    for (int mt = 0; mt < 2; mt++)
        #pragma unroll
        for (int nt = 0; nt < 4; nt++)
            #pragma unroll
            for (int q = 0; q < 4; q++) c[mt][nt][q] = 0.0f;

    // cp.async thread coords: A 2 pieces (128 rows x 8 x16B), B 1 piece (128 x 4)
    const int a_row0 = tid >> 3, a16_0 = tid & 7;
    const int a_row1 = (tid + 512) >> 3, a16_1 = (tid + 512) & 7;
    const int b_row = tid >> 2, b16 = tid & 3;

    auto issue_stage = [&](int it, int st) {
        const uint32_t sbase = smb + (uint32_t)(st * STAGEB);
        if (MODE != 2) {
            cpa16(sbase + (uint32_t)a_row0 * RSA + a16_0 * 16,
                  ApU + (size_t)(m0 + a_row0) * ldaU + (kcA0 + it) * 32 + a16_0 * 4);
            cpa16(sbase + (uint32_t)a_row1 * RSA + a16_1 * 16,
                  ApU + (size_t)(m0 + a_row1) * ldaU + (kcA0 + it) * 32 + a16_1 * 4);
        }
        cpa16(sbase + ABYT + (uint32_t)b_row * RSB + b16 * 16,
              BpU + (size_t)(n0 + b_row) * ldbU + it * 16 + b16 * 4);
        cpa_commit();
    };

    // MODE2 A path: fp32 score -> fp16 1-term
    float4 pa[2];
    auto load_a2 = [&](int it) {
        #pragma unroll
        for (int l = 0; l < 2; l++) {
            int idx = tid + l * 512, row = idx >> 3, f4 = idx & 7;
            pa[l] = *(const float4*)(Af + (size_t)(m0 + row) * S_ + it * 32 + f4 * 4);
        }
    };
    auto store_a2 = [&](int st) {
        char* base = smc + st * STAGEB;
        #pragma unroll
        for (int l = 0; l < 2; l++) {
            int idx = tid + l * 512, row = idx >> 3, f4 = idx & 7;
            float4 v = pa[l];
            __half2 H0 = __halves2half2(__float2half_rn(v.x), __float2half_rn(v.y));
            __half2 H1 = __halves2half2(__float2half_rn(v.z), __float2half_rn(v.w));
            *(uint2*)(base + row * RSA + f4 * 8) =
                make_uint2(*(uint32_t*)&H0, *(uint32_t*)&H1);
        }
    };

    if (MODE == 2) { load_a2(0); store_a2(0); }
    issue_stage(0, 0);

    for (int it = 0; it < NITER; it++) {
        if (it + 1 < NITER) {
            if (MODE == 2) load_a2(it + 1);
            issue_stage(it + 1, (it + 1) & 1);
            cpa_wait1();
        } else {
            cpa_wait0();
        }
        __syncthreads();

        {
            const uint32_t so = (uint32_t)((it & 1) * STAGEB);
            #pragma unroll
            for (int ks = 0; ks < 2; ks++) {
                const uint32_t ko = so + (uint32_t)(ks * 32);
                uint32_t ah[2][4], alo[2][4], bh2[2][4];
                #pragma unroll
                for (int mt = 0; mt < 2; mt++) {
                    ldsm4(ah[mt], aAddr[mt] + ko);
                    if (MODE != 2) ldsm4(alo[mt], aAddr[mt] + ko + 64);
                }
                #pragma unroll
                for (int np = 0; np < 2; np++)
                    ldsm4(bh2[np], bAddr[np] + ko);
                #pragma unroll
                for (int mt = 0; mt < 2; mt++)
                    #pragma unroll
                    for (int nt = 0; nt < 4; nt++) {
                        const uint32_t* bf = &bh2[nt >> 1][(nt & 1) * 2];
                        mma_f16(c[mt][nt], ah[mt], bf);
                        if (MODE != 2) mma_f16(c[mt][nt], alo[mt], bf);
                    }
            }
        }

        if (it + 1 < NITER) {
            __syncthreads();
            if (MODE == 2) store_a2((it + 1) & 1);
        }
    }

    // ------------------------------ epilogue --------------------------------
    if (MODE == 0) {
        #pragma unroll
        for (int mt = 0; mt < 2; mt++) {
            const int r0 = m0 + wm * 32 + mt * 16 + gid;
            #pragma unroll
            for (int nt = 0; nt < 4; nt++) {
                const int n = n0 + wn * 32 + nt * 8 + 2 * tig;
                const float b0 = g_bias[n], b1 = g_bias[n + 1];
                float v00 = c[mt][nt][0] + b0, v01 = c[mt][nt][1] + b1;
                float v10 = c[mt][nt][2] + b0, v11 = c[mt][nt][3] + b1;
                if (n < D_) {
                    *(float2*)(shortcut + (size_t)r0 * D_ + n)       = make_float2(v00, v01);
                    *(float2*)(shortcut + (size_t)(r0 + 8) * D_ + n) = make_float2(v10, v11);
                } else if (n < 2 * D_) {                 // q: hi/lo pack
                    const int qc = n - D_;
                    const int chunk = qc >> 5, w = qc & 31;
                    __half h00 = __float2half_rn(v00), h01h = __float2half_rn(v01);
                    __half h10 = __float2half_rn(v10), h11h = __float2half_rn(v11);
                    __half2 H0 = __halves2half2(h00, h01h);
                    __half2 L0 = __halves2half2(
                        __float2half_rn(v00 - __half2float(h00)),
                        __float2half_rn(v01 - __half2float(h01h)));
                    __half2 H1 = __halves2half2(h10, h11h);
                    __half2 L1 = __halves2half2(
                        __float2half_rn(v10 - __half2float(h10)),
                        __float2half_rn(v11 - __half2float(h11h)));
                    size_t q0 = (size_t)r0 * D_ + (size_t)chunk * 32 + (w >> 1);
                    size_t q1 = (size_t)(r0 + 8) * D_ + (size_t)chunk * 32 + (w >> 1);
                    g_qp[q0]      = *(uint32_t*)&H0;
                    g_qp[q0 + 16] = *(uint32_t*)&L0;
                    g_qp[q1]      = *(uint32_t*)&H1;
                    g_qp[q1 + 16] = *(uint32_t*)&L1;
                } else if (n < 2 * D_ + KD) {            // k: hi pack
                    const int kc2 = n - 2 * D_;
                    const int chunk = kc2 >> 5, w = kc2 & 31;
                    __half2 H0 = __halves2half2(__float2half_rn(v00), __float2half_rn(v01));
                    __half2 H1 = __halves2half2(__float2half_rn(v10), __float2half_rn(v11));
                    g_kp[(size_t)r0 * 64 + chunk * 16 + (w >> 1)]       = *(uint32_t*)&H0;
                    g_kp[(size_t)(r0 + 8) * 64 + chunk * 16 + (w >> 1)] = *(uint32_t*)&H1;
                } else {                                  // v: fp32
                    const int d = n - (2 * D_ + KD);
                    *(float2*)(g_v + (size_t)r0 * KD + d)       = make_float2(v00, v01);
                    *(float2*)(g_v + (size_t)(r0 + 8) * KD + d) = make_float2(v10, v11);
                }
            }
        }
    } else if (MODE == 1) {
        const float inv = 1.0f / 16384.0f;
        float* Cp = score + (size_t)bh * S_ * S_;
        #pragma unroll
        for (int mt = 0; mt < 2; mt++) {
            const int r0 = m0 + wm * 32 + mt * 16 + gid;
            float rs0 = 0.0f, rs1 = 0.0f;
            #pragma unroll
            for (int nt = 0; nt < 4; nt++) {
                const int n = n0 + wn * 32 + nt * 8 + 2 * tig;
                float v0 = c[mt][nt][0] * inv, v1 = c[mt][nt][1] * inv;
                float v2 = c[mt][nt][2] * inv, v3 = c[mt][nt][3] * inv;
                *(float2*)(Cp + (size_t)r0 * S_ + n)       = make_float2(v0, v1);
                *(float2*)(Cp + (size_t)(r0 + 8) * S_ + n) = make_float2(v2, v3);
                rs0 += __expf(v0) + __expf(v1);
                rs1 += __expf(v2) + __expf(v3);
            }
            rs0 += __shfl_xor_sync(0xFFFFFFFFu, rs0, 1);
            rs0 += __shfl_xor_sync(0xFFFFFFFFu, rs0, 2);
            rs1 += __shfl_xor_sync(0xFFFFFFFFu, rs1, 1);
            rs1 += __shfl_xor_sync(0xFFFFFFFFu, rs1, 2);
            if (tig == 0) {
                const size_t pidx = (size_t)(blockIdx.x * 4 + wn) * (BH_ * S_)
                                  + (size_t)bh * S_;
                g_partial[pidx + r0]     = rs0;
                g_partial[pidx + r0 + 8] = rs1;
            }
        }
    } else {
        #pragma unroll
        for (int mt = 0; mt < 2; mt++) {
            const int r0 = m0 + wm * 32 + mt * 16 + gid;
            const float il0 = 1.0f / g_sum[(size_t)bh * S_ + r0];
            const float il1 = 1.0f / g_sum[(size_t)bh * S_ + r0 + 8];
            #pragma unroll
            for (int nt = 0; nt < 4; nt++) {
                const int col = wn * 32 + nt * 8 + 2 * tig;
                const float w0 = g_v1[bb * KD + col], w1 = g_v1[bb * KD + col + 1];
                float2 o0 = make_float2((c[mt][nt][0] + w0) * il0,
                                        (c[mt][nt][1] + w1) * il0);
                float2 o1 = make_float2((c[mt][nt][2] + w0) * il1,
                                        (c[mt][nt][3] + w1) * il1);
                *(float2*)(atten + (size_t)bh * S_ * KD + (size_t)r0 * KD + col) = o0;
                *(float2*)(atten + (size_t)bh * S_ * KD + (size_t)(r0 + 8) * KD + col) = o1;
                *(float2*)(res + (size_t)(bb * S_ + r0) * D_ + (bh & 15) * KD + col) = o0;
                *(float2*)(res + (size_t)(bb * S_ + r0 + 8) * D_ + (bh & 15) * KD + col) = o1;
            }
        }
    }
}

// ---------------------------------------------------------------------------
extern "C" void kernel_launch(void* const* d_in, const int* in_sizes, int n_in,
                              void* d_out, int out_size)
{
    const float* in_x  = (const float*)d_in[0];
    const float* W_sc  = (const float*)d_in[1];
    const float* b_sc  = (const float*)d_in[2];
    const float* W_qkv = (const float*)d_in[3];
    const float* b_qkv = (const float*)d_in[4];

    float* out       = (float*)d_out;
    float* score     = out;
    float* atten     = score + (size_t)BH_ * S_ * S_;
    float* res       = atten + (size_t)BH_ * S_ * KD;
    float* short_cut = res   + (size_t)B_ * S_ * D_;

    cudaFuncSetAttribute(gemm_mma<0>, cudaFuncAttributeMaxDynamicSharedMemorySize, SMEMB);
    cudaFuncSetAttribute(gemm_mma<1>, cudaFuncAttributeMaxDynamicSharedMemorySize, SMEMB);
    cudaFuncSetAttribute(gemm_mma<2>, cudaFuncAttributeMaxDynamicSharedMemorySize, SMEMB);

    pack_x<<<(unsigned)(((size_t)B_ * S_ * D_ / 4) / 256), 256>>>(in_x);
    trans_w<<<dim3(NTOT / 32, D_ / 32), 256>>>(W_sc, W_qkv, b_sc, b_qkv);
    // fused shortcut+qkv GEMM
    gemm_mma<0><<<dim3(NTOT / 128, (B_ * S_) / 128), 512, SMEMB>>>(
        nullptr, score, atten, res, short_cut);
    trans_v<<<dim3(S_ / 32, KD / 32, B_), 256>>>();
    colsum_v<<<B_ * 16, 128>>>();
    reduce_v1<<<B_, 128>>>();
    // score GEMM (+ partial exp sums)
    gemm_mma<1><<<dim3(S_ / 128, S_ / 128, BH_), 512, SMEMB>>>(
        nullptr, score, atten, res, short_cut);
    reduce_sums<<<(BH_ * S_) / 256, 256>>>();
    // PV GEMM (linearized softmax numerator)
    gemm_mma<2><<<dim3(S_ / 128, BH_), 512, SMEMB>>>(
        score, score, atten, res, short_cut);
}

// round 11
// speedup vs baseline: 4.1784x; 1.1551x over previous
#include <cuda_runtime.h>
#include <cuda_fp16.h>
#include <cstdint>
#include <cstddef>

#define S_    2048
#define D_    2048
#define QKV_N 2304
#define KD    128
#define NTOT  4352   // D + QKV_N
#define BH_   32
#define B_    2
#define H_    16

// ---------------- scratch (__device__ globals; no allocations) --------------
__device__ __align__(128) uint32_t g_xp[(size_t)B_ * S_ * D_];        // X hi/lo
__device__ __align__(128) uint32_t g_wtp[(size_t)NTOT * 1024];        // W^T hi
__device__ __align__(128) uint32_t g_qp[(size_t)B_ * S_ * D_];        // q hi/lo
__device__ __align__(128) uint32_t g_kp[(size_t)B_ * S_ * 64];        // k hi
__device__ __align__(128) uint32_t g_vtp[(size_t)B_ * KD * 1024];     // v^T hi
__device__ float g_v[(size_t)B_ * S_ * KD];                           // v fp32
__device__ float g_bias[NTOT];
__device__ float g_v1p[(size_t)B_ * 16 * KD];
__device__ float g_v1[(size_t)B_ * KD];                               // V1 = sum_t v[t,:]

// ---------------- helpers ----------------------------------------------------
__device__ __forceinline__ uint32_t smem_u32(const void* p) {
    uint32_t a;
    asm("{ .reg .u64 t; cvta.to.shared.u64 t, %1; cvt.u32.u64 %0, t; }" : "=r"(a) : "l"(p));
    return a;
}
__device__ __forceinline__ void mma_f16(float c[4], const uint32_t a[4],
                                        const uint32_t b[2]) {
    asm volatile(
        "mma.sync.aligned.m16n8k16.row.col.f32.f16.f16.f32 "
        "{%0,%1,%2,%3}, {%4,%5,%6,%7}, {%8,%9}, {%0,%1,%2,%3};"
        : "+f"(c[0]), "+f"(c[1]), "+f"(c[2]), "+f"(c[3])
        : "r"(a[0]), "r"(a[1]), "r"(a[2]), "r"(a[3]), "r"(b[0]), "r"(b[1]));
}
__device__ __forceinline__ void ldsm4(uint32_t r[4], uint32_t addr) {
    asm volatile("ldmatrix.sync.aligned.m8n8.x4.shared.b16 {%0,%1,%2,%3}, [%4];"
        : "=r"(r[0]), "=r"(r[1]), "=r"(r[2]), "=r"(r[3]) : "r"(addr));
}
__device__ __forceinline__ void cpa16(uint32_t s, const void* g) {
    asm volatile("cp.async.cg.shared.global [%0], [%1], 16;" :: "r"(s), "l"(g) : "memory");
}
#define CPA_COMMIT() asm volatile("cp.async.commit_group;" ::: "memory")
#define CPA_WAIT(n)  asm volatile("cp.async.wait_group %0;" :: "n"(n) : "memory")

__device__ __forceinline__ void split4h(float4 v, uint32_t& h01, uint32_t& h23,
                                        uint32_t& l01, uint32_t& l23) {
    __half hx = __float2half_rn(v.x), hy = __float2half_rn(v.y);
    __half hz = __float2half_rn(v.z), hw = __float2half_rn(v.w);
    __half2 H0 = __halves2half2(hx, hy), H1 = __halves2half2(hz, hw);
    __half2 L0 = __halves2half2(__float2half_rn(v.x - __half2float(hx)),
                                __float2half_rn(v.y - __half2float(hy)));
    __half2 L1 = __halves2half2(__float2half_rn(v.z - __half2float(hz)),
                                __float2half_rn(v.w - __half2float(hw)));
    h01 = *(uint32_t*)&H0; h23 = *(uint32_t*)&H1;
    l01 = *(uint32_t*)&L0; l23 = *(uint32_t*)&L1;
}

// ---------------------------------------------------------------------------
// prep kernels
// ---------------------------------------------------------------------------
__global__ void __launch_bounds__(256) pack_x(const float* __restrict__ in_x)
{
    const size_t fid = (size_t)blockIdx.x * 256 + threadIdx.x;
    const size_t row = fid >> 9;
    const int r = (int)(fid & 511);
    const int kc = r >> 3, f4 = r & 7, w = f4 * 4;
    float4 v = *(const float4*)(in_x + row * D_ + kc * 32 + w);
    uint32_t h01, h23, l01, l23;
    split4h(v, h01, h23, l01, l23);
    const size_t b32 = row * D_ + kc * 32;
    g_xp[b32 + (w >> 1)]      = h01;
    g_xp[b32 + (w >> 1) + 1]  = h23;
    g_xp[b32 + 16 + (w >> 1)] = l01;
    g_xp[b32 + 17 + (w >> 1)] = l23;
}

__global__ void __launch_bounds__(256) trans_w(
    const float* __restrict__ Wsc, const float* __restrict__ Wqkv,
    const float* __restrict__ bsc, const float* __restrict__ bqkv)
{
    __shared__ float t[32][33];
    const int n0 = blockIdx.x * 32, k0 = blockIdx.y * 32;
    const int tx = threadIdx.x & 31, ty = threadIdx.x >> 5;
    const int n = n0 + tx;
    #pragma unroll
    for (int r = 0; r < 4; r++) {
        int k = k0 + ty + r * 8;
        t[ty + r * 8][tx] = (n < D_) ? Wsc[(size_t)k * D_ + n]
                                     : Wqkv[(size_t)k * QKV_N + (n - D_)];
    }
    if (blockIdx.y == 0 && threadIdx.x < 32) {
        int nb = n0 + threadIdx.x;
        g_bias[nb] = (nb < D_) ? bsc[nb] : bqkv[nb - D_];
    }
    __syncthreads();
    uint16_t* p16 = (uint16_t*)g_wtp;
    const int kc = k0 >> 5;
    #pragma unroll
    for (int r = 0; r < 4; r++) {
        const int nn = n0 + ty + r * 8;
        __half h = __float2half_rn(t[tx][ty + r * 8]);
        p16[(size_t)nn * 2048 + kc * 32 + tx] = *(uint16_t*)&h;
    }
}

__global__ void __launch_bounds__(256) trans_v()
{
    __shared__ float t[32][33];
    const int b = blockIdx.z;
    const int t0 = blockIdx.x * 32, d0 = blockIdx.y * 32;
    const int tx = threadIdx.x & 31, ty = threadIdx.x >> 5;
    #pragma unroll
    for (int r = 0; r < 4; r++)
        t[ty + r * 8][tx] = g_v[(size_t)(b * S_ + t0 + ty + r * 8) * KD + d0 + tx];
    __syncthreads();
    uint16_t* p16 = (uint16_t*)g_vtp;
    const int tc = t0 >> 5;
    #pragma unroll
    for (int r = 0; r < 4; r++) {
        const int d = d0 + ty + r * 8;
        __half h = __float2half_rn(t[tx][ty + r * 8]);
        p16[((size_t)b * KD + d) * 2048 + tc * 32 + tx] = *(uint16_t*)&h;
    }
}

__global__ void __launch_bounds__(128) colsum_v()
{
    const int g = blockIdx.x, b = g >> 4, tc = g & 15, d = threadIdx.x;
    float s = 0.0f;
    #pragma unroll 8
    for (int t = 0; t < 128; t++)
        s += g_v[(size_t)(b * S_ + tc * 128 + t) * KD + d];
    g_v1p[(size_t)g * KD + d] = s;
}
__global__ void __launch_bounds__(128) reduce_v1()
{
    const int b = blockIdx.x, d = threadIdx.x;
    float s = 0.0f;
    #pragma unroll
    for (int c = 0; c < 16; c++)
        s += g_v1p[(size_t)(b * 16 + c) * KD + d];
    g_v1[b * KD + d] = s;
}

// ---------------------------------------------------------------------------
// GEMM0: C = X @ W^T + bias. fp16 2-term (X hi/lo, W hi). 512 thr, 4x4 warps,
// warp tile 32x32, BM=BN=128, BK=32, 3-stage cp.async, 1 sync/iter.
// ---------------------------------------------------------------------------
#define RSA    144
#define RSB    80
#define ABYT   (128 * RSA)
#define BBYT   (128 * RSB)
#define STAGEB (ABYT + BBYT)          // 28672
#define SMEM0  (3 * STAGEB)           // 86016

__global__ void __launch_bounds__(512, 1) gemm0(float* __restrict__ shortcut)
{
    extern __shared__ uint32_t smw[];
    const int tid = threadIdx.x;
    const int warp = tid >> 5, lane = tid & 31;
    const int gid = lane >> 2, tig = lane & 3;
    const int wm = warp >> 2, wn = warp & 3;
    const int m0 = blockIdx.y * 128, n0 = blockIdx.x * 128;

    const uint32_t smb = smem_u32(smw);
    const int lr = lane & 7;
    const int a_r8 = (lane >> 3) & 1, a_kh = lane >> 4;
    const int b_r8 = lane >> 4,       b_kh = (lane >> 3) & 1;
    uint32_t aAddr[2], bAddr[2];
    #pragma unroll
    for (int mt = 0; mt < 2; mt++)
        aAddr[mt] = smb + (uint32_t)(wm * 32 + mt * 16 + lr + a_r8 * 8) * RSA
                  + (uint32_t)(a_kh * 16);
    #pragma unroll
    for (int np = 0; np < 2; np++)
        bAddr[np] = smb + (uint32_t)ABYT
                  + (uint32_t)(wn * 32 + np * 16 + lr + b_r8 * 8) * RSB
                  + (uint32_t)(b_kh * 16);

    float c[2][4][4];
    #pragma unroll
    for (int mt = 0; mt < 2; mt++)
        #pragma unroll
        for (int nt = 0; nt < 4; nt++)
            #pragma unroll
            for (int q = 0; q < 4; q++) c[mt][nt][q] = 0.0f;

    const int a_row0 = tid >> 3, a16_0 = tid & 7;
    const int a_row1 = (tid + 512) >> 3, a16_1 = (tid + 512) & 7;
    const int b_row = tid >> 2, b16 = tid & 3;

    auto issue = [&](int it, int st) {
        const uint32_t sbase = smb + (uint32_t)(st * STAGEB);
        cpa16(sbase + (uint32_t)a_row0 * RSA + a16_0 * 16,
              g_xp + (size_t)(m0 + a_row0) * D_ + it * 32 + a16_0 * 4);
        cpa16(sbase + (uint32_t)a_row1 * RSA + a16_1 * 16,
              g_xp + (size_t)(m0 + a_row1) * D_ + it * 32 + a16_1 * 4);
        cpa16(sbase + ABYT + (uint32_t)b_row * RSB + b16 * 16,
              g_wtp + (size_t)(n0 + b_row) * 1024 + it * 16 + b16 * 4);
        CPA_COMMIT();
    };

    issue(0, 0); issue(1, 1);

    for (int it = 0; it < 64; it++) {
        CPA_WAIT(1);
        __syncthreads();
        if (it + 2 < 64) issue(it + 2, (it + 2) % 3);

        const uint32_t so = (uint32_t)((it % 3) * STAGEB);
        #pragma unroll
        for (int ks = 0; ks < 2; ks++) {
            const uint32_t ko = so + (uint32_t)(ks * 32);
            uint32_t ah[2][4], alo[2][4], bh2[2][4];
            #pragma unroll
            for (int mt = 0; mt < 2; mt++) {
                ldsm4(ah[mt], aAddr[mt] + ko);
                ldsm4(alo[mt], aAddr[mt] + ko + 64);
            }
            #pragma unroll
            for (int np = 0; np < 2; np++)
                ldsm4(bh2[np], bAddr[np] + ko);
            #pragma unroll
            for (int mt = 0; mt < 2; mt++)
                #pragma unroll
                for (int nt = 0; nt < 4; nt++) {
                    const uint32_t* bf = &bh2[nt >> 1][(nt & 1) * 2];
                    mma_f16(c[mt][nt], ah[mt], bf);
                    mma_f16(c[mt][nt], alo[mt], bf);
                }
        }
    }

    // epilogue: shortcut fp32 / q hi+lo / k hi / v fp32
    #pragma unroll
    for (int mt = 0; mt < 2; mt++) {
        const int r0 = m0 + wm * 32 + mt * 16 + gid;
        #pragma unroll
        for (int nt = 0; nt < 4; nt++) {
            const int n = n0 + wn * 32 + nt * 8 + 2 * tig;
            const float b0 = g_bias[n], b1 = g_bias[n + 1];
            float v00 = c[mt][nt][0] + b0, v01 = c[mt][nt][1] + b1;
            float v10 = c[mt][nt][2] + b0, v11 = c[mt][nt][3] + b1;
            if (n < D_) {
                *(float2*)(shortcut + (size_t)r0 * D_ + n)       = make_float2(v00, v01);
                *(float2*)(shortcut + (size_t)(r0 + 8) * D_ + n) = make_float2(v10, v11);
            } else if (n < 2 * D_) {
                const int qc = n - D_;
                const int chunk = qc >> 5, w = qc & 31;
                __half h00 = __float2half_rn(v00), h01h = __float2half_rn(v01);
                __half h10 = __float2half_rn(v10), h11h = __float2half_rn(v11);
                __half2 H0 = __halves2half2(h00, h01h);
                __half2 L0 = __halves2half2(
                    __float2half_rn(v00 - __half2float(h00)),
                    __float2half_rn(v01 - __half2float(h01h)));
                __half2 H1 = __halves2half2(h10, h11h);
                __half2 L1 = __halves2half2(
                    __float2half_rn(v10 - __half2float(h10)),
                    __float2half_rn(v11 - __half2float(h11h)));
                size_t q0 = (size_t)r0 * D_ + (size_t)chunk * 32 + (w >> 1);
                size_t q1 = (size_t)(r0 + 8) * D_ + (size_t)chunk * 32 + (w >> 1);
                g_qp[q0]      = *(uint32_t*)&H0;
                g_qp[q0 + 16] = *(uint32_t*)&L0;
                g_qp[q1]      = *(uint32_t*)&H1;
                g_qp[q1 + 16] = *(uint32_t*)&L1;
            } else if (n < 2 * D_ + KD) {
                const int kc2 = n - 2 * D_;
                const int chunk = kc2 >> 5, w = kc2 & 31;
                __half2 H0 = __halves2half2(__float2half_rn(v00), __float2half_rn(v01));
                __half2 H1 = __halves2half2(__float2half_rn(v10), __float2half_rn(v11));
                g_kp[(size_t)r0 * 64 + chunk * 16 + (w >> 1)]       = *(uint32_t*)&H0;
                g_kp[(size_t)(r0 + 8) * 64 + chunk * 16 + (w >> 1)] = *(uint32_t*)&H1;
            } else {
                const int d = n - (2 * D_ + KD);
                *(float2*)(g_v + (size_t)r0 * KD + d)       = make_float2(v00, v01);
                *(float2*)(g_v + (size_t)(r0 + 8) * KD + d) = make_float2(v10, v11);
            }
        }
    }
}

// ---------------------------------------------------------------------------
// Fused attention: per CTA (m-tile 128 rows, one bh): score out, Σexp in regs,
// Sv accumulated over 16 t-tiles; atten/res = (Sv + V1)/Σexp. 512 thr.
// smem: q[128x528] | K[128x272] | VT[2][128x272] | scoreA[128x272] | rsum[128]
// ---------------------------------------------------------------------------
#define QROW 528
#define QBYT (128 * QROW)          // 67584
#define TROW 272
#define TBYT (128 * TROW)          // 34816
#define OFF_K  QBYT
#define OFF_VT (QBYT + TBYT)
#define OFF_SA (QBYT + 3 * TBYT)
#define OFF_RS (QBYT + 4 * TBYT)
#define SMEMA  (OFF_RS + 512)      // 207360

__global__ void __launch_bounds__(512, 1) attn(
    float* __restrict__ score, float* __restrict__ atten, float* __restrict__ res)
{
    extern __shared__ uint32_t smw[];
    char* smc = (char*)smw;
    float* rsm = (float*)(smc + OFF_RS);

    const int tid = threadIdx.x;
    const int warp = tid >> 5, lane = tid & 31;
    const int gid = lane >> 2, tig = lane & 3;
    const int wm = warp >> 2, wn = warp & 3;

    const int m0 = blockIdx.x * 128;
    const int bh = blockIdx.y, bb = bh >> 4, h = bh & 15;

    const uint32_t smb = smem_u32(smw);
    const uint32_t* qg = g_qp + (size_t)bb * S_ * D_;
    const uint32_t* kg = g_kp + (size_t)bb * S_ * 64;
    const uint32_t* vg = g_vtp + (size_t)bb * KD * 1024;
    float* Cp = score + (size_t)bh * S_ * S_;

    // ---- q tile load (once): 4096 x 16B pieces ----
    {
        const int kc0 = 4 * h;
        #pragma unroll
        for (int p = 0; p < 8; p++) {
            int i = tid + p * 512;
            int row = i >> 5, rem = i & 31, cch = rem >> 3, sub = rem & 7;
            uint32_t soff = (sub < 4)
                ? (uint32_t)(row * QROW + cch * 64 + sub * 16)
                : (uint32_t)(row * QROW + 256 + cch * 64 + (sub - 4) * 16);
            const uint32_t* g = qg + (size_t)(m0 + row) * D_ + (kc0 + cch) * 32
                              + ((sub < 4) ? sub * 4 : 16 + (sub - 4) * 4);
            cpa16(smb + soff, g);
        }
        CPA_COMMIT();
    }
    if (tid < 128) rsm[tid] = 0.0f;

    // ---- cp.async issue helpers ----
    const int t_row = tid >> 4, t_s = tid & 15;   // 4 pieces/thread per tile
    auto issue_k = [&](int t) {
        #pragma unroll
        for (int p = 0; p < 4; p++) {
            int row = t_row + p * 32;
            cpa16(smb + OFF_K + (uint32_t)row * TROW + t_s * 16,
                  kg + (size_t)(t * 128 + row) * 64 + t_s * 4);
        }
        CPA_COMMIT();
    };
    auto issue_vt = [&](int t, int buf) {
        #pragma unroll
        for (int p = 0; p < 4; p++) {
            int d = t_row + p * 32;
            cpa16(smb + OFF_VT + (uint32_t)buf * TBYT + (uint32_t)d * TROW + t_s * 16,
                  vg + (size_t)d * 1024 + t * 64 + t_s * 4);
        }
        CPA_COMMIT();
    };

    // ---- ldmatrix base addresses ----
    const int lr = lane & 7;
    const int a_r8 = (lane >> 3) & 1, a_kh = lane >> 4;
    const int b_r8 = lane >> 4,       b_kh = (lane >> 3) & 1;
    uint32_t aQ[2], bK[2], aS[2], bV[2];
    #pragma unroll
    for (int mt = 0; mt < 2; mt++) {
        const uint32_t arow = (uint32_t)(wm * 32 + mt * 16 + lr + a_r8 * 8);
        aQ[mt] = smb + arow * QROW + (uint32_t)(a_kh * 16);
        aS[mt] = smb + OFF_SA + arow * TROW + (uint32_t)(a_kh * 16);
    }
    #pragma unroll
    for (int np = 0; np < 2; np++) {
        const uint32_t brow = (uint32_t)(wn * 32 + np * 16 + lr + b_r8 * 8);
        bK[np] = smb + OFF_K + brow * TROW + (uint32_t)(b_kh * 16);
        bV[np] = smb + OFF_VT + brow * TROW + (uint32_t)(b_kh * 16);
    }

    float c2[2][4][4];
    #pragma unroll
    for (int mt = 0; mt < 2; mt++)
        #pragma unroll
        for (int nt = 0; nt < 4; nt++)
            #pragma unroll
            for (int q = 0; q < 4; q++) c2[mt][nt][q] = 0.0f;
    float rs[2][2] = {{0.0f, 0.0f}, {0.0f, 0.0f}};

    // prologue loads
    issue_vt(0, 0);
    issue_k(0);

    const float inv = 1.0f / 16384.0f;

    for (int t0 = 0; t0 < 16; t0++) {
        if (t0 + 1 < 16) { issue_vt(t0 + 1, (t0 + 1) & 1); CPA_WAIT(1); }
        else             { CPA_WAIT(0); }
        __syncthreads();

        // ---- GEMM1: score tile = q (2-term) x k-tile ----
        float c1[2][4][4];
        #pragma unroll
        for (int mt = 0; mt < 2; mt++)
            #pragma unroll
            for (int nt = 0; nt < 4; nt++)
                #pragma unroll
                for (int q = 0; q < 4; q++) c1[mt][nt][q] = 0.0f;
        #pragma unroll
        for (int ks = 0; ks < 8; ks++) {
            const uint32_t ko = (uint32_t)(ks * 32);
            uint32_t ah[2][4], alo[2][4], bk2[2][4];
            #pragma unroll
            for (int mt = 0; mt < 2; mt++) {
                ldsm4(ah[mt], aQ[mt] + ko);
                ldsm4(alo[mt], aQ[mt] + ko + 256);
            }
            #pragma unroll
            for (int np = 0; np < 2; np++)
                ldsm4(bk2[np], bK[np] + ko);
            #pragma unroll
            for (int mt = 0; mt < 2; mt++)
                #pragma unroll
                for (int nt = 0; nt < 4; nt++) {
                    const uint32_t* bf = &bk2[nt >> 1][(nt & 1) * 2];
                    mma_f16(c1[mt][nt], ah[mt], bf);
                    mma_f16(c1[mt][nt], alo[mt], bf);
                }
        }

        // ---- epilogue1: score write, Σexp accum, scoreA fp16 ----
        #pragma unroll
        for (int mt = 0; mt < 2; mt++) {
            const int rl = wm * 32 + mt * 16 + gid;
            #pragma unroll
            for (int nt = 0; nt < 4; nt++) {
                const int col = wn * 32 + nt * 8 + 2 * tig;
                float v0 = c1[mt][nt][0] * inv, v1 = c1[mt][nt][1] * inv;
                float v2 = c1[mt][nt][2] * inv, v3 = c1[mt][nt][3] * inv;
                *(float2*)(Cp + (size_t)(m0 + rl) * S_ + t0 * 128 + col)
                    = make_float2(v0, v1);
                *(float2*)(Cp + (size_t)(m0 + rl + 8) * S_ + t0 * 128 + col)
                    = make_float2(v2, v3);
                rs[mt][0] += __expf(v0) + __expf(v1);
                rs[mt][1] += __expf(v2) + __expf(v3);
                __half2 P0 = __halves2half2(__float2half_rn(v0), __float2half_rn(v1));
                __half2 P1 = __halves2half2(__float2half_rn(v2), __float2half_rn(v3));
                *(uint32_t*)(smc + OFF_SA + rl * TROW + col * 2)       = *(uint32_t*)&P0;
                *(uint32_t*)(smc + OFF_SA + (rl + 8) * TROW + col * 2) = *(uint32_t*)&P1;
            }
        }
        __syncthreads();
        if (t0 + 1 < 16) issue_k(t0 + 1);   // overlaps GEMM2

        // ---- GEMM2: Sv += scoreA (1-term) x vT-tile ----
        {
            const uint32_t vb = (uint32_t)((t0 & 1) * TBYT);
            #pragma unroll
            for (int ks = 0; ks < 8; ks++) {
                const uint32_t ko = (uint32_t)(ks * 32);
                uint32_t as2[2][4], bv2[2][4];
                #pragma unroll
                for (int mt = 0; mt < 2; mt++)
                    ldsm4(as2[mt], aS[mt] + ko);
                #pragma unroll
                for (int np = 0; np < 2; np++)
                    ldsm4(bv2[np], bV[np] + vb + ko);
                #pragma unroll
                for (int mt = 0; mt < 2; mt++)
                    #pragma unroll
                    for (int nt = 0; nt < 4; nt++)
                        mma_f16(c2[mt][nt], as2[mt], &bv2[nt >> 1][(nt & 1) * 2]);
            }
        }
        __syncthreads();
    }

    // ---- Σexp cross-warp reduce ----
    #pragma unroll
    for (int mt = 0; mt < 2; mt++) {
        float a = rs[mt][0], b = rs[mt][1];
        a += __shfl_xor_sync(0xFFFFFFFFu, a, 1);
        a += __shfl_xor_sync(0xFFFFFFFFu, a, 2);
        b += __shfl_xor_sync(0xFFFFFFFFu, b, 1);
        b += __shfl_xor_sync(0xFFFFFFFFu, b, 2);
        if (tig == 0) {
            atomicAdd(&rsm[wm * 32 + mt * 16 + gid], a);
            atomicAdd(&rsm[wm * 32 + mt * 16 + gid + 8], b);
        }
    }
    __syncthreads();

    // ---- final: atten / res ----
    #pragma unroll
    for (int mt = 0; mt < 2; mt++) {
        const int rl = wm * 32 + mt * 16 + gid;
        const int r0 = m0 + rl;
        const float il0 = 1.0f / rsm[rl];
        const float il1 = 1.0f / rsm[rl + 8];
        #pragma unroll
        for (int nt = 0; nt < 4; nt++) {
            const int col = wn * 32 + nt * 8 + 2 * tig;
            const float w0 = g_v1[bb * KD + col], w1 = g_v1[bb * KD + col + 1];
            float2 o0 = make_float2((c2[mt][nt][0] + w0) * il0,
                                    (c2[mt][nt][1] + w1) * il0);
            float2 o1 = make_float2((c2[mt][nt][2] + w0) * il1,
                                    (c2[mt][nt][3] + w1) * il1);
            *(float2*)(atten + (size_t)bh * S_ * KD + (size_t)r0 * KD + col) = o0;
            *(float2*)(atten + (size_t)bh * S_ * KD + (size_t)(r0 + 8) * KD + col) = o1;
            *(float2*)(res + (size_t)(bb * S_ + r0) * D_ + h * KD + col) = o0;
            *(float2*)(res + (size_t)(bb * S_ + r0 + 8) * D_ + h * KD + col) = o1;
        }
    }
}

// ---------------------------------------------------------------------------
extern "C" void kernel_launch(void* const* d_in, const int* in_sizes, int n_in,
                              void* d_out, int out_size)
{
    const float* in_x  = (const float*)d_in[0];
    const float* W_sc  = (const float*)d_in[1];
    const float* b_sc  = (const float*)d_in[2];
    const float* W_qkv = (const float*)d_in[3];
    const float* b_qkv = (const float*)d_in[4];

    float* out       = (float*)d_out;
    float* score     = out;
    float* atten     = score + (size_t)BH_ * S_ * S_;
    float* res       = atten + (size_t)BH_ * S_ * KD;
    float* short_cut = res   + (size_t)B_ * S_ * D_;

    cudaFuncSetAttribute(gemm0, cudaFuncAttributeMaxDynamicSharedMemorySize, SMEM0);
    cudaFuncSetAttribute(attn,  cudaFuncAttributeMaxDynamicSharedMemorySize, SMEMA);

    pack_x<<<(unsigned)(((size_t)B_ * S_ * D_ / 4) / 256), 256>>>(in_x);
    trans_w<<<dim3(NTOT / 32, D_ / 32), 256>>>(W_sc, W_qkv, b_sc, b_qkv);
    gemm0<<<dim3(NTOT / 128, (B_ * S_) / 128), 512, SMEM0>>>(short_cut);
    trans_v<<<dim3(S_ / 32, KD / 32, B_), 256>>>();
    colsum_v<<<B_ * 16, 128>>>();
    reduce_v1<<<B_, 128>>>();
    attn<<<dim3(S_ / 128, BH_), 512, SMEMA>>>(score, atten, res);
}

// round 12
// speedup vs baseline: 5.4631x; 1.3075x over previous
#include <cuda_runtime.h>
#include <cuda_fp16.h>
#include <cstdint>
#include <cstddef>

#define S_    2048
#define D_    2048
#define QKV_N 2304
#define KD    128
#define NTOT  4352   // D + QKV_N
#define BH_   32
#define B_    2
#define H_    16

// ---------------- scratch (__device__ globals; no allocations) --------------
__device__ __align__(128) uint32_t g_xp[(size_t)B_ * S_ * 1024];      // X hi only
__device__ __align__(128) uint32_t g_wtp[(size_t)NTOT * 1024];        // W^T hi
__device__ __align__(128) uint32_t g_qp[(size_t)B_ * S_ * D_];        // q hi/lo
__device__ __align__(128) uint32_t g_kp[(size_t)B_ * S_ * 64];        // k hi
__device__ __align__(128) uint32_t g_vtp[(size_t)B_ * KD * 1024];     // v^T hi
__device__ float g_v[(size_t)B_ * S_ * KD];                           // v fp32
__device__ float g_bias[NTOT];
__device__ float g_v1p[(size_t)B_ * 16 * KD];
__device__ float g_v1[(size_t)B_ * KD];                               // V1 = sum_t v[t,:]

// ---------------- helpers ----------------------------------------------------
__device__ __forceinline__ uint32_t smem_u32(const void* p) {
    uint32_t a;
    asm("{ .reg .u64 t; cvta.to.shared.u64 t, %1; cvt.u32.u64 %0, t; }" : "=r"(a) : "l"(p));
    return a;
}
__device__ __forceinline__ void mma_f16(float c[4], const uint32_t a[4],
                                        const uint32_t b[2]) {
    asm volatile(
        "mma.sync.aligned.m16n8k16.row.col.f32.f16.f16.f32 "
        "{%0,%1,%2,%3}, {%4,%5,%6,%7}, {%8,%9}, {%0,%1,%2,%3};"
        : "+f"(c[0]), "+f"(c[1]), "+f"(c[2]), "+f"(c[3])
        : "r"(a[0]), "r"(a[1]), "r"(a[2]), "r"(a[3]), "r"(b[0]), "r"(b[1]));
}
__device__ __forceinline__ void ldsm4(uint32_t r[4], uint32_t addr) {
    asm volatile("ldmatrix.sync.aligned.m8n8.x4.shared.b16 {%0,%1,%2,%3}, [%4];"
        : "=r"(r[0]), "=r"(r[1]), "=r"(r[2]), "=r"(r[3]) : "r"(addr));
}
__device__ __forceinline__ void cpa16(uint32_t s, const void* g) {
    asm volatile("cp.async.cg.shared.global [%0], [%1], 16;" :: "r"(s), "l"(g) : "memory");
}
#define CPA_COMMIT() asm volatile("cp.async.commit_group;" ::: "memory")
#define CPA_WAIT(n)  asm volatile("cp.async.wait_group %0;" :: "n"(n) : "memory")

// ---------------------------------------------------------------------------
// prep kernels
// ---------------------------------------------------------------------------
__global__ void __launch_bounds__(256) pack_x(const float* __restrict__ in_x)
{
    const size_t fid = (size_t)blockIdx.x * 256 + threadIdx.x;
    const size_t row = fid >> 9;
    const int r = (int)(fid & 511);
    const int kc = r >> 3, f4 = r & 7;
    float4 v = *(const float4*)(in_x + row * D_ + kc * 32 + f4 * 4);
    __half2 H0 = __halves2half2(__float2half_rn(v.x), __float2half_rn(v.y));
    __half2 H1 = __halves2half2(__float2half_rn(v.z), __float2half_rn(v.w));
    const size_t b32 = row * 1024 + kc * 16;
    g_xp[b32 + f4 * 2]     = *(uint32_t*)&H0;
    g_xp[b32 + f4 * 2 + 1] = *(uint32_t*)&H1;
}

__global__ void __launch_bounds__(256) trans_w(
    const float* __restrict__ Wsc, const float* __restrict__ Wqkv,
    const float* __restrict__ bsc, const float* __restrict__ bqkv)
{
    __shared__ float t[32][33];
    const int n0 = blockIdx.x * 32, k0 = blockIdx.y * 32;
    const int tx = threadIdx.x & 31, ty = threadIdx.x >> 5;
    const int n = n0 + tx;
    #pragma unroll
    for (int r = 0; r < 4; r++) {
        int k = k0 + ty + r * 8;
        t[ty + r * 8][tx] = (n < D_) ? Wsc[(size_t)k * D_ + n]
                                     : Wqkv[(size_t)k * QKV_N + (n - D_)];
    }
    if (blockIdx.y == 0 && threadIdx.x < 32) {
        int nb = n0 + threadIdx.x;
        g_bias[nb] = (nb < D_) ? bsc[nb] : bqkv[nb - D_];
    }
    __syncthreads();
    uint16_t* p16 = (uint16_t*)g_wtp;
    const int kc = k0 >> 5;
    #pragma unroll
    for (int r = 0; r < 4; r++) {
        const int nn = n0 + ty + r * 8;
        __half h = __float2half_rn(t[tx][ty + r * 8]);
        p16[(size_t)nn * 2048 + kc * 32 + tx] = *(uint16_t*)&h;
    }
}

__global__ void __launch_bounds__(256) trans_v()
{
    __shared__ float t[32][33];
    const int b = blockIdx.z;
    const int t0 = blockIdx.x * 32, d0 = blockIdx.y * 32;
    const int tx = threadIdx.x & 31, ty = threadIdx.x >> 5;
    #pragma unroll
    for (int r = 0; r < 4; r++)
        t[ty + r * 8][tx] = g_v[(size_t)(b * S_ + t0 + ty + r * 8) * KD + d0 + tx];
    __syncthreads();
    uint16_t* p16 = (uint16_t*)g_vtp;
    const int tc = t0 >> 5;
    #pragma unroll
    for (int r = 0; r < 4; r++) {
        const int d = d0 + ty + r * 8;
        __half h = __float2half_rn(t[tx][ty + r * 8]);
        p16[((size_t)b * KD + d) * 2048 + tc * 32 + tx] = *(uint16_t*)&h;
    }
}

__global__ void __launch_bounds__(128) colsum_v()
{
    const int g = blockIdx.x, b = g >> 4, tc = g & 15, d = threadIdx.x;
    float s = 0.0f;
    #pragma unroll 8
    for (int t = 0; t < 128; t++)
        s += g_v[(size_t)(b * S_ + tc * 128 + t) * KD + d];
    g_v1p[(size_t)g * KD + d] = s;
}
__global__ void __launch_bounds__(128) reduce_v1()
{
    const int b = blockIdx.x, d = threadIdx.x;
    float s = 0.0f;
    #pragma unroll
    for (int c = 0; c < 16; c++)
        s += g_v1p[(size_t)(b * 16 + c) * KD + d];
    g_v1[b * KD + d] = s;
}

// ---------------------------------------------------------------------------
// GEMM0: C = X @ W^T + bias. fp16 1-term (X hi, W hi). 512 thr, 4x4 warps,
// warp tile 32x32, BM=BN=128, BK=32, 3-stage cp.async, 1 sync/iter.
// smem rows 80B (64 data + 16 pad) for both operands.
// ---------------------------------------------------------------------------
#define RS0    80
#define TBYT0  (128 * RS0)            // 10240
#define STAGE0 (2 * TBYT0)            // 20480
#define SMEM0  (3 * STAGE0)           // 61440

__global__ void __launch_bounds__(512, 1) gemm0(float* __restrict__ shortcut)
{
    extern __shared__ uint32_t smw[];
    const int tid = threadIdx.x;
    const int warp = tid >> 5, lane = tid & 31;
    const int gid = lane >> 2, tig = lane & 3;
    const int wm = warp >> 2, wn = warp & 3;
    const int m0 = blockIdx.y * 128, n0 = blockIdx.x * 128;

    const uint32_t smb = smem_u32(smw);
    const int lr = lane & 7;
    const int a_r8 = (lane >> 3) & 1, a_kh = lane >> 4;
    const int b_r8 = lane >> 4,       b_kh = (lane >> 3) & 1;
    uint32_t aAddr[2], bAddr[2];
    #pragma unroll
    for (int mt = 0; mt < 2; mt++)
        aAddr[mt] = smb + (uint32_t)(wm * 32 + mt * 16 + lr + a_r8 * 8) * RS0
                  + (uint32_t)(a_kh * 16);
    #pragma unroll
    for (int np = 0; np < 2; np++)
        bAddr[np] = smb + (uint32_t)TBYT0
                  + (uint32_t)(wn * 32 + np * 16 + lr + b_r8 * 8) * RS0
                  + (uint32_t)(b_kh * 16);

    float c[2][4][4];
    #pragma unroll
    for (int mt = 0; mt < 2; mt++)
        #pragma unroll
        for (int nt = 0; nt < 4; nt++)
            #pragma unroll
            for (int q = 0; q < 4; q++) c[mt][nt][q] = 0.0f;

    const int c_row = tid >> 2, c_s = tid & 3;   // 512 pieces per operand tile

    auto issue = [&](int it, int st) {
        const uint32_t sbase = smb + (uint32_t)(st * STAGE0);
        cpa16(sbase + (uint32_t)c_row * RS0 + c_s * 16,
              g_xp + (size_t)(m0 + c_row) * 1024 + it * 16 + c_s * 4);
        cpa16(sbase + TBYT0 + (uint32_t)c_row * RS0 + c_s * 16,
              g_wtp + (size_t)(n0 + c_row) * 1024 + it * 16 + c_s * 4);
        CPA_COMMIT();
    };

    issue(0, 0); issue(1, 1);

    for (int it = 0; it < 64; it++) {
        CPA_WAIT(1);
        __syncthreads();
        if (it + 2 < 64) issue(it + 2, (it + 2) % 3);

        const uint32_t so = (uint32_t)((it % 3) * STAGE0);
        #pragma unroll
        for (int ks = 0; ks < 2; ks++) {
            const uint32_t ko = so + (uint32_t)(ks * 32);
            uint32_t ah[2][4], bh2[2][4];
            #pragma unroll
            for (int mt = 0; mt < 2; mt++)
                ldsm4(ah[mt], aAddr[mt] + ko);
            #pragma unroll
            for (int np = 0; np < 2; np++)
                ldsm4(bh2[np], bAddr[np] + ko);
            #pragma unroll
            for (int mt = 0; mt < 2; mt++)
                #pragma unroll
                for (int nt = 0; nt < 4; nt++)
                    mma_f16(c[mt][nt], ah[mt], &bh2[nt >> 1][(nt & 1) * 2]);
        }
    }

    // epilogue: shortcut fp32 / q hi+lo / k hi / v fp32
    #pragma unroll
    for (int mt = 0; mt < 2; mt++) {
        const int r0 = m0 + wm * 32 + mt * 16 + gid;
        #pragma unroll
        for (int nt = 0; nt < 4; nt++) {
            const int n = n0 + wn * 32 + nt * 8 + 2 * tig;
            const float b0 = g_bias[n], b1 = g_bias[n + 1];
            float v00 = c[mt][nt][0] + b0, v01 = c[mt][nt][1] + b1;
            float v10 = c[mt][nt][2] + b0, v11 = c[mt][nt][3] + b1;
            if (n < D_) {
                *(float2*)(shortcut + (size_t)r0 * D_ + n)       = make_float2(v00, v01);
                *(float2*)(shortcut + (size_t)(r0 + 8) * D_ + n) = make_float2(v10, v11);
            } else if (n < 2 * D_) {
                const int qc = n - D_;
                const int chunk = qc >> 5, w = qc & 31;
                __half h00 = __float2half_rn(v00), h01h = __float2half_rn(v01);
                __half h10 = __float2half_rn(v10), h11h = __float2half_rn(v11);
                __half2 H0 = __halves2half2(h00, h01h);
                __half2 L0 = __halves2half2(
                    __float2half_rn(v00 - __half2float(h00)),
                    __float2half_rn(v01 - __half2float(h01h)));
                __half2 H1 = __halves2half2(h10, h11h);
                __half2 L1 = __halves2half2(
                    __float2half_rn(v10 - __half2float(h10)),
                    __float2half_rn(v11 - __half2float(h11h)));
                size_t q0 = (size_t)r0 * D_ + (size_t)chunk * 32 + (w >> 1);
                size_t q1 = (size_t)(r0 + 8) * D_ + (size_t)chunk * 32 + (w >> 1);
                g_qp[q0]      = *(uint32_t*)&H0;
                g_qp[q0 + 16] = *(uint32_t*)&L0;
                g_qp[q1]      = *(uint32_t*)&H1;
                g_qp[q1 + 16] = *(uint32_t*)&L1;
            } else if (n < 2 * D_ + KD) {
                const int kc2 = n - 2 * D_;
                const int chunk = kc2 >> 5, w = kc2 & 31;
                __half2 H0 = __halves2half2(__float2half_rn(v00), __float2half_rn(v01));
                __half2 H1 = __halves2half2(__float2half_rn(v10), __float2half_rn(v11));
                g_kp[(size_t)r0 * 64 + chunk * 16 + (w >> 1)]       = *(uint32_t*)&H0;
                g_kp[(size_t)(r0 + 8) * 64 + chunk * 16 + (w >> 1)] = *(uint32_t*)&H1;
            } else {
                const int d = n - (2 * D_ + KD);
                *(float2*)(g_v + (size_t)r0 * KD + d)       = make_float2(v00, v01);
                *(float2*)(g_v + (size_t)(r0 + 8) * KD + d) = make_float2(v10, v11);
            }
        }
    }
}

// ---------------------------------------------------------------------------
// Fused attention: per CTA (m-tile 128 rows, one bh): score out, Σexp in regs,
// Sv accumulated over 16 t-tiles; atten/res = (Sv + V1)/Σexp. 512 thr.
// smem: q[128x528] | K[128x272] | VT[2][128x272] | scoreA[128x272] | rsum[128]
// ---------------------------------------------------------------------------
#define QROW 528
#define QBYT (128 * QROW)          // 67584
#define TROW 272
#define TBYT (128 * TROW)          // 34816
#define OFF_K  QBYT
#define OFF_VT (QBYT + TBYT)
#define OFF_SA (QBYT + 3 * TBYT)
#define OFF_RS (QBYT + 4 * TBYT)
#define SMEMA  (OFF_RS + 512)      // 207360

__global__ void __launch_bounds__(512, 1) attn(
    float* __restrict__ score, float* __restrict__ atten, float* __restrict__ res)
{
    extern __shared__ uint32_t smw[];
    char* smc = (char*)smw;
    float* rsm = (float*)(smc + OFF_RS);

    const int tid = threadIdx.x;
    const int warp = tid >> 5, lane = tid & 31;
    const int gid = lane >> 2, tig = lane & 3;
    const int wm = warp >> 2, wn = warp & 3;

    const int m0 = blockIdx.x * 128;
    const int bh = blockIdx.y, bb = bh >> 4, h = bh & 15;

    const uint32_t smb = smem_u32(smw);
    const uint32_t* qg = g_qp + (size_t)bb * S_ * D_;
    const uint32_t* kg = g_kp + (size_t)bb * S_ * 64;
    const uint32_t* vg = g_vtp + (size_t)bb * KD * 1024;
    float* Cp = score + (size_t)bh * S_ * S_;

    // ---- q tile load (once) ----
    {
        const int kc0 = 4 * h;
        #pragma unroll
        for (int p = 0; p < 8; p++) {
            int i = tid + p * 512;
            int row = i >> 5, rem = i & 31, cch = rem >> 3, sub = rem & 7;
            uint32_t soff = (sub < 4)
                ? (uint32_t)(row * QROW + cch * 64 + sub * 16)
                : (uint32_t)(row * QROW + 256 + cch * 64 + (sub - 4) * 16);
            const uint32_t* g = qg + (size_t)(m0 + row) * D_ + (kc0 + cch) * 32
                              + ((sub < 4) ? sub * 4 : 16 + (sub - 4) * 4);
            cpa16(smb + soff, g);
        }
        CPA_COMMIT();
    }
    if (tid < 128) rsm[tid] = 0.0f;

    const int t_row = tid >> 4, t_s = tid & 15;
    auto issue_k = [&](int t) {
        #pragma unroll
        for (int p = 0; p < 4; p++) {
            int row = t_row + p * 32;
            cpa16(smb + OFF_K + (uint32_t)row * TROW + t_s * 16,
                  kg + (size_t)(t * 128 + row) * 64 + t_s * 4);
        }
        CPA_COMMIT();
    };
    auto issue_vt = [&](int t, int buf) {
        #pragma unroll
        for (int p = 0; p < 4; p++) {
            int d = t_row + p * 32;
            cpa16(smb + OFF_VT + (uint32_t)buf * TBYT + (uint32_t)d * TROW + t_s * 16,
                  vg + (size_t)d * 1024 + t * 64 + t_s * 4);
        }
        CPA_COMMIT();
    };

    const int lr = lane & 7;
    const int a_r8 = (lane >> 3) & 1, a_kh = lane >> 4;
    const int b_r8 = lane >> 4,       b_kh = (lane >> 3) & 1;
    uint32_t aQ[2], bK[2], aS[2], bV[2];
    #pragma unroll
    for (int mt = 0; mt < 2; mt++) {
        const uint32_t arow = (uint32_t)(wm * 32 + mt * 16 + lr + a_r8 * 8);
        aQ[mt] = smb + arow * QROW + (uint32_t)(a_kh * 16);
        aS[mt] = smb + OFF_SA + arow * TROW + (uint32_t)(a_kh * 16);
    }
    #pragma unroll
    for (int np = 0; np < 2; np++) {
        const uint32_t brow = (uint32_t)(wn * 32 + np * 16 + lr + b_r8 * 8);
        bK[np] = smb + OFF_K + brow * TROW + (uint32_t)(b_kh * 16);
        bV[np] = smb + OFF_VT + brow * TROW + (uint32_t)(b_kh * 16);
    }

    float c2[2][4][4];
    #pragma unroll
    for (int mt = 0; mt < 2; mt++)
        #pragma unroll
        for (int nt = 0; nt < 4; nt++)
            #pragma unroll
            for (int q = 0; q < 4; q++) c2[mt][nt][q] = 0.0f;
    float rs[2][2] = {{0.0f, 0.0f}, {0.0f, 0.0f}};

    issue_vt(0, 0);
    issue_k(0);

    const float inv = 1.0f / 16384.0f;

    for (int t0 = 0; t0 < 16; t0++) {
        if (t0 + 1 < 16) { issue_vt(t0 + 1, (t0 + 1) & 1); CPA_WAIT(1); }
        else             { CPA_WAIT(0); }
        __syncthreads();

        // ---- GEMM1: score tile = q (2-term) x k-tile ----
        float c1[2][4][4];
        #pragma unroll
        for (int mt = 0; mt < 2; mt++)
            #pragma unroll
            for (int nt = 0; nt < 4; nt++)
                #pragma unroll
                for (int q = 0; q < 4; q++) c1[mt][nt][q] = 0.0f;
        #pragma unroll
        for (int ks = 0; ks < 8; ks++) {
            const uint32_t ko = (uint32_t)(ks * 32);
            uint32_t ah[2][4], alo[2][4], bk2[2][4];
            #pragma unroll
            for (int mt = 0; mt < 2; mt++) {
                ldsm4(ah[mt], aQ[mt] + ko);
                ldsm4(alo[mt], aQ[mt] + ko + 256);
            }
            #pragma unroll
            for (int np = 0; np < 2; np++)
                ldsm4(bk2[np], bK[np] + ko);
            #pragma unroll
            for (int mt = 0; mt < 2; mt++)
                #pragma unroll
                for (int nt = 0; nt < 4; nt++) {
                    const uint32_t* bf = &bk2[nt >> 1][(nt & 1) * 2];
                    mma_f16(c1[mt][nt], ah[mt], bf);
                    mma_f16(c1[mt][nt], alo[mt], bf);
                }
        }

        // ---- epilogue1: score write, Σexp accum, scoreA fp16 ----
        #pragma unroll
        for (int mt = 0; mt < 2; mt++) {
            const int rl = wm * 32 + mt * 16 + gid;
            #pragma unroll
            for (int nt = 0; nt < 4; nt++) {
                const int col = wn * 32 + nt * 8 + 2 * tig;
                float v0 = c1[mt][nt][0] * inv, v1 = c1[mt][nt][1] * inv;
                float v2 = c1[mt][nt][2] * inv, v3 = c1[mt][nt][3] * inv;
                *(float2*)(Cp + (size_t)(m0 + rl) * S_ + t0 * 128 + col)
                    = make_float2(v0, v1);
                *(float2*)(Cp + (size_t)(m0 + rl + 8) * S_ + t0 * 128 + col)
                    = make_float2(v2, v3);
                rs[mt][0] += __expf(v0) + __expf(v1);
                rs[mt][1] += __expf(v2) + __expf(v3);
                __half2 P0 = __halves2half2(__float2half_rn(v0), __float2half_rn(v1));
                __half2 P1 = __halves2half2(__float2half_rn(v2), __float2half_rn(v3));
                *(uint32_t*)(smc + OFF_SA + rl * TROW + col * 2)       = *(uint32_t*)&P0;
                *(uint32_t*)(smc + OFF_SA + (rl + 8) * TROW + col * 2) = *(uint32_t*)&P1;
            }
        }
        __syncthreads();
        if (t0 + 1 < 16) issue_k(t0 + 1);   // overlaps GEMM2

        // ---- GEMM2: Sv += scoreA (1-term) x vT-tile ----
        {
            const uint32_t vb = (uint32_t)((t0 & 1) * TBYT);
            #pragma unroll
            for (int ks = 0; ks < 8; ks++) {
                const uint32_t ko = (uint32_t)(ks * 32);
                uint32_t as2[2][4], bv2[2][4];
                #pragma unroll
                for (int mt = 0; mt < 2; mt++)
                    ldsm4(as2[mt], aS[mt] + ko);
                #pragma unroll
                for (int np = 0; np < 2; np++)
                    ldsm4(bv2[np], bV[np] + vb + ko);
                #pragma unroll
                for (int mt = 0; mt < 2; mt++)
                    #pragma unroll
                    for (int nt = 0; nt < 4; nt++)
                        mma_f16(c2[mt][nt], as2[mt], &bv2[nt >> 1][(nt & 1) * 2]);
            }
        }
        __syncthreads();
    }

    // ---- Σexp cross-warp reduce ----
    #pragma unroll
    for (int mt = 0; mt < 2; mt++) {
        float a = rs[mt][0], b = rs[mt][1];
        a += __shfl_xor_sync(0xFFFFFFFFu, a, 1);
        a += __shfl_xor_sync(0xFFFFFFFFu, a, 2);
        b += __shfl_xor_sync(0xFFFFFFFFu, b, 1);
        b += __shfl_xor_sync(0xFFFFFFFFu, b, 2);
        if (tig == 0) {
            atomicAdd(&rsm[wm * 32 + mt * 16 + gid], a);
            atomicAdd(&rsm[wm * 32 + mt * 16 + gid + 8], b);
        }
    }
    __syncthreads();

    // ---- final: atten / res ----
    #pragma unroll
    for (int mt = 0; mt < 2; mt++) {
        const int rl = wm * 32 + mt * 16 + gid;
        const int r0 = m0 + rl;
        const float il0 = 1.0f / rsm[rl];
        const float il1 = 1.0f / rsm[rl + 8];
        #pragma unroll
        for (int nt = 0; nt < 4; nt++) {
            const int col = wn * 32 + nt * 8 + 2 * tig;
            const float w0 = g_v1[bb * KD + col], w1 = g_v1[bb * KD + col + 1];
            float2 o0 = make_float2((c2[mt][nt][0] + w0) * il0,
                                    (c2[mt][nt][1] + w1) * il0);
            float2 o1 = make_float2((c2[mt][nt][2] + w0) * il1,
                                    (c2[mt][nt][3] + w1) * il1);
            *(float2*)(atten + (size_t)bh * S_ * KD + (size_t)r0 * KD + col) = o0;
            *(float2*)(atten + (size_t)bh * S_ * KD + (size_t)(r0 + 8) * KD + col) = o1;
            *(float2*)(res + (size_t)(bb * S_ + r0) * D_ + h * KD + col) = o0;
            *(float2*)(res + (size_t)(bb * S_ + r0 + 8) * D_ + h * KD + col) = o1;
        }
    }
}

// ---------------------------------------------------------------------------
extern "C" void kernel_launch(void* const* d_in, const int* in_sizes, int n_in,
                              void* d_out, int out_size)
{
    const float* in_x  = (const float*)d_in[0];
    const float* W_sc  = (const float*)d_in[1];
    const float* b_sc  = (const float*)d_in[2];
    const float* W_qkv = (const float*)d_in[3];
    const float* b_qkv = (const float*)d_in[4];

    float* out       = (float*)d_out;
    float* score     = out;
    float* atten     = score + (size_t)BH_ * S_ * S_;
    float* res       = atten + (size_t)BH_ * S_ * KD;
    float* short_cut = res   + (size_t)B_ * S_ * D_;

    cudaFuncSetAttribute(gemm0, cudaFuncAttributeMaxDynamicSharedMemorySize, SMEM0);
    cudaFuncSetAttribute(attn,  cudaFuncAttributeMaxDynamicSharedMemorySize, SMEMA);

    pack_x<<<(unsigned)(((size_t)B_ * S_ * D_ / 4) / 256), 256>>>(in_x);
    trans_w<<<dim3(NTOT / 32, D_ / 32), 256>>>(W_sc, W_qkv, b_sc, b_qkv);
    gemm0<<<dim3(NTOT / 128, (B_ * S_) / 128), 512, SMEM0>>>(short_cut);
    trans_v<<<dim3(S_ / 32, KD / 32, B_), 256>>>();
    colsum_v<<<B_ * 16, 128>>>();
    reduce_v1<<<B_, 128>>>();
    attn<<<dim3(S_ / 128, BH_), 512, SMEMA>>>(score, atten, res);
}

// round 13
// speedup vs baseline: 6.0070x; 1.0996x over previous
#include <cuda_runtime.h>
#include <cuda_fp16.h>
#include <cstdint>
#include <cstddef>

#define S_    2048
#define D_    2048
#define QKV_N 2304
#define KD    128
#define NTOT  4352   // D + QKV_N
#define BH_   32
#define B_    2
#define H_    16

// ---------------- scratch (__device__ globals; no allocations) --------------
__device__ __align__(128) uint32_t g_xp[(size_t)B_ * S_ * 1024];      // X hi
__device__ __align__(128) uint32_t g_wtp[(size_t)NTOT * 1024];        // W^T hi
__device__ __align__(128) uint32_t g_qp[(size_t)B_ * S_ * 1024];      // q hi
__device__ __align__(128) uint32_t g_kp[(size_t)B_ * S_ * 64];        // k hi
__device__ __align__(128) uint32_t g_vtp[(size_t)B_ * KD * 1024];     // v^T hi
__device__ float g_v[(size_t)B_ * S_ * KD];                           // v fp32
__device__ float g_bias[NTOT];
__device__ float g_v1p[(size_t)B_ * 16 * KD];
__device__ float g_v1[(size_t)B_ * KD];                               // V1 = sum_t v[t,:]

// ---------------- helpers ----------------------------------------------------
__device__ __forceinline__ uint32_t smem_u32(const void* p) {
    uint32_t a;
    asm("{ .reg .u64 t; cvta.to.shared.u64 t, %1; cvt.u32.u64 %0, t; }" : "=r"(a) : "l"(p));
    return a;
}
__device__ __forceinline__ void mma_f16(float c[4], const uint32_t a[4],
                                        const uint32_t b[2]) {
    asm volatile(
        "mma.sync.aligned.m16n8k16.row.col.f32.f16.f16.f32 "
        "{%0,%1,%2,%3}, {%4,%5,%6,%7}, {%8,%9}, {%0,%1,%2,%3};"
        : "+f"(c[0]), "+f"(c[1]), "+f"(c[2]), "+f"(c[3])
        : "r"(a[0]), "r"(a[1]), "r"(a[2]), "r"(a[3]), "r"(b[0]), "r"(b[1]));
}
__device__ __forceinline__ void ldsm4(uint32_t r[4], uint32_t addr) {
    asm volatile("ldmatrix.sync.aligned.m8n8.x4.shared.b16 {%0,%1,%2,%3}, [%4];"
        : "=r"(r[0]), "=r"(r[1]), "=r"(r[2]), "=r"(r[3]) : "r"(addr));
}
__device__ __forceinline__ void cpa16(uint32_t s, const void* g) {
    asm volatile("cp.async.cg.shared.global [%0], [%1], 16;" :: "r"(s), "l"(g) : "memory");
}
#define CPA_COMMIT() asm volatile("cp.async.commit_group;" ::: "memory")
#define CPA_WAIT(n)  asm volatile("cp.async.wait_group %0;" :: "n"(n) : "memory")

// ---------------------------------------------------------------------------
// prep kernels
// ---------------------------------------------------------------------------
__global__ void __launch_bounds__(256) pack_x(const float* __restrict__ in_x)
{
    const size_t fid = (size_t)blockIdx.x * 256 + threadIdx.x;
    const size_t row = fid >> 9;
    const int r = (int)(fid & 511);
    const int kc = r >> 3, f4 = r & 7;
    float4 v = *(const float4*)(in_x + row * D_ + kc * 32 + f4 * 4);
    __half2 H0 = __halves2half2(__float2half_rn(v.x), __float2half_rn(v.y));
    __half2 H1 = __halves2half2(__float2half_rn(v.z), __float2half_rn(v.w));
    const size_t b32 = row * 1024 + kc * 16;
    g_xp[b32 + f4 * 2]     = *(uint32_t*)&H0;
    g_xp[b32 + f4 * 2 + 1] = *(uint32_t*)&H1;
}

__global__ void __launch_bounds__(256) trans_w(
    const float* __restrict__ Wsc, const float* __restrict__ Wqkv,
    const float* __restrict__ bsc, const float* __restrict__ bqkv)
{
    __shared__ float t[32][33];
    const int n0 = blockIdx.x * 32, k0 = blockIdx.y * 32;
    const int tx = threadIdx.x & 31, ty = threadIdx.x >> 5;
    const int n = n0 + tx;
    #pragma unroll
    for (int r = 0; r < 4; r++) {
        int k = k0 + ty + r * 8;
        t[ty + r * 8][tx] = (n < D_) ? Wsc[(size_t)k * D_ + n]
                                     : Wqkv[(size_t)k * QKV_N + (n - D_)];
    }
    if (blockIdx.y == 0 && threadIdx.x < 32) {
        int nb = n0 + threadIdx.x;
        g_bias[nb] = (nb < D_) ? bsc[nb] : bqkv[nb - D_];
    }
    __syncthreads();
    uint16_t* p16 = (uint16_t*)g_wtp;
    const int kc = k0 >> 5;
    #pragma unroll
    for (int r = 0; r < 4; r++) {
        const int nn = n0 + ty + r * 8;
        __half h = __float2half_rn(t[tx][ty + r * 8]);
        p16[(size_t)nn * 2048 + kc * 32 + tx] = *(uint16_t*)&h;
    }
}

__global__ void __launch_bounds__(256) trans_v()
{
    __shared__ float t[32][33];
    const int b = blockIdx.z;
    const int t0 = blockIdx.x * 32, d0 = blockIdx.y * 32;
    const int tx = threadIdx.x & 31, ty = threadIdx.x >> 5;
    #pragma unroll
    for (int r = 0; r < 4; r++)
        t[ty + r * 8][tx] = g_v[(size_t)(b * S_ + t0 + ty + r * 8) * KD + d0 + tx];
    __syncthreads();
    uint16_t* p16 = (uint16_t*)g_vtp;
    const int tc = t0 >> 5;
    #pragma unroll
    for (int r = 0; r < 4; r++) {
        const int d = d0 + ty + r * 8;
        __half h = __float2half_rn(t[tx][ty + r * 8]);
        p16[((size_t)b * KD + d) * 2048 + tc * 32 + tx] = *(uint16_t*)&h;
    }
}

__global__ void __launch_bounds__(128) colsum_v()
{
    const int g = blockIdx.x, b = g >> 4, tc = g & 15, d = threadIdx.x;
    float s = 0.0f;
    #pragma unroll 8
    for (int t = 0; t < 128; t++)
        s += g_v[(size_t)(b * S_ + tc * 128 + t) * KD + d];
    g_v1p[(size_t)g * KD + d] = s;
}
__global__ void __launch_bounds__(128) reduce_v1()
{
    const int b = blockIdx.x, d = threadIdx.x;
    float s = 0.0f;
    #pragma unroll
    for (int c = 0; c < 16; c++)
        s += g_v1p[(size_t)(b * 16 + c) * KD + d];
    g_v1[b * KD + d] = s;
}

// ---------------------------------------------------------------------------
// GEMM0: C = X @ W^T + bias. fp16 1-term. 512 thr, 4x4 warps, warp tile 32x32,
// BM=BN=128, BK=32, 3-stage cp.async, 1 sync/iter. smem rows 80B.
// ---------------------------------------------------------------------------
#define RS0    80
#define TBYT0  (128 * RS0)            // 10240
#define STAGE0 (2 * TBYT0)            // 20480
#define SMEM0  (3 * STAGE0)           // 61440

__global__ void __launch_bounds__(512, 1) gemm0(float* __restrict__ shortcut)
{
    extern __shared__ uint32_t smw[];
    const int tid = threadIdx.x;
    const int warp = tid >> 5, lane = tid & 31;
    const int gid = lane >> 2, tig = lane & 3;
    const int wm = warp >> 2, wn = warp & 3;
    const int m0 = blockIdx.y * 128, n0 = blockIdx.x * 128;

    const uint32_t smb = smem_u32(smw);
    const int lr = lane & 7;
    const int a_r8 = (lane >> 3) & 1, a_kh = lane >> 4;
    const int b_r8 = lane >> 4,       b_kh = (lane >> 3) & 1;
    uint32_t aAddr[2], bAddr[2];
    #pragma unroll
    for (int mt = 0; mt < 2; mt++)
        aAddr[mt] = smb + (uint32_t)(wm * 32 + mt * 16 + lr + a_r8 * 8) * RS0
                  + (uint32_t)(a_kh * 16);
    #pragma unroll
    for (int np = 0; np < 2; np++)
        bAddr[np] = smb + (uint32_t)TBYT0
                  + (uint32_t)(wn * 32 + np * 16 + lr + b_r8 * 8) * RS0
                  + (uint32_t)(b_kh * 16);

    float c[2][4][4];
    #pragma unroll
    for (int mt = 0; mt < 2; mt++)
        #pragma unroll
        for (int nt = 0; nt < 4; nt++)
            #pragma unroll
            for (int q = 0; q < 4; q++) c[mt][nt][q] = 0.0f;

    const int c_row = tid >> 2, c_s = tid & 3;

    auto issue = [&](int it, int st) {
        const uint32_t sbase = smb + (uint32_t)(st * STAGE0);
        cpa16(sbase + (uint32_t)c_row * RS0 + c_s * 16,
              g_xp + (size_t)(m0 + c_row) * 1024 + it * 16 + c_s * 4);
        cpa16(sbase + TBYT0 + (uint32_t)c_row * RS0 + c_s * 16,
              g_wtp + (size_t)(n0 + c_row) * 1024 + it * 16 + c_s * 4);
        CPA_COMMIT();
    };

    issue(0, 0); issue(1, 1);

    for (int it = 0; it < 64; it++) {
        CPA_WAIT(1);
        __syncthreads();
        if (it + 2 < 64) issue(it + 2, (it + 2) % 3);

        const uint32_t so = (uint32_t)((it % 3) * STAGE0);
        #pragma unroll
        for (int ks = 0; ks < 2; ks++) {
            const uint32_t ko = so + (uint32_t)(ks * 32);
            uint32_t ah[2][4], bh2[2][4];
            #pragma unroll
            for (int mt = 0; mt < 2; mt++)
                ldsm4(ah[mt], aAddr[mt] + ko);
            #pragma unroll
            for (int np = 0; np < 2; np++)
                ldsm4(bh2[np], bAddr[np] + ko);
            #pragma unroll
            for (int mt = 0; mt < 2; mt++)
                #pragma unroll
                for (int nt = 0; nt < 4; nt++)
                    mma_f16(c[mt][nt], ah[mt], &bh2[nt >> 1][(nt & 1) * 2]);
        }
    }

    // epilogue: shortcut fp32 / q hi / k hi / v fp32
    #pragma unroll
    for (int mt = 0; mt < 2; mt++) {
        const int r0 = m0 + wm * 32 + mt * 16 + gid;
        #pragma unroll
        for (int nt = 0; nt < 4; nt++) {
            const int n = n0 + wn * 32 + nt * 8 + 2 * tig;
            const float b0 = g_bias[n], b1 = g_bias[n + 1];
            float v00 = c[mt][nt][0] + b0, v01 = c[mt][nt][1] + b1;
            float v10 = c[mt][nt][2] + b0, v11 = c[mt][nt][3] + b1;
            if (n < D_) {
                *(float2*)(shortcut + (size_t)r0 * D_ + n)       = make_float2(v00, v01);
                *(float2*)(shortcut + (size_t)(r0 + 8) * D_ + n) = make_float2(v10, v11);
            } else if (n < 2 * D_) {
                const int qc = n - D_;
                const int chunk = qc >> 5, w = qc & 31;
                __half2 H0 = __halves2half2(__float2half_rn(v00), __float2half_rn(v01));
                __half2 H1 = __halves2half2(__float2half_rn(v10), __float2half_rn(v11));
                g_qp[(size_t)r0 * 1024 + chunk * 16 + (w >> 1)]       = *(uint32_t*)&H0;
                g_qp[(size_t)(r0 + 8) * 1024 + chunk * 16 + (w >> 1)] = *(uint32_t*)&H1;
            } else if (n < 2 * D_ + KD) {
                const int kc2 = n - 2 * D_;
                const int chunk = kc2 >> 5, w = kc2 & 31;
                __half2 H0 = __halves2half2(__float2half_rn(v00), __float2half_rn(v01));
                __half2 H1 = __halves2half2(__float2half_rn(v10), __float2half_rn(v11));
                g_kp[(size_t)r0 * 64 + chunk * 16 + (w >> 1)]       = *(uint32_t*)&H0;
                g_kp[(size_t)(r0 + 8) * 64 + chunk * 16 + (w >> 1)] = *(uint32_t*)&H1;
            } else {
                const int d = n - (2 * D_ + KD);
                *(float2*)(g_v + (size_t)r0 * KD + d)       = make_float2(v00, v01);
                *(float2*)(g_v + (size_t)(r0 + 8) * KD + d) = make_float2(v10, v11);
            }
        }
    }
}

// ---------------------------------------------------------------------------
// Fused attention (all fp16 1-term): per CTA (m-tile 128 rows, one bh):
// score out, Σexp in regs, Sv over 16 t-tiles; atten/res = (Sv + V1)/Σexp.
// smem: q[128x272] | K[128x272] | VT[2][128x272] | scoreA[128x272] | rsum[128]
// ---------------------------------------------------------------------------
#define TROW 272
#define TBYT (128 * TROW)          // 34816
#define OFF_K  TBYT
#define OFF_VT (2 * TBYT)
#define OFF_SA (4 * TBYT)
#define OFF_RS (5 * TBYT)
#define SMEMA  (OFF_RS + 512)      // 174592

__global__ void __launch_bounds__(512, 1) attn(
    float* __restrict__ score, float* __restrict__ atten, float* __restrict__ res)
{
    extern __shared__ uint32_t smw[];
    char* smc = (char*)smw;
    float* rsm = (float*)(smc + OFF_RS);

    const int tid = threadIdx.x;
    const int warp = tid >> 5, lane = tid & 31;
    const int gid = lane >> 2, tig = lane & 3;
    const int wm = warp >> 2, wn = warp & 3;

    const int m0 = blockIdx.x * 128;
    const int bh = blockIdx.y, bb = bh >> 4, h = bh & 15;

    const uint32_t smb = smem_u32(smw);
    const uint32_t* qg = g_qp + (size_t)bb * S_ * 1024;
    const uint32_t* kg = g_kp + (size_t)bb * S_ * 64;
    const uint32_t* vg = g_vtp + (size_t)bb * KD * 1024;
    float* Cp = score + (size_t)bh * S_ * S_;

    // ---- q tile load (once): 128 rows x 256B = 2048 x 16B pieces ----
    {
        #pragma unroll
        for (int p = 0; p < 4; p++) {
            int i = tid + p * 512;
            int row = i >> 4, piece = i & 15;
            cpa16(smb + (uint32_t)row * TROW + piece * 16,
                  qg + (size_t)(m0 + row) * 1024 + h * 64 + piece * 4);
        }
        CPA_COMMIT();
    }
    if (tid < 128) rsm[tid] = 0.0f;

    const int t_row = tid >> 4, t_s = tid & 15;
    auto issue_k = [&](int t) {
        #pragma unroll
        for (int p = 0; p < 4; p++) {
            int row = t_row + p * 32;
            cpa16(smb + OFF_K + (uint32_t)row * TROW + t_s * 16,
                  kg + (size_t)(t * 128 + row) * 64 + t_s * 4);
        }
        CPA_COMMIT();
    };
    auto issue_vt = [&](int t, int buf) {
        #pragma unroll
        for (int p = 0; p < 4; p++) {
            int d = t_row + p * 32;
            cpa16(smb + OFF_VT + (uint32_t)buf * TBYT + (uint32_t)d * TROW + t_s * 16,
                  vg + (size_t)d * 1024 + t * 64 + t_s * 4);
        }
        CPA_COMMIT();
    };

    const int lr = lane & 7;
    const int a_r8 = (lane >> 3) & 1, a_kh = lane >> 4;
    const int b_r8 = lane >> 4,       b_kh = (lane >> 3) & 1;
    uint32_t aQ[2], bK[2], aS[2], bV[2];
    #pragma unroll
    for (int mt = 0; mt < 2; mt++) {
        const uint32_t arow = (uint32_t)(wm * 32 + mt * 16 + lr + a_r8 * 8);
        aQ[mt] = smb + arow * TROW + (uint32_t)(a_kh * 16);
        aS[mt] = smb + OFF_SA + arow * TROW + (uint32_t)(a_kh * 16);
    }
    #pragma unroll
    for (int np = 0; np < 2; np++) {
        const uint32_t brow = (uint32_t)(wn * 32 + np * 16 + lr + b_r8 * 8);
        bK[np] = smb + OFF_K + brow * TROW + (uint32_t)(b_kh * 16);
        bV[np] = smb + OFF_VT + brow * TROW + (uint32_t)(b_kh * 16);
    }

    float c2[2][4][4];
    #pragma unroll
    for (int mt = 0; mt < 2; mt++)
        #pragma unroll
        for (int nt = 0; nt < 4; nt++)
            #pragma unroll
            for (int q = 0; q < 4; q++) c2[mt][nt][q] = 0.0f;
    float rs[2][2] = {{0.0f, 0.0f}, {0.0f, 0.0f}};

    issue_vt(0, 0);
    issue_k(0);

    const float inv = 1.0f / 16384.0f;

    for (int t0 = 0; t0 < 16; t0++) {
        if (t0 + 1 < 16) { issue_vt(t0 + 1, (t0 + 1) & 1); CPA_WAIT(1); }
        else             { CPA_WAIT(0); }
        __syncthreads();

        // ---- GEMM1: score tile = q (1-term) x k-tile ----
        float c1[2][4][4];
        #pragma unroll
        for (int mt = 0; mt < 2; mt++)
            #pragma unroll
            for (int nt = 0; nt < 4; nt++)
                #pragma unroll
                for (int q = 0; q < 4; q++) c1[mt][nt][q] = 0.0f;
        #pragma unroll
        for (int ks = 0; ks < 8; ks++) {
            const uint32_t ko = (uint32_t)(ks * 32);
            uint32_t ah[2][4], bk2[2][4];
            #pragma unroll
            for (int mt = 0; mt < 2; mt++)
                ldsm4(ah[mt], aQ[mt] + ko);
            #pragma unroll
            for (int np = 0; np < 2; np++)
                ldsm4(bk2[np], bK[np] + ko);
            #pragma unroll
            for (int mt = 0; mt < 2; mt++)
                #pragma unroll
                for (int nt = 0; nt < 4; nt++)
                    mma_f16(c1[mt][nt], ah[mt], &bk2[nt >> 1][(nt & 1) * 2]);
        }

        // ---- epilogue1: score write, Σexp accum, scoreA fp16 ----
        #pragma unroll
        for (int mt = 0; mt < 2; mt++) {
            const int rl = wm * 32 + mt * 16 + gid;
            #pragma unroll
            for (int nt = 0; nt < 4; nt++) {
                const int col = wn * 32 + nt * 8 + 2 * tig;
                float v0 = c1[mt][nt][0] * inv, v1 = c1[mt][nt][1] * inv;
                float v2 = c1[mt][nt][2] * inv, v3 = c1[mt][nt][3] * inv;
                *(float2*)(Cp + (size_t)(m0 + rl) * S_ + t0 * 128 + col)
                    = make_float2(v0, v1);
                *(float2*)(Cp + (size_t)(m0 + rl + 8) * S_ + t0 * 128 + col)
                    = make_float2(v2, v3);
                rs[mt][0] += __expf(v0) + __expf(v1);
                rs[mt][1] += __expf(v2) + __expf(v3);
                __half2 P0 = __halves2half2(__float2half_rn(v0), __float2half_rn(v1));
                __half2 P1 = __halves2half2(__float2half_rn(v2), __float2half_rn(v3));
                *(uint32_t*)(smc + OFF_SA + rl * TROW + col * 2)       = *(uint32_t*)&P0;
                *(uint32_t*)(smc + OFF_SA + (rl + 8) * TROW + col * 2) = *(uint32_t*)&P1;
            }
        }
        __syncthreads();
        if (t0 + 1 < 16) issue_k(t0 + 1);   // overlaps GEMM2

        // ---- GEMM2: Sv += scoreA (1-term) x vT-tile ----
        {
            const uint32_t vb = (uint32_t)((t0 & 1) * TBYT);
            #pragma unroll
            for (int ks = 0; ks < 8; ks++) {
                const uint32_t ko = (uint32_t)(ks * 32);
                uint32_t as2[2][4], bv2[2][4];
                #pragma unroll
                for (int mt = 0; mt < 2; mt++)
                    ldsm4(as2[mt], aS[mt] + ko);
                #pragma unroll
                for (int np = 0; np < 2; np++)
                    ldsm4(bv2[np], bV[np] + vb + ko);
                #pragma unroll
                for (int mt = 0; mt < 2; mt++)
                    #pragma unroll
                    for (int nt = 0; nt < 4; nt++)
                        mma_f16(c2[mt][nt], as2[mt], &bv2[nt >> 1][(nt & 1) * 2]);
            }
        }
        __syncthreads();
    }

    // ---- Σexp cross-warp reduce ----
    #pragma unroll
    for (int mt = 0; mt < 2; mt++) {
        float a = rs[mt][0], b = rs[mt][1];
        a += __shfl_xor_sync(0xFFFFFFFFu, a, 1);
        a += __shfl_xor_sync(0xFFFFFFFFu, a, 2);
        b += __shfl_xor_sync(0xFFFFFFFFu, b, 1);
        b += __shfl_xor_sync(0xFFFFFFFFu, b, 2);
        if (tig == 0) {
            atomicAdd(&rsm[wm * 32 + mt * 16 + gid], a);
            atomicAdd(&rsm[wm * 32 + mt * 16 + gid + 8], b);
        }
    }
    __syncthreads();

    // ---- final: atten / res ----
    #pragma unroll
    for (int mt = 0; mt < 2; mt++) {
        const int rl = wm * 32 + mt * 16 + gid;
        const int r0 = m0 + rl;
        const float il0 = 1.0f / rsm[rl];
        const float il1 = 1.0f / rsm[rl + 8];
        #pragma unroll
        for (int nt = 0; nt < 4; nt++) {
            const int col = wn * 32 + nt * 8 + 2 * tig;
            const float w0 = g_v1[bb * KD + col], w1 = g_v1[bb * KD + col + 1];
            float2 o0 = make_float2((c2[mt][nt][0] + w0) * il0,
                                    (c2[mt][nt][1] + w1) * il0);
            float2 o1 = make_float2((c2[mt][nt][2] + w0) * il1,
                                    (c2[mt][nt][3] + w1) * il1);
            *(float2*)(atten + (size_t)bh * S_ * KD + (size_t)r0 * KD + col) = o0;
            *(float2*)(atten + (size_t)bh * S_ * KD + (size_t)(r0 + 8) * KD + col) = o1;
            *(float2*)(res + (size_t)(bb * S_ + r0) * D_ + h * KD + col) = o0;
            *(float2*)(res + (size_t)(bb * S_ + r0 + 8) * D_ + h * KD + col) = o1;
        }
    }
}

// ---------------------------------------------------------------------------
extern "C" void kernel_launch(void* const* d_in, const int* in_sizes, int n_in,
                              void* d_out, int out_size)
{
    const float* in_x  = (const float*)d_in[0];
    const float* W_sc  = (const float*)d_in[1];
    const float* b_sc  = (const float*)d_in[2];
    const float* W_qkv = (const float*)d_in[3];
    const float* b_qkv = (const float*)d_in[4];

    float* out       = (float*)d_out;
    float* score     = out;
    float* atten     = score + (size_t)BH_ * S_ * S_;
    float* res       = atten + (size_t)BH_ * S_ * KD;
    float* short_cut = res   + (size_t)B_ * S_ * D_;

    cudaFuncSetAttribute(gemm0, cudaFuncAttributeMaxDynamicSharedMemorySize, SMEM0);
    cudaFuncSetAttribute(attn,  cudaFuncAttributeMaxDynamicSharedMemorySize, SMEMA);

    pack_x<<<(unsigned)(((size_t)B_ * S_ * D_ / 4) / 256), 256>>>(in_x);
    trans_w<<<dim3(NTOT / 32, D_ / 32), 256>>>(W_sc, W_qkv, b_sc, b_qkv);
    gemm0<<<dim3(NTOT / 128, (B_ * S_) / 128), 512, SMEM0>>>(short_cut);
    trans_v<<<dim3(S_ / 32, KD / 32, B_), 256>>>();
    colsum_v<<<B_ * 16, 128>>>();
    reduce_v1<<<B_, 128>>>();
    attn<<<dim3(S_ / 128, BH_), 512, SMEMA>>>(score, atten, res);
}